// round 1
// baseline (speedup 1.0000x reference)
#include <cuda_runtime.h>
#include <math.h>

#define BB 2
#define SS 2048
#define DIMM 2048
#define NH 16
#define QR 1536
#define KVR 512
#define DN 128
#define DR 64
#define DVV 128
#define MT (BB*SS)   // 4096 token rows

// ---------------- scratch (allocation-free: __device__ globals) ----------------
__device__ float g_qc[MT*QR];              // 25 MB
__device__ float g_kvc[MT*KVR];            // 8 MB
__device__ float g_qnope[MT*NH*DN];        // 33 MB
__device__ float g_qpe[MT*NH*DR];          // 16 MB
__device__ float g_kvup[MT*NH*(DN+DVV)];   // 67 MB
__device__ float g_krope[MT*DR];           // 1 MB
__device__ float g_attn[MT*NH*DVV];        // 33 MB

// ---------------- generic NT GEMM: C[M,N] = A[M,K] * B[N,K]^T ----------------
// BM=128, BN=128, BK=16, 256 threads, 8x8 microtile.
// M % 128 == 0, K % 16 == 0 assumed (true for all call sites). N guarded.
__global__ __launch_bounds__(256) void gemm_nt_k(
    const float* __restrict__ A, const float* __restrict__ B,
    float* __restrict__ C, int M, int N, int K)
{
    __shared__ float As[16][128];
    __shared__ float Bs[16][128];
    const int m0 = blockIdx.y * 128;
    const int n0 = blockIdx.x * 128;
    const int tid = threadIdx.x;
    const int tx = tid & 15;        // 0..15 -> 8 cols each
    const int ty = tid >> 4;        // 0..15 -> 8 rows each

    float acc[8][8];
#pragma unroll
    for (int i = 0; i < 8; i++)
#pragma unroll
        for (int j = 0; j < 8; j++) acc[i][j] = 0.f;

    for (int k0 = 0; k0 < K; k0 += 16) {
        // load A tile (transposed into As[k][m]) : 128x16 = 512 float4
#pragma unroll
        for (int l = tid; l < 512; l += 256) {
            int row = l >> 2;          // 0..127
            int c4  = l & 3;           // 0..3
            float4 v = *(const float4*)&A[(size_t)(m0 + row) * K + k0 + c4 * 4];
            As[c4*4+0][row] = v.x; As[c4*4+1][row] = v.y;
            As[c4*4+2][row] = v.z; As[c4*4+3][row] = v.w;
        }
        // load B tile (transposed into Bs[k][n]), guard rows >= N with zeros
#pragma unroll
        for (int l = tid; l < 512; l += 256) {
            int row = l >> 2;
            int c4  = l & 3;
            float4 v = make_float4(0.f, 0.f, 0.f, 0.f);
            if (n0 + row < N)
                v = *(const float4*)&B[(size_t)(n0 + row) * K + k0 + c4 * 4];
            Bs[c4*4+0][row] = v.x; Bs[c4*4+1][row] = v.y;
            Bs[c4*4+2][row] = v.z; Bs[c4*4+3][row] = v.w;
        }
        __syncthreads();
#pragma unroll
        for (int k = 0; k < 16; k++) {
            float a[8], b[8];
            float4 a0 = *(const float4*)&As[k][ty*8];
            float4 a1 = *(const float4*)&As[k][ty*8+4];
            float4 b0 = *(const float4*)&Bs[k][tx*8];
            float4 b1 = *(const float4*)&Bs[k][tx*8+4];
            a[0]=a0.x;a[1]=a0.y;a[2]=a0.z;a[3]=a0.w;a[4]=a1.x;a[5]=a1.y;a[6]=a1.z;a[7]=a1.w;
            b[0]=b0.x;b[1]=b0.y;b[2]=b0.z;b[3]=b0.w;b[4]=b1.x;b[5]=b1.y;b[6]=b1.z;b[7]=b1.w;
#pragma unroll
            for (int i = 0; i < 8; i++)
#pragma unroll
                for (int j = 0; j < 8; j++)
                    acc[i][j] = fmaf(a[i], b[j], acc[i][j]);
        }
        __syncthreads();
    }
    // store (float4, guard col < N; N is a multiple of 4 at all call sites)
#pragma unroll
    for (int i = 0; i < 8; i++) {
        size_t row = (size_t)(m0 + ty*8 + i);
#pragma unroll
        for (int j4 = 0; j4 < 2; j4++) {
            int col = n0 + tx*8 + j4*4;
            if (col < N) {
                float4 v = make_float4(acc[i][j4*4+0], acc[i][j4*4+1],
                                       acc[i][j4*4+2], acc[i][j4*4+3]);
                *(float4*)&C[row * N + col] = v;
            }
        }
    }
}

// ---------------- RMSNorm (in-place capable), one block per row ----------------
__global__ void rmsnorm_k(const float* __restrict__ in, const float* __restrict__ w,
                          float* __restrict__ out, int W)
{
    const int row = blockIdx.x;
    const float* x = in + (size_t)row * W;
    float ss = 0.f;
    for (int i = threadIdx.x; i < W; i += blockDim.x) { float v = x[i]; ss += v * v; }
    __shared__ float red[32];
#pragma unroll
    for (int o = 16; o; o >>= 1) ss += __shfl_down_sync(0xffffffffu, ss, o);
    if ((threadIdx.x & 31) == 0) red[threadIdx.x >> 5] = ss;
    __syncthreads();
    if (threadIdx.x < 32) {
        float v = (threadIdx.x < (blockDim.x >> 5)) ? red[threadIdx.x] : 0.f;
#pragma unroll
        for (int o = 16; o; o >>= 1) v += __shfl_down_sync(0xffffffffu, v, o);
        if (threadIdx.x == 0) red[0] = rsqrtf(v / (float)W + 1e-6f);
    }
    __syncthreads();
    float r = red[0];
    for (int i = threadIdx.x; i < W; i += blockDim.x)
        out[(size_t)row * W + i] = x[i] * r * w[i];
}

// ---------------- RoPE (LLaMA-style interleaved pairs), in place ----------------
// x: [MT, nheads*d], position = row % SS
__global__ void rope_k(float* __restrict__ x, int nheads, int d, int total_pairs)
{
    int idx = blockIdx.x * blockDim.x + threadIdx.x;
    if (idx >= total_pairs) return;
    int pairs_per_row = nheads * (d / 2);
    int row = idx / pairs_per_row;
    int p   = idx % pairs_per_row;
    int h = p / (d / 2);
    int i = p % (d / 2);
    int pos = row % SS;
    float inv = powf(10000.f, (-2.0f * (float)i) / (float)d);
    float ang = (float)pos * inv;
    float s, c;
    sincosf(ang, &s, &c);
    float* base = x + (size_t)row * nheads * d + h * d + 2 * i;
    float x1 = base[0], x2 = base[1];
    base[0] = x1 * c - x2 * s;
    base[1] = x1 * s + x2 * c;
}

// ---------------- causal flash attention ----------------
// grid: (S/32, NH, B); 256 threads. 32 queries x 32 keys per tile.
// Thread t: query qi = t/8, owns V-dims [sub*16, sub*16+16), sub = t%8.
__global__ __launch_bounds__(256) void attn_k(
    const float* __restrict__ qn,   // [MT, NH*DN]
    const float* __restrict__ qp,   // [MT, NH*DR]  (rope applied)
    const float* __restrict__ kv,   // [MT, NH*(DN+DVV)]
    const float* __restrict__ kr,   // [MT, DR]     (rope applied)
    float* __restrict__ o)          // [MT, NH*DVV]
{
    extern __shared__ float sm[];
    float* Qs  = sm;                   // 32 x 193 (padded)
    float* KsT = Qs + 32 * 193;        // 192 x 32 (transposed)
    float* Vs  = KsT + 192 * 32;       // 32 x 128
    float* Ps  = Vs + 32 * 128;        // 32 x 33  (padded)

    const int qt = blockIdx.x, h = blockIdx.y, b = blockIdx.z;
    const int q0 = qt * 32;
    const int tid = threadIdx.x;
    const int qi = tid >> 3, sub = tid & 7;
    const float scale = rsqrtf(192.f);

    // load Q tile (pre-scaled)
    for (int l = tid; l < 32 * 192; l += 256) {
        int r = l / 192, d = l % 192;
        size_t m = (size_t)(b * SS + q0 + r);
        float v = (d < 128) ? qn[m * (NH * DN) + h * DN + d]
                            : qp[m * (NH * DR) + h * DR + (d - 128)];
        Qs[r * 193 + d] = v * scale;
    }

    float acc[16];
#pragma unroll
    for (int d = 0; d < 16; d++) acc[d] = 0.f;
    float m_run = -INFINITY, l_run = 0.f;

    const int ntiles = qt + 1;
    for (int kt = 0; kt < ntiles; kt++) {
        const int k0 = kt * 32;
        __syncthreads();
        // K tile -> transposed shared; V tile
        for (int l = tid; l < 32 * 192; l += 256) {
            int r = l / 192, d = l % 192;
            size_t m = (size_t)(b * SS + k0 + r);
            float v = (d < 128) ? kv[m * (NH * 256) + h * 256 + d]
                                : kr[m * DR + (d - 128)];
            KsT[d * 32 + r] = v;
        }
        for (int l = tid; l < 32 * 128; l += 256) {
            int r = l >> 7, d = l & 127;
            size_t m = (size_t)(b * SS + k0 + r);
            Vs[r * 128 + d] = kv[m * (NH * 256) + h * 256 + 128 + d];
        }
        __syncthreads();

        // scores: this thread does keys kj = sub*4 .. sub*4+3 for row qi
        {
            float s0 = 0.f, s1 = 0.f, s2 = 0.f, s3 = 0.f;
            const float* qrow = Qs + qi * 193;
#pragma unroll 8
            for (int t = 0; t < 192; t++) {
                float q = qrow[t];
                float4 kk = *(const float4*)&KsT[t * 32 + sub * 4];
                s0 = fmaf(q, kk.x, s0); s1 = fmaf(q, kk.y, s1);
                s2 = fmaf(q, kk.z, s2); s3 = fmaf(q, kk.w, s3);
            }
            float sv[4] = {s0, s1, s2, s3};
#pragma unroll
            for (int i = 0; i < 4; i++) {
                int kj = sub * 4 + i;
                bool ok = (k0 + kj) <= (q0 + qi);
                Ps[qi * 33 + kj] = ok ? sv[i] : -INFINITY;
            }
        }
        __syncthreads();

        // online softmax + PV (8 threads per query duplicate m/l bookkeeping)
        {
            const float* prow = Ps + qi * 33;
            float tmax = -INFINITY;
#pragma unroll
            for (int j = 0; j < 32; j++) tmax = fmaxf(tmax, prow[j]);
            float new_m = fmaxf(m_run, tmax);
            float factor = __expf(m_run - new_m);   // 0 when m_run == -inf
            l_run *= factor;
#pragma unroll
            for (int d = 0; d < 16; d++) acc[d] *= factor;
#pragma unroll 4
            for (int j = 0; j < 32; j++) {
                float p = __expf(prow[j] - new_m);
                l_run += p;
                const float4* vrow = (const float4*)&Vs[j * 128 + sub * 16];
#pragma unroll
                for (int d4 = 0; d4 < 4; d4++) {
                    float4 vv = vrow[d4];
                    acc[d4*4+0] = fmaf(p, vv.x, acc[d4*4+0]);
                    acc[d4*4+1] = fmaf(p, vv.y, acc[d4*4+1]);
                    acc[d4*4+2] = fmaf(p, vv.z, acc[d4*4+2]);
                    acc[d4*4+3] = fmaf(p, vv.w, acc[d4*4+3]);
                }
            }
            m_run = new_m;
        }
    }

    float inv_l = 1.f / l_run;
    size_t m = (size_t)(b * SS + q0 + qi);
    float* orow = o + m * (NH * DVV) + h * DVV + sub * 16;
#pragma unroll
    for (int d = 0; d < 16; d++) orow[d] = acc[d] * inv_l;
}

// ---------------- host orchestration ----------------
static void launch_gemm(const float* A, const float* B, float* C, int M, int N, int K)
{
    dim3 grid((N + 127) / 128, M / 128);
    gemm_nt_k<<<grid, 256>>>(A, B, C, M, N, K);
}

extern "C" void kernel_launch(void* const* d_in, const int* in_sizes, int n_in,
                              void* d_out, int out_size)
{
    const float* x        = (const float*)d_in[0];
    const float* wq_down  = (const float*)d_in[1];
    const float* q_norm_w = (const float*)d_in[2];
    const float* wq_up    = (const float*)d_in[3];
    const float* wq_rope  = (const float*)d_in[4];
    const float* wkv_down = (const float*)d_in[5];
    const float* kv_norm_w= (const float*)d_in[6];
    const float* wkv_up   = (const float*)d_in[7];
    const float* wk_rope  = (const float*)d_in[8];
    const float* wo       = (const float*)d_in[9];
    float* out = (float*)d_out;

    float *qc, *kvc, *qn, *qp, *kvu, *kr, *at;
    cudaGetSymbolAddress((void**)&qc,  g_qc);
    cudaGetSymbolAddress((void**)&kvc, g_kvc);
    cudaGetSymbolAddress((void**)&qn,  g_qnope);
    cudaGetSymbolAddress((void**)&qp,  g_qpe);
    cudaGetSymbolAddress((void**)&kvu, g_kvup);
    cudaGetSymbolAddress((void**)&kr,  g_krope);
    cudaGetSymbolAddress((void**)&at,  g_attn);

    // down projections
    launch_gemm(x, wq_down,  qc,  MT, QR,  DIMM);
    launch_gemm(x, wkv_down, kvc, MT, KVR, DIMM);
    launch_gemm(x, wk_rope,  kr,  MT, DR,  DIMM);

    // rmsnorm (in place)
    rmsnorm_k<<<MT, 256>>>(qc,  q_norm_w,  qc,  QR);
    rmsnorm_k<<<MT, 256>>>(kvc, kv_norm_w, kvc, KVR);

    // up projections
    launch_gemm(qc,  wq_up,   qn,  MT, NH*DN,        QR);
    launch_gemm(qc,  wq_rope, qp,  MT, NH*DR,        QR);
    launch_gemm(kvc, wkv_up,  kvu, MT, NH*(DN+DVV),  KVR);

    // rope (in place)
    {
        int tot = MT * NH * (DR / 2);
        rope_k<<<(tot + 255) / 256, 256>>>(qp, NH, DR, tot);
    }
    {
        int tot = MT * 1 * (DR / 2);
        rope_k<<<(tot + 255) / 256, 256>>>(kr, 1, DR, tot);
    }

    // attention
    size_t shbytes = (size_t)(32*193 + 192*32 + 32*128 + 32*33) * sizeof(float); // ~70 KB
    cudaFuncSetAttribute(attn_k, cudaFuncAttributeMaxDynamicSharedMemorySize, (int)shbytes);
    attn_k<<<dim3(SS/32, NH, BB), 256, shbytes>>>(qn, qp, kvu, kr, at);

    // output projection
    launch_gemm(at, wo, out, MT, DIMM, NH*DVV);
}

// round 3
// speedup vs baseline: 1.1863x; 1.1863x over previous
#include <cuda_runtime.h>
#include <cuda_bf16.h>
#include <math.h>
#include <stdint.h>

#define BB 2
#define SS 2048
#define DIMM 2048
#define NH 16
#define QR 1536
#define KVR 512
#define DN 128
#define DR 64
#define DVV 128
#define MT (BB*SS)   // 4096 token rows

// ---------------- fp32 scratch ----------------
__device__ float g_qc[MT*QR];
__device__ float g_kvc[MT*KVR];
__device__ float g_qnope[MT*NH*DN];
__device__ float g_qpe[MT*NH*DR];
__device__ float g_kvup[MT*NH*(DN+DVV)];
__device__ float g_krope[MT*DR];
__device__ float g_attn[MT*NH*DVV];

// ---------------- bf16 split scratch (K' = 3K) ----------------
__device__ __nv_bfloat16 g_xs  [MT   * 3*DIMM];
__device__ __nv_bfloat16 g_wqd [QR   * 3*DIMM];
__device__ __nv_bfloat16 g_wkvd[KVR  * 3*DIMM];
__device__ __nv_bfloat16 g_wkr [128  * 3*DIMM];   // padded 64->128 rows
__device__ __nv_bfloat16 g_qcs [MT   * 3*QR];
__device__ __nv_bfloat16 g_wqu [(NH*DN) * 3*QR];
__device__ __nv_bfloat16 g_wqr [(NH*DR) * 3*QR];
__device__ __nv_bfloat16 g_kvcs[MT   * 3*KVR];
__device__ __nv_bfloat16 g_wkvu[(NH*(DN+DVV)) * 3*KVR];
__device__ __nv_bfloat16 g_ats [MT   * 3*(NH*DVV)];
__device__ __nv_bfloat16 g_wos [DIMM * 3*(NH*DVV)];

// ============================================================
// helpers (base sm_103-safe PTX only: cp.async / ldmatrix / mma.sync)
// ============================================================
__device__ __forceinline__ uint32_t smem_u32(const void* p){
    uint32_t a;
    asm("{ .reg .u64 t; cvta.to.shared.u64 t, %1; cvt.u32.u64 %0, t; }" : "=r"(a) : "l"(p));
    return a;
}
#define CPA16(dst, src) asm volatile("cp.async.cg.shared.global [%0], [%1], 16;" :: "r"(dst), "l"(src))
#define CPCOMMIT()      asm volatile("cp.async.commit_group;")
#define CPWAIT(n)       asm volatile("cp.async.wait_group %0;" :: "n"(n))

__device__ __forceinline__ void ldsm4(uint32_t* r, uint32_t addr){
    asm volatile("ldmatrix.sync.aligned.m8n8.x4.shared.b16 {%0,%1,%2,%3}, [%4];"
        : "=r"(r[0]), "=r"(r[1]), "=r"(r[2]), "=r"(r[3]) : "r"(addr));
}
__device__ __forceinline__ void mma16816(float* c, const uint32_t* a, uint32_t b0, uint32_t b1){
    asm volatile("mma.sync.aligned.m16n8k16.row.col.f32.bf16.bf16.f32 "
        "{%0,%1,%2,%3}, {%4,%5,%6,%7}, {%8,%9}, {%0,%1,%2,%3};"
        : "+f"(c[0]), "+f"(c[1]), "+f"(c[2]), "+f"(c[3])
        : "r"(a[0]), "r"(a[1]), "r"(a[2]), "r"(a[3]), "r"(b0), "r"(b1));
}

// ============================================================
// split-3 conversion: out [Rpad, 3C] bf16 from in [R, C] fp32
// mode 0 (A): [hi | lo | hi]    mode 1 (B): [hi | hi | lo]
// ============================================================
__global__ void split3_k(const float* __restrict__ in, __nv_bfloat16* __restrict__ out,
                         int R, int Rpad, int C, int mode)
{
    long long i = (long long)blockIdx.x * blockDim.x + threadIdx.x;
    long long tot = (long long)Rpad * C;
    if (i >= tot) return;
    int r = (int)(i / C), c = (int)(i % C);
    float x = (r < R) ? in[(size_t)r * C + c] : 0.f;
    __nv_bfloat16 h = __float2bfloat16(x);
    __nv_bfloat16 l = __float2bfloat16(x - __bfloat162float(h));
    size_t base = (size_t)r * 3 * C;
    if (mode == 0) { out[base + c] = h; out[base + C + c] = l; out[base + 2*C + c] = h; }
    else           { out[base + c] = h; out[base + C + c] = h; out[base + 2*C + c] = l; }
}

// ============================================================
// mma.sync bf16 GEMM: C[M,N] = A[M,Kp] * B[N,Kp]^T, fp32 out
// BM=BN=128, BK=32, 4 stages cp.async, 8 warps (32x64 each).
// M%128==0, Kp%32==0, B buffer has ceil(N,128) rows, N%8==0.
// ============================================================
#define STAGES 4
#define STAGE_BYTES 20480               // A: 128*80  B: 128*80
#define GEMM_SMEM (STAGES*STAGE_BYTES)  // 81920

__global__ __launch_bounds__(256, 2) void gemm_tc(
    const __nv_bfloat16* __restrict__ A, const __nv_bfloat16* __restrict__ B,
    float* __restrict__ C, int M, int N, int Kp)
{
    extern __shared__ __align__(16) char smem[];
    const uint32_t sb = smem_u32(smem);
    const int m0 = blockIdx.y * 128, n0 = blockIdx.x * 128;
    const int tid = threadIdx.x, lane = tid & 31;
    const int wm = (tid >> 5) & 3;      // 0..3 -> 32-row slice
    const int wn = tid >> 7;            // 0..1 -> 64-col slice

    float acc[2][8][4];
#pragma unroll
    for (int i = 0; i < 2; i++)
#pragma unroll
        for (int j = 0; j < 8; j++)
#pragma unroll
            for (int q = 0; q < 4; q++) acc[i][j][q] = 0.f;

    const int KT = Kp >> 5;

    const __nv_bfloat16* Ag0 = A + (size_t)m0 * Kp;
    const __nv_bfloat16* Bg0 = B + (size_t)n0 * Kp;

    auto fill = [&](int j){
        uint32_t base = sb + (uint32_t)(j % STAGES) * STAGE_BYTES;
        int k0 = j << 5;
#pragma unroll
        for (int i = 0; i < 2; i++) {
            int idx = tid + i * 256;            // 0..511
            int r = idx >> 2, c = idx & 3;
            CPA16(base + (uint32_t)(r*80 + c*16), Ag0 + (size_t)r * Kp + k0 + c*8);
        }
#pragma unroll
        for (int i = 0; i < 2; i++) {
            int idx = tid + i * 256;
            int r = idx >> 2, c = idx & 3;
            CPA16(base + 10240u + (uint32_t)(r*80 + c*16), Bg0 + (size_t)r * Kp + k0 + c*8);
        }
        CPCOMMIT();
    };

    for (int j = 0; j < STAGES-1; j++) fill(j);

    const int a_row  = lane & 15;
    const int a_col8 = (lane >> 4) * 8;
    const int b_nrow = (lane & 7) + ((lane & 16) ? 8 : 0);
    const int b_kc   = (lane & 8) ? 8 : 0;

    for (int kt = 0; kt < KT; kt++) {
        CPWAIT(STAGES-2);
        __syncthreads();
        if (kt + STAGES-1 < KT) fill(kt + STAGES-1);
        else CPCOMMIT();

        uint32_t aT = sb + (uint32_t)(kt % STAGES) * STAGE_BYTES;
        uint32_t bT = aT + 10240u;
#pragma unroll
        for (int ks = 0; ks < 2; ks++) {
            uint32_t a[2][4];
#pragma unroll
            for (int i = 0; i < 2; i++) {
                int row = wm*32 + i*16 + a_row;
                int col = ks*16 + a_col8;
                ldsm4(a[i], aT + (uint32_t)(row*80 + col*2));
            }
            uint32_t b[4][4];
#pragma unroll
            for (int g = 0; g < 4; g++) {
                int n  = wn*64 + g*16 + b_nrow;
                int kc = ks*16 + b_kc;
                ldsm4(b[g], bT + (uint32_t)(n*80 + kc*2));
            }
#pragma unroll
            for (int i = 0; i < 2; i++)
#pragma unroll
                for (int g = 0; g < 4; g++) {
                    mma16816(acc[i][2*g],   a[i], b[g][0], b[g][1]);
                    mma16816(acc[i][2*g+1], a[i], b[g][2], b[g][3]);
                }
        }
    }

    // epilogue
    const int rb = m0 + wm*32;
    const int cb = n0 + wn*64;
#pragma unroll
    for (int i = 0; i < 2; i++)
#pragma unroll
        for (int j = 0; j < 8; j++) {
            int c = cb + j*8 + (lane & 3)*2;
            if (c < N) {
                int r = rb + i*16 + (lane >> 2);
                float2 v0 = make_float2(acc[i][j][0], acc[i][j][1]);
                float2 v1 = make_float2(acc[i][j][2], acc[i][j][3]);
                *(float2*)&C[(size_t)r * N + c]       = v0;
                *(float2*)&C[(size_t)(r+8) * N + c]   = v1;
            }
        }
}

// ---------------- RMSNorm ----------------
__global__ void rmsnorm_k(const float* __restrict__ in, const float* __restrict__ w,
                          float* __restrict__ out, int W)
{
    const int row = blockIdx.x;
    const float* x = in + (size_t)row * W;
    float ss = 0.f;
    for (int i = threadIdx.x; i < W; i += blockDim.x) { float v = x[i]; ss += v * v; }
    __shared__ float red[32];
#pragma unroll
    for (int o = 16; o; o >>= 1) ss += __shfl_down_sync(0xffffffffu, ss, o);
    if ((threadIdx.x & 31) == 0) red[threadIdx.x >> 5] = ss;
    __syncthreads();
    if (threadIdx.x < 32) {
        float v = (threadIdx.x < (blockDim.x >> 5)) ? red[threadIdx.x] : 0.f;
#pragma unroll
        for (int o = 16; o; o >>= 1) v += __shfl_down_sync(0xffffffffu, v, o);
        if (threadIdx.x == 0) red[0] = rsqrtf(v / (float)W + 1e-6f);
    }
    __syncthreads();
    float r = red[0];
    for (int i = threadIdx.x; i < W; i += blockDim.x)
        out[(size_t)row * W + i] = x[i] * r * w[i];
}

// ---------------- RoPE ----------------
__global__ void rope_k(float* __restrict__ x, int nheads, int d, int total_pairs)
{
    int idx = blockIdx.x * blockDim.x + threadIdx.x;
    if (idx >= total_pairs) return;
    int pairs_per_row = nheads * (d / 2);
    int row = idx / pairs_per_row;
    int p   = idx % pairs_per_row;
    int h = p / (d / 2);
    int i = p % (d / 2);
    int pos = row % SS;
    float inv = powf(10000.f, (-2.0f * (float)i) / (float)d);
    float ang = (float)pos * inv;
    float s, c;
    sincosf(ang, &s, &c);
    float* base = x + (size_t)row * nheads * d + h * d + 2 * i;
    float x1 = base[0], x2 = base[1];
    base[0] = x1 * c - x2 * s;
    base[1] = x1 * s + x2 * c;
}

// ---------------- causal flash attention (shared-exp softmax) ----------------
__global__ __launch_bounds__(256) void attn_k(
    const float* __restrict__ qn, const float* __restrict__ qp,
    const float* __restrict__ kv, const float* __restrict__ kr,
    float* __restrict__ o)
{
    extern __shared__ float sm[];
    float* Qs  = sm;                   // 32 x 193
    float* KsT = Qs + 32 * 193;        // 192 x 32
    float* Vs  = KsT + 192 * 32;       // 32 x 128
    float* Ps  = Vs + 32 * 128;        // 32 x 33

    const int qt = blockIdx.x, h = blockIdx.y, b = blockIdx.z;
    const int q0 = qt * 32;
    const int tid = threadIdx.x;
    const int qi = tid >> 3, sub = tid & 7;
    const float scale = rsqrtf(192.f);

    for (int l = tid; l < 32 * 192; l += 256) {
        int r = l / 192, d = l % 192;
        size_t m = (size_t)(b * SS + q0 + r);
        float v = (d < 128) ? qn[m * (NH * DN) + h * DN + d]
                            : qp[m * (NH * DR) + h * DR + (d - 128)];
        Qs[r * 193 + d] = v * scale;
    }

    float acc[16];
#pragma unroll
    for (int d = 0; d < 16; d++) acc[d] = 0.f;
    float m_run = -INFINITY, l_run = 0.f;

    const int ntiles = qt + 1;
    for (int kt = 0; kt < ntiles; kt++) {
        const int k0 = kt * 32;
        __syncthreads();
        for (int l = tid; l < 32 * 192; l += 256) {
            int r = l / 192, d = l % 192;
            size_t m = (size_t)(b * SS + k0 + r);
            float v = (d < 128) ? kv[m * (NH * 256) + h * 256 + d]
                                : kr[m * DR + (d - 128)];
            KsT[d * 32 + r] = v;
        }
        for (int l = tid; l < 32 * 128; l += 256) {
            int r = l >> 7, d = l & 127;
            size_t m = (size_t)(b * SS + k0 + r);
            Vs[r * 128 + d] = kv[m * (NH * 256) + h * 256 + 128 + d];
        }
        __syncthreads();

        // raw scores -> Ps
        {
            float s0 = 0.f, s1 = 0.f, s2 = 0.f, s3 = 0.f;
            const float* qrow = Qs + qi * 193;
#pragma unroll 8
            for (int t = 0; t < 192; t++) {
                float q = qrow[t];
                float4 kk = *(const float4*)&KsT[t * 32 + sub * 4];
                s0 = fmaf(q, kk.x, s0); s1 = fmaf(q, kk.y, s1);
                s2 = fmaf(q, kk.z, s2); s3 = fmaf(q, kk.w, s3);
            }
            float sv[4] = {s0, s1, s2, s3};
#pragma unroll
            for (int i = 0; i < 4; i++) {
                int kj = sub * 4 + i;
                bool ok = (k0 + kj) <= (q0 + qi);
                Ps[qi * 33 + kj] = ok ? sv[i] : -INFINITY;
            }
        }
        __syncthreads();

        // online softmax: exp computed once per score (shared via Ps)
        {
            float* prow = Ps + qi * 33;
            float tmax = -INFINITY;
#pragma unroll
            for (int j = 0; j < 32; j++) tmax = fmaxf(tmax, prow[j]);
            float new_m = fmaxf(m_run, tmax);
            float factor = __expf(m_run - new_m);
            __syncwarp();
#pragma unroll
            for (int i = 0; i < 4; i++) {
                int kj = sub * 4 + i;
                prow[kj] = __expf(prow[kj] - new_m);
            }
            __syncwarp();
            float lsum = 0.f;
#pragma unroll
            for (int j = 0; j < 32; j++) lsum += prow[j];
            l_run = l_run * factor + lsum;
#pragma unroll
            for (int d = 0; d < 16; d++) acc[d] *= factor;
#pragma unroll 4
            for (int j = 0; j < 32; j++) {
                float p = prow[j];
                const float4* vrow = (const float4*)&Vs[j * 128 + sub * 16];
#pragma unroll
                for (int d4 = 0; d4 < 4; d4++) {
                    float4 vv = vrow[d4];
                    acc[d4*4+0] = fmaf(p, vv.x, acc[d4*4+0]);
                    acc[d4*4+1] = fmaf(p, vv.y, acc[d4*4+1]);
                    acc[d4*4+2] = fmaf(p, vv.z, acc[d4*4+2]);
                    acc[d4*4+3] = fmaf(p, vv.w, acc[d4*4+3]);
                }
            }
            m_run = new_m;
        }
    }

    float inv_l = 1.f / l_run;
    size_t m = (size_t)(b * SS + q0 + qi);
    float* orow = o + m * (NH * DVV) + h * DVV + sub * 16;
#pragma unroll
    for (int d = 0; d < 16; d++) orow[d] = acc[d] * inv_l;
}

// ---------------- host orchestration ----------------
static void conv3(const float* in, __nv_bfloat16* out, int R, int Rpad, int C, int mode)
{
    long long tot = (long long)Rpad * C;
    int blocks = (int)((tot + 255) / 256);
    split3_k<<<blocks, 256>>>(in, out, R, Rpad, C, mode);
}

static void gemm3(const __nv_bfloat16* A, const __nv_bfloat16* B, float* C, int M, int N, int Kp)
{
    cudaFuncSetAttribute(gemm_tc, cudaFuncAttributeMaxDynamicSharedMemorySize, GEMM_SMEM);
    dim3 grid((N + 127) / 128, M / 128);
    gemm_tc<<<grid, 256, GEMM_SMEM>>>(A, B, C, M, N, Kp);
}

extern "C" void kernel_launch(void* const* d_in, const int* in_sizes, int n_in,
                              void* d_out, int out_size)
{
    const float* x        = (const float*)d_in[0];
    const float* wq_down  = (const float*)d_in[1];
    const float* q_norm_w = (const float*)d_in[2];
    const float* wq_up    = (const float*)d_in[3];
    const float* wq_rope  = (const float*)d_in[4];
    const float* wkv_down = (const float*)d_in[5];
    const float* kv_norm_w= (const float*)d_in[6];
    const float* wkv_up   = (const float*)d_in[7];
    const float* wk_rope  = (const float*)d_in[8];
    const float* wo       = (const float*)d_in[9];
    float* out = (float*)d_out;

    float *qc, *kvc, *qn, *qp, *kvu, *kr, *at;
    cudaGetSymbolAddress((void**)&qc,  g_qc);
    cudaGetSymbolAddress((void**)&kvc, g_kvc);
    cudaGetSymbolAddress((void**)&qn,  g_qnope);
    cudaGetSymbolAddress((void**)&qp,  g_qpe);
    cudaGetSymbolAddress((void**)&kvu, g_kvup);
    cudaGetSymbolAddress((void**)&kr,  g_krope);
    cudaGetSymbolAddress((void**)&at,  g_attn);

    __nv_bfloat16 *xs, *wqd, *wkvd, *wkr, *qcs, *wqu, *wqr, *kvcs, *wkvu, *ats, *wos;
    cudaGetSymbolAddress((void**)&xs,   g_xs);
    cudaGetSymbolAddress((void**)&wqd,  g_wqd);
    cudaGetSymbolAddress((void**)&wkvd, g_wkvd);
    cudaGetSymbolAddress((void**)&wkr,  g_wkr);
    cudaGetSymbolAddress((void**)&qcs,  g_qcs);
    cudaGetSymbolAddress((void**)&wqu,  g_wqu);
    cudaGetSymbolAddress((void**)&wqr,  g_wqr);
    cudaGetSymbolAddress((void**)&kvcs, g_kvcs);
    cudaGetSymbolAddress((void**)&wkvu, g_wkvu);
    cudaGetSymbolAddress((void**)&ats,  g_ats);
    cudaGetSymbolAddress((void**)&wos,  g_wos);

    // --- stage 1: down projections (K' = 6144) ---
    conv3(x,        xs,   MT,   MT,  DIMM, 0);
    conv3(wq_down,  wqd,  QR,   QR,  DIMM, 1);
    conv3(wkv_down, wkvd, KVR,  KVR, DIMM, 1);
    conv3(wk_rope,  wkr,  DR,   128, DIMM, 1);

    gemm3(xs, wqd,  qc,  MT, QR,  3*DIMM);
    gemm3(xs, wkvd, kvc, MT, KVR, 3*DIMM);
    gemm3(xs, wkr,  kr,  MT, DR,  3*DIMM);

    // --- rmsnorm ---
    rmsnorm_k<<<MT, 256>>>(qc,  q_norm_w,  qc,  QR);
    rmsnorm_k<<<MT, 256>>>(kvc, kv_norm_w, kvc, KVR);

    // --- stage 2: up projections ---
    conv3(qc,      qcs,  MT,           MT,           QR,  0);
    conv3(wq_up,   wqu,  NH*DN,        NH*DN,        QR,  1);
    conv3(wq_rope, wqr,  NH*DR,        NH*DR,        QR,  1);
    conv3(kvc,     kvcs, MT,           MT,           KVR, 0);
    conv3(wkv_up,  wkvu, NH*(DN+DVV),  NH*(DN+DVV),  KVR, 1);

    gemm3(qcs,  wqu,  qn,  MT, NH*DN,       3*QR);
    gemm3(qcs,  wqr,  qp,  MT, NH*DR,       3*QR);
    gemm3(kvcs, wkvu, kvu, MT, NH*(DN+DVV), 3*KVR);

    // --- rope ---
    {
        int tot = MT * NH * (DR / 2);
        rope_k<<<(tot + 255) / 256, 256>>>(qp, NH, DR, tot);
    }
    {
        int tot = MT * 1 * (DR / 2);
        rope_k<<<(tot + 255) / 256, 256>>>(kr, 1, DR, tot);
    }

    // --- attention ---
    size_t shbytes = (size_t)(32*193 + 192*32 + 32*128 + 32*33) * sizeof(float);
    cudaFuncSetAttribute(attn_k, cudaFuncAttributeMaxDynamicSharedMemorySize, (int)shbytes);
    attn_k<<<dim3(SS/32, NH, BB), 256, shbytes>>>(qn, qp, kvu, kr, at);

    // --- output projection (K' = 6144) ---
    conv3(at, ats, MT,   MT,   NH*DVV, 0);
    conv3(wo, wos, DIMM, DIMM, NH*DVV, 1);
    gemm3(ats, wos, out, MT, DIMM, 3*(NH*DVV));
}

// round 4
// speedup vs baseline: 1.2832x; 1.0817x over previous
#include <cuda_runtime.h>
#include <cuda_bf16.h>
#include <math.h>
#include <stdint.h>

#define BB 2
#define SS 2048
#define DIMM 2048
#define NH 16
#define QR 1536
#define KVR 512
#define DN 128
#define DR 64
#define DVV 128
#define MT (BB*SS)   // 4096 token rows

// ---------------- fp32 scratch ----------------
__device__ float g_qc[MT*QR];
__device__ float g_kvc[MT*KVR];
__device__ float g_qnope[MT*NH*DN];
__device__ float g_qpe[MT*NH*DR];
__device__ float g_kvup[MT*NH*(DN+DVV)];
__device__ float g_krope[MT*DR];
__device__ float g_attn[MT*NH*DVV];

// ---------------- bf16 split scratch (K' = 3K) ----------------
__device__ __nv_bfloat16 g_xs  [MT   * 3*DIMM];
__device__ __nv_bfloat16 g_wqd [QR   * 3*DIMM];
__device__ __nv_bfloat16 g_wkvd[KVR  * 3*DIMM];
__device__ __nv_bfloat16 g_wkr [128  * 3*DIMM];   // padded 64->128 rows
__device__ __nv_bfloat16 g_qcs [MT   * 3*QR];
__device__ __nv_bfloat16 g_wqu [(NH*DN) * 3*QR];
__device__ __nv_bfloat16 g_wqr [(NH*DR) * 3*QR];
__device__ __nv_bfloat16 g_kvcs[MT   * 3*KVR];
__device__ __nv_bfloat16 g_wkvu[(NH*(DN+DVV)) * 3*KVR];
__device__ __nv_bfloat16 g_ats [MT   * 3*(NH*DVV)];
__device__ __nv_bfloat16 g_wos [DIMM * 3*(NH*DVV)];

// ============================================================
// helpers (base sm_103-safe PTX: cp.async / ldmatrix / mma.sync)
// ============================================================
__device__ __forceinline__ uint32_t smem_u32(const void* p){
    uint32_t a;
    asm("{ .reg .u64 t; cvta.to.shared.u64 t, %1; cvt.u32.u64 %0, t; }" : "=r"(a) : "l"(p));
    return a;
}
#define CPA16(dst, src) asm volatile("cp.async.cg.shared.global [%0], [%1], 16;" :: "r"(dst), "l"(src))
#define CPCOMMIT()      asm volatile("cp.async.commit_group;")
#define CPWAIT(n)       asm volatile("cp.async.wait_group %0;" :: "n"(n))

__device__ __forceinline__ void ldsm4(uint32_t* r, uint32_t addr){
    asm volatile("ldmatrix.sync.aligned.m8n8.x4.shared.b16 {%0,%1,%2,%3}, [%4];"
        : "=r"(r[0]), "=r"(r[1]), "=r"(r[2]), "=r"(r[3]) : "r"(addr));
}
__device__ __forceinline__ void mma16816(float* c, const uint32_t* a, uint32_t b0, uint32_t b1){
    asm volatile("mma.sync.aligned.m16n8k16.row.col.f32.bf16.bf16.f32 "
        "{%0,%1,%2,%3}, {%4,%5,%6,%7}, {%8,%9}, {%0,%1,%2,%3};"
        : "+f"(c[0]), "+f"(c[1]), "+f"(c[2]), "+f"(c[3])
        : "r"(a[0]), "r"(a[1]), "r"(a[2]), "r"(a[3]), "r"(b0), "r"(b1));
}
// XOR swizzle for 128-byte rows: row r, 16B-chunk c (0..7)
__device__ __forceinline__ uint32_t sw128(int row, int chunk){
    return (uint32_t)(row * 128 + ((chunk ^ (row & 7)) * 16));
}

// ============================================================
// split-3 conversion: out [Rpad, 3C] bf16 from in [R, C] fp32
// mode 0 (A): [hi | lo | hi]    mode 1 (B): [hi | hi | lo]
// ============================================================
__global__ void split3_k(const float* __restrict__ in, __nv_bfloat16* __restrict__ out,
                         int R, int Rpad, int C, int mode)
{
    long long i = (long long)blockIdx.x * blockDim.x + threadIdx.x;
    long long tot = (long long)Rpad * C;
    if (i >= tot) return;
    int r = (int)(i / C), c = (int)(i % C);
    float x = (r < R) ? in[(size_t)r * C + c] : 0.f;
    __nv_bfloat16 h = __float2bfloat16(x);
    __nv_bfloat16 l = __float2bfloat16(x - __bfloat162float(h));
    size_t base = (size_t)r * 3 * C;
    if (mode == 0) { out[base + c] = h; out[base + C + c] = l; out[base + 2*C + c] = h; }
    else           { out[base + c] = h; out[base + C + c] = h; out[base + 2*C + c] = l; }
}

// ============================================================
// mma.sync bf16 GEMM: C[M,N] = A[M,Kp] * B[N,Kp]^T, fp32 out
// BM=BN=128, BK=64, 3 stages cp.async, 8 warps (32x64 each).
// M%128==0, Kp%64==0, B buffer has ceil(N,128) rows, N%8==0.
// ============================================================
#define STAGES 3
#define STAGE_BYTES 32768               // A: 128*128B, B: 128*128B
#define GEMM_SMEM (STAGES*STAGE_BYTES)  // 98304

__global__ __launch_bounds__(256, 2) void gemm_tc(
    const __nv_bfloat16* __restrict__ A, const __nv_bfloat16* __restrict__ B,
    float* __restrict__ C, int M, int N, int Kp)
{
    extern __shared__ __align__(16) char smem[];
    const uint32_t sb = smem_u32(smem);
    const int m0 = blockIdx.y * 128, n0 = blockIdx.x * 128;
    const int tid = threadIdx.x, lane = tid & 31;
    const int wm = (tid >> 5) & 3;      // 0..3 -> 32-row slice
    const int wn = tid >> 7;            // 0..1 -> 64-col slice

    float acc[2][8][4];
#pragma unroll
    for (int i = 0; i < 2; i++)
#pragma unroll
        for (int j = 0; j < 8; j++)
#pragma unroll
            for (int q = 0; q < 4; q++) acc[i][j][q] = 0.f;

    const int KT = Kp >> 6;   // Kp / 64
    const __nv_bfloat16* Ag0 = A + (size_t)m0 * Kp;
    const __nv_bfloat16* Bg0 = B + (size_t)n0 * Kp;

    const int fr = tid >> 3;         // 0..31 base row step
    const int fc = tid & 7;          // chunk 0..7

    auto fill = [&](int j){
        uint32_t base = sb + (uint32_t)(j % STAGES) * STAGE_BYTES;
        int k0 = j << 6;
#pragma unroll
        for (int i = 0; i < 4; i++) {
            int r = fr + i * 32;
            CPA16(base + sw128(r, fc), Ag0 + (size_t)r * Kp + k0 + fc*8);
        }
#pragma unroll
        for (int i = 0; i < 4; i++) {
            int r = fr + i * 32;
            CPA16(base + 16384u + sw128(r, fc), Bg0 + (size_t)r * Kp + k0 + fc*8);
        }
        CPCOMMIT();
    };

    fill(0);
    fill(1);

    const int a_row  = lane & 15;
    const int a_ch   = lane >> 4;        // 0/1
    const int b_nrow = (lane & 7) + ((lane & 16) ? 8 : 0);
    const int b_ch   = (lane >> 3) & 1;  // 0/1

    for (int kt = 0; kt < KT; kt++) {
        CPWAIT(1);
        __syncthreads();
        if (kt + 2 < KT) fill(kt + 2);
        else CPCOMMIT();

        uint32_t aT = sb + (uint32_t)(kt % STAGES) * STAGE_BYTES;
        uint32_t bT = aT + 16384u;
#pragma unroll
        for (int ks = 0; ks < 4; ks++) {
            uint32_t a[2][4];
#pragma unroll
            for (int i = 0; i < 2; i++)
                ldsm4(a[i], aT + sw128(wm*32 + i*16 + a_row, ks*2 + a_ch));
            uint32_t b[4][4];
#pragma unroll
            for (int g = 0; g < 4; g++)
                ldsm4(b[g], bT + sw128(wn*64 + g*16 + b_nrow, ks*2 + b_ch));
#pragma unroll
            for (int i = 0; i < 2; i++)
#pragma unroll
                for (int g = 0; g < 4; g++) {
                    mma16816(acc[i][2*g],   a[i], b[g][0], b[g][1]);
                    mma16816(acc[i][2*g+1], a[i], b[g][2], b[g][3]);
                }
        }
        __syncthreads();
    }

    // epilogue
    const int rb = m0 + wm*32;
    const int cb = n0 + wn*64;
#pragma unroll
    for (int i = 0; i < 2; i++)
#pragma unroll
        for (int j = 0; j < 8; j++) {
            int c = cb + j*8 + (lane & 3)*2;
            if (c < N) {
                int r = rb + i*16 + (lane >> 2);
                *(float2*)&C[(size_t)r * N + c]     = make_float2(acc[i][j][0], acc[i][j][1]);
                *(float2*)&C[(size_t)(r+8) * N + c] = make_float2(acc[i][j][2], acc[i][j][3]);
            }
        }
}

// ---------------- RMSNorm ----------------
__global__ void rmsnorm_k(const float* __restrict__ in, const float* __restrict__ w,
                          float* __restrict__ out, int W)
{
    const int row = blockIdx.x;
    const float* x = in + (size_t)row * W;
    float ss = 0.f;
    for (int i = threadIdx.x; i < W; i += blockDim.x) { float v = x[i]; ss += v * v; }
    __shared__ float red[32];
#pragma unroll
    for (int o = 16; o; o >>= 1) ss += __shfl_down_sync(0xffffffffu, ss, o);
    if ((threadIdx.x & 31) == 0) red[threadIdx.x >> 5] = ss;
    __syncthreads();
    if (threadIdx.x < 32) {
        float v = (threadIdx.x < (blockDim.x >> 5)) ? red[threadIdx.x] : 0.f;
#pragma unroll
        for (int o = 16; o; o >>= 1) v += __shfl_down_sync(0xffffffffu, v, o);
        if (threadIdx.x == 0) red[0] = rsqrtf(v / (float)W + 1e-6f);
    }
    __syncthreads();
    float r = red[0];
    for (int i = threadIdx.x; i < W; i += blockDim.x)
        out[(size_t)row * W + i] = x[i] * r * w[i];
}

// ---------------- RoPE ----------------
__global__ void rope_k(float* __restrict__ x, int nheads, int d, int total_pairs)
{
    int idx = blockIdx.x * blockDim.x + threadIdx.x;
    if (idx >= total_pairs) return;
    int pairs_per_row = nheads * (d / 2);
    int row = idx / pairs_per_row;
    int p   = idx % pairs_per_row;
    int h = p / (d / 2);
    int i = p % (d / 2);
    int pos = row % SS;
    float inv = powf(10000.f, (-2.0f * (float)i) / (float)d);
    float ang = (float)pos * inv;
    float s, c;
    sincosf(ang, &s, &c);
    float* base = x + (size_t)row * nheads * d + h * d + 2 * i;
    float x1 = base[0], x2 = base[1];
    base[0] = x1 * c - x2 * s;
    base[1] = x1 * s + x2 * c;
}

// ---------------- causal flash attention (fp32, shared-exp) ----------------
#define QPITCH 196
#define PPITCH 36
__global__ __launch_bounds__(256) void attn_k(
    const float* __restrict__ qn, const float* __restrict__ qp,
    const float* __restrict__ kv, const float* __restrict__ kr,
    float* __restrict__ o)
{
    extern __shared__ float sm[];
    float* Qs  = sm;                      // 32 x QPITCH
    float* KsT = Qs + 32 * QPITCH;        // 192 x 32
    float* Vs  = KsT + 192 * 32;          // 32 x 128
    float* Ps  = Vs + 32 * 128;           // 32 x PPITCH

    const int qt = blockIdx.x, h = blockIdx.y, b = blockIdx.z;
    const int q0 = qt * 32;
    const int tid = threadIdx.x;
    const int qi = tid >> 3, sub = tid & 7;
    const float scale = rsqrtf(192.f);

    for (int l = tid; l < 32 * 192; l += 256) {
        int r = l / 192, d = l % 192;
        size_t m = (size_t)(b * SS + q0 + r);
        float v = (d < 128) ? qn[m * (NH * DN) + h * DN + d]
                            : qp[m * (NH * DR) + h * DR + (d - 128)];
        Qs[r * QPITCH + d] = v * scale;
    }

    float acc[16];
#pragma unroll
    for (int d = 0; d < 16; d++) acc[d] = 0.f;
    float m_run = -INFINITY, l_run = 0.f;

    const int ntiles = qt + 1;
    for (int kt = 0; kt < ntiles; kt++) {
        const int k0 = kt * 32;
        __syncthreads();
        for (int l = tid; l < 32 * 192; l += 256) {
            int r = l / 192, d = l % 192;
            size_t m = (size_t)(b * SS + k0 + r);
            float v = (d < 128) ? kv[m * (NH * 256) + h * 256 + d]
                                : kr[m * DR + (d - 128)];
            KsT[d * 32 + r] = v;
        }
        for (int l = tid; l < 32 * 128; l += 256) {
            int r = l >> 7, d = l & 127;
            size_t m = (size_t)(b * SS + k0 + r);
            Vs[r * 128 + d] = kv[m * (NH * 256) + h * 256 + 128 + d];
        }
        __syncthreads();

        // raw scores -> Ps
        {
            float s0 = 0.f, s1 = 0.f, s2 = 0.f, s3 = 0.f;
            const float4* q4 = (const float4*)(Qs + qi * QPITCH);
#pragma unroll 4
            for (int t4 = 0; t4 < 48; t4++) {
                float4 q = q4[t4];
                const float* kbase = &KsT[t4 * 4 * 32 + sub * 4];
                float4 k0v = *(const float4*)(kbase);
                float4 k1v = *(const float4*)(kbase + 32);
                float4 k2v = *(const float4*)(kbase + 64);
                float4 k3v = *(const float4*)(kbase + 96);
                s0 = fmaf(q.x, k0v.x, s0); s1 = fmaf(q.x, k0v.y, s1);
                s2 = fmaf(q.x, k0v.z, s2); s3 = fmaf(q.x, k0v.w, s3);
                s0 = fmaf(q.y, k1v.x, s0); s1 = fmaf(q.y, k1v.y, s1);
                s2 = fmaf(q.y, k1v.z, s2); s3 = fmaf(q.y, k1v.w, s3);
                s0 = fmaf(q.z, k2v.x, s0); s1 = fmaf(q.z, k2v.y, s1);
                s2 = fmaf(q.z, k2v.z, s2); s3 = fmaf(q.z, k2v.w, s3);
                s0 = fmaf(q.w, k3v.x, s0); s1 = fmaf(q.w, k3v.y, s1);
                s2 = fmaf(q.w, k3v.z, s2); s3 = fmaf(q.w, k3v.w, s3);
            }
            float sv[4] = {s0, s1, s2, s3};
#pragma unroll
            for (int i = 0; i < 4; i++) {
                int kj = sub * 4 + i;
                bool ok = (k0 + kj) <= (q0 + qi);
                Ps[qi * PPITCH + kj] = ok ? sv[i] : -INFINITY;
            }
        }
        __syncthreads();

        // online softmax: exp computed once per score (shared via Ps)
        {
            float* prow = Ps + qi * PPITCH;
            float tmax = -INFINITY;
#pragma unroll
            for (int j4 = 0; j4 < 8; j4++) {
                float4 v = *(const float4*)(prow + j4*4);
                tmax = fmaxf(tmax, fmaxf(fmaxf(v.x, v.y), fmaxf(v.z, v.w)));
            }
            float new_m = fmaxf(m_run, tmax);
            float factor = __expf(m_run - new_m);
            __syncwarp();
#pragma unroll
            for (int i = 0; i < 4; i++) {
                int kj = sub * 4 + i;
                prow[kj] = __expf(prow[kj] - new_m);
            }
            __syncwarp();
            float lsum = 0.f;
#pragma unroll
            for (int j4 = 0; j4 < 8; j4++) {
                float4 v = *(const float4*)(prow + j4*4);
                lsum += (v.x + v.y) + (v.z + v.w);
            }
            l_run = l_run * factor + lsum;
#pragma unroll
            for (int d = 0; d < 16; d++) acc[d] *= factor;
#pragma unroll 4
            for (int j = 0; j < 32; j++) {
                float p = prow[j];
                const float4* vrow = (const float4*)&Vs[j * 128 + sub * 16];
#pragma unroll
                for (int d4 = 0; d4 < 4; d4++) {
                    float4 vv = vrow[d4];
                    acc[d4*4+0] = fmaf(p, vv.x, acc[d4*4+0]);
                    acc[d4*4+1] = fmaf(p, vv.y, acc[d4*4+1]);
                    acc[d4*4+2] = fmaf(p, vv.z, acc[d4*4+2]);
                    acc[d4*4+3] = fmaf(p, vv.w, acc[d4*4+3]);
                }
            }
            m_run = new_m;
        }
    }

    float inv_l = 1.f / l_run;
    size_t m = (size_t)(b * SS + q0 + qi);
    float* orow = o + m * (NH * DVV) + h * DVV + sub * 16;
#pragma unroll
    for (int d = 0; d < 16; d++) orow[d] = acc[d] * inv_l;
}

// ---------------- host orchestration ----------------
static void conv3(const float* in, __nv_bfloat16* out, int R, int Rpad, int C, int mode)
{
    long long tot = (long long)Rpad * C;
    int blocks = (int)((tot + 255) / 256);
    split3_k<<<blocks, 256>>>(in, out, R, Rpad, C, mode);
}

static void gemm3(const __nv_bfloat16* A, const __nv_bfloat16* B, float* C, int M, int N, int Kp)
{
    cudaFuncSetAttribute(gemm_tc, cudaFuncAttributeMaxDynamicSharedMemorySize, GEMM_SMEM);
    dim3 grid((N + 127) / 128, M / 128);
    gemm_tc<<<grid, 256, GEMM_SMEM>>>(A, B, C, M, N, Kp);
}

extern "C" void kernel_launch(void* const* d_in, const int* in_sizes, int n_in,
                              void* d_out, int out_size)
{
    const float* x        = (const float*)d_in[0];
    const float* wq_down  = (const float*)d_in[1];
    const float* q_norm_w = (const float*)d_in[2];
    const float* wq_up    = (const float*)d_in[3];
    const float* wq_rope  = (const float*)d_in[4];
    const float* wkv_down = (const float*)d_in[5];
    const float* kv_norm_w= (const float*)d_in[6];
    const float* wkv_up   = (const float*)d_in[7];
    const float* wk_rope  = (const float*)d_in[8];
    const float* wo       = (const float*)d_in[9];
    float* out = (float*)d_out;

    float *qc, *kvc, *qn, *qp, *kvu, *kr, *at;
    cudaGetSymbolAddress((void**)&qc,  g_qc);
    cudaGetSymbolAddress((void**)&kvc, g_kvc);
    cudaGetSymbolAddress((void**)&qn,  g_qnope);
    cudaGetSymbolAddress((void**)&qp,  g_qpe);
    cudaGetSymbolAddress((void**)&kvu, g_kvup);
    cudaGetSymbolAddress((void**)&kr,  g_krope);
    cudaGetSymbolAddress((void**)&at,  g_attn);

    __nv_bfloat16 *xs, *wqd, *wkvd, *wkr, *qcs, *wqu, *wqr, *kvcs, *wkvu, *ats, *wos;
    cudaGetSymbolAddress((void**)&xs,   g_xs);
    cudaGetSymbolAddress((void**)&wqd,  g_wqd);
    cudaGetSymbolAddress((void**)&wkvd, g_wkvd);
    cudaGetSymbolAddress((void**)&wkr,  g_wkr);
    cudaGetSymbolAddress((void**)&qcs,  g_qcs);
    cudaGetSymbolAddress((void**)&wqu,  g_wqu);
    cudaGetSymbolAddress((void**)&wqr,  g_wqr);
    cudaGetSymbolAddress((void**)&kvcs, g_kvcs);
    cudaGetSymbolAddress((void**)&wkvu, g_wkvu);
    cudaGetSymbolAddress((void**)&ats,  g_ats);
    cudaGetSymbolAddress((void**)&wos,  g_wos);

    // launch order arranged so the biggest GEMM is launch index 3 (profiled)
    conv3(x,        xs,   MT,   MT,  DIMM, 0);   // 0
    conv3(wq_down,  wqd,  QR,   QR,  DIMM, 1);   // 1
    conv3(wkv_down, wkvd, KVR,  KVR, DIMM, 1);   // 2
    gemm3(xs, wqd,  qc,  MT, QR,  3*DIMM);       // 3  <- profile target
    conv3(wk_rope,  wkr,  DR,   128, DIMM, 1);   // 4
    gemm3(xs, wkvd, kvc, MT, KVR, 3*DIMM);       // 5
    gemm3(xs, wkr,  kr,  MT, DR,  3*DIMM);       // 6

    rmsnorm_k<<<MT, 256>>>(qc,  q_norm_w,  qc,  QR);
    rmsnorm_k<<<MT, 256>>>(kvc, kv_norm_w, kvc, KVR);

    conv3(qc,      qcs,  MT,           MT,           QR,  0);
    conv3(wq_up,   wqu,  NH*DN,        NH*DN,        QR,  1);
    conv3(wq_rope, wqr,  NH*DR,        NH*DR,        QR,  1);
    conv3(kvc,     kvcs, MT,           MT,           KVR, 0);
    conv3(wkv_up,  wkvu, NH*(DN+DVV),  NH*(DN+DVV),  KVR, 1);

    gemm3(qcs,  wqu,  qn,  MT, NH*DN,       3*QR);
    gemm3(qcs,  wqr,  qp,  MT, NH*DR,       3*QR);
    gemm3(kvcs, wkvu, kvu, MT, NH*(DN+DVV), 3*KVR);

    {
        int tot = MT * NH * (DR / 2);
        rope_k<<<(tot + 255) / 256, 256>>>(qp, NH, DR, tot);
    }
    {
        int tot = MT * 1 * (DR / 2);
        rope_k<<<(tot + 255) / 256, 256>>>(kr, 1, DR, tot);
    }

    size_t shbytes = (size_t)(32*QPITCH + 192*32 + 32*128 + 32*PPITCH) * sizeof(float);
    cudaFuncSetAttribute(attn_k, cudaFuncAttributeMaxDynamicSharedMemorySize, (int)shbytes);
    attn_k<<<dim3(SS/32, NH, BB), 256, shbytes>>>(qn, qp, kvu, kr, at);

    conv3(at, ats, MT,   MT,   NH*DVV, 0);
    conv3(wo, wos, DIMM, DIMM, NH*DVV, 1);
    gemm3(ats, wos, out, MT, DIMM, 3*(NH*DVV));
}

// round 5
// speedup vs baseline: 5.9094x; 4.6052x over previous
#include <cuda_runtime.h>
#include <cuda_bf16.h>
#include <math.h>
#include <stdint.h>

#define BB 2
#define SS 2048
#define DIMM 2048
#define NH 16
#define QR 1536
#define KVR 512
#define DN 128
#define DR 64
#define DVV 128
#define MT (BB*SS)   // 4096 token rows

// ---------------- fp32 scratch ----------------
__device__ float g_qc[MT*QR];
__device__ float g_kvc[MT*KVR];
__device__ float g_qnope[MT*NH*DN];
__device__ float g_qpe[MT*NH*DR];
__device__ float g_kvup[MT*NH*(DN+DVV)];
__device__ float g_krope[MT*DR];

// ---------------- bf16 split scratch (K' = 3K) ----------------
__device__ __nv_bfloat16 g_xs  [MT   * 3*DIMM];
__device__ __nv_bfloat16 g_wqd [QR   * 3*DIMM];
__device__ __nv_bfloat16 g_wkvd[KVR  * 3*DIMM];
__device__ __nv_bfloat16 g_wkr [128  * 3*DIMM];
__device__ __nv_bfloat16 g_qcs [MT   * 3*QR];
__device__ __nv_bfloat16 g_wqu [(NH*DN) * 3*QR];
__device__ __nv_bfloat16 g_wqr [(NH*DR) * 3*QR];
__device__ __nv_bfloat16 g_kvcs[MT   * 3*KVR];
__device__ __nv_bfloat16 g_wkvu[(NH*(DN+DVV)) * 3*KVR];
__device__ __nv_bfloat16 g_ats [MT   * 3*(NH*DVV)];
__device__ __nv_bfloat16 g_wos [DIMM * 3*(NH*DVV)];

// ---------------- attention packed operands ----------------
__device__ __nv_bfloat16 g_qsp[BB*NH*SS*576];        // [bh][s][Qh|Ql|Qh]
__device__ __nv_bfloat16 g_ksp[BB*NH*SS*576];        // [bh][s][Kh|Kh|Kl]
__device__ __nv_bfloat16 g_vt [BB*NH*128*3*SS];      // [bh][d][tile*192 + [Vh|Vh|Vl]]

// ============================================================
// helpers (base sm_103-safe PTX: cp.async / ldmatrix / mma.sync)
// ============================================================
__device__ __forceinline__ uint32_t smem_u32(const void* p){
    uint32_t a;
    asm("{ .reg .u64 t; cvta.to.shared.u64 t, %1; cvt.u32.u64 %0, t; }" : "=r"(a) : "l"(p));
    return a;
}
#define CPA16(dst, src) asm volatile("cp.async.cg.shared.global [%0], [%1], 16;" :: "r"(dst), "l"(src))
#define CPCOMMIT()      asm volatile("cp.async.commit_group;")
#define CPWAIT(n)       asm volatile("cp.async.wait_group %0;" :: "n"(n))

__device__ __forceinline__ void ldsm4(uint32_t* r, uint32_t addr){
    asm volatile("ldmatrix.sync.aligned.m8n8.x4.shared.b16 {%0,%1,%2,%3}, [%4];"
        : "=r"(r[0]), "=r"(r[1]), "=r"(r[2]), "=r"(r[3]) : "r"(addr));
}
__device__ __forceinline__ void mma16816(float* c, const uint32_t* a, uint32_t b0, uint32_t b1){
    asm volatile("mma.sync.aligned.m16n8k16.row.col.f32.bf16.bf16.f32 "
        "{%0,%1,%2,%3}, {%4,%5,%6,%7}, {%8,%9}, {%0,%1,%2,%3};"
        : "+f"(c[0]), "+f"(c[1]), "+f"(c[2]), "+f"(c[3])
        : "r"(a[0]), "r"(a[1]), "r"(a[2]), "r"(a[3]), "r"(b0), "r"(b1));
}
__device__ __forceinline__ uint32_t sw128(int row, int chunk){
    return (uint32_t)(row * 128 + ((chunk ^ (row & 7)) * 16));
}

// ============================================================
// split-3 conversion (dense GEMM operands)
// ============================================================
__global__ void split3_k(const float* __restrict__ in, __nv_bfloat16* __restrict__ out,
                         int R, int Rpad, int C, int mode)
{
    long long i = (long long)blockIdx.x * blockDim.x + threadIdx.x;
    long long tot = (long long)Rpad * C;
    if (i >= tot) return;
    int r = (int)(i / C), c = (int)(i % C);
    float x = (r < R) ? in[(size_t)r * C + c] : 0.f;
    __nv_bfloat16 h = __float2bfloat16(x);
    __nv_bfloat16 l = __float2bfloat16(x - __bfloat162float(h));
    size_t base = (size_t)r * 3 * C;
    if (mode == 0) { out[base + c] = h; out[base + C + c] = l; out[base + 2*C + c] = h; }
    else           { out[base + c] = h; out[base + C + c] = h; out[base + 2*C + c] = l; }
}

// ============================================================
// dense mma.sync bf16 GEMM (unchanged from round 4 — verified)
// ============================================================
#define STAGES 3
#define STAGE_BYTES 32768
#define GEMM_SMEM (STAGES*STAGE_BYTES)

__global__ __launch_bounds__(256, 2) void gemm_tc(
    const __nv_bfloat16* __restrict__ A, const __nv_bfloat16* __restrict__ B,
    float* __restrict__ C, int M, int N, int Kp)
{
    extern __shared__ __align__(16) char smem[];
    const uint32_t sb = smem_u32(smem);
    const int m0 = blockIdx.y * 128, n0 = blockIdx.x * 128;
    const int tid = threadIdx.x, lane = tid & 31;
    const int wm = (tid >> 5) & 3;
    const int wn = tid >> 7;

    float acc[2][8][4];
#pragma unroll
    for (int i = 0; i < 2; i++)
#pragma unroll
        for (int j = 0; j < 8; j++)
#pragma unroll
            for (int q = 0; q < 4; q++) acc[i][j][q] = 0.f;

    const int KT = Kp >> 6;
    const __nv_bfloat16* Ag0 = A + (size_t)m0 * Kp;
    const __nv_bfloat16* Bg0 = B + (size_t)n0 * Kp;

    const int fr = tid >> 3;
    const int fc = tid & 7;

    auto fill = [&](int j){
        uint32_t base = sb + (uint32_t)(j % STAGES) * STAGE_BYTES;
        int k0 = j << 6;
#pragma unroll
        for (int i = 0; i < 4; i++) {
            int r = fr + i * 32;
            CPA16(base + sw128(r, fc), Ag0 + (size_t)r * Kp + k0 + fc*8);
        }
#pragma unroll
        for (int i = 0; i < 4; i++) {
            int r = fr + i * 32;
            CPA16(base + 16384u + sw128(r, fc), Bg0 + (size_t)r * Kp + k0 + fc*8);
        }
        CPCOMMIT();
    };

    fill(0);
    fill(1);

    const int a_row  = lane & 15;
    const int a_ch   = lane >> 4;
    const int b_nrow = (lane & 7) + ((lane & 16) ? 8 : 0);
    const int b_ch   = (lane >> 3) & 1;

    for (int kt = 0; kt < KT; kt++) {
        CPWAIT(1);
        __syncthreads();
        if (kt + 2 < KT) fill(kt + 2);
        else CPCOMMIT();

        uint32_t aT = sb + (uint32_t)(kt % STAGES) * STAGE_BYTES;
        uint32_t bT = aT + 16384u;
#pragma unroll
        for (int ks = 0; ks < 4; ks++) {
            uint32_t a[2][4];
#pragma unroll
            for (int i = 0; i < 2; i++)
                ldsm4(a[i], aT + sw128(wm*32 + i*16 + a_row, ks*2 + a_ch));
            uint32_t b[4][4];
#pragma unroll
            for (int g = 0; g < 4; g++)
                ldsm4(b[g], bT + sw128(wn*64 + g*16 + b_nrow, ks*2 + b_ch));
#pragma unroll
            for (int i = 0; i < 2; i++)
#pragma unroll
                for (int g = 0; g < 4; g++) {
                    mma16816(acc[i][2*g],   a[i], b[g][0], b[g][1]);
                    mma16816(acc[i][2*g+1], a[i], b[g][2], b[g][3]);
                }
        }
        __syncthreads();
    }

    const int rb = m0 + wm*32;
    const int cb = n0 + wn*64;
#pragma unroll
    for (int i = 0; i < 2; i++)
#pragma unroll
        for (int j = 0; j < 8; j++) {
            int c = cb + j*8 + (lane & 3)*2;
            if (c < N) {
                int r = rb + i*16 + (lane >> 2);
                *(float2*)&C[(size_t)r * N + c]     = make_float2(acc[i][j][0], acc[i][j][1]);
                *(float2*)&C[(size_t)(r+8) * N + c] = make_float2(acc[i][j][2], acc[i][j][3]);
            }
        }
}

// ---------------- RMSNorm ----------------
__global__ void rmsnorm_k(const float* __restrict__ in, const float* __restrict__ w,
                          float* __restrict__ out, int W)
{
    const int row = blockIdx.x;
    const float* x = in + (size_t)row * W;
    float ss = 0.f;
    for (int i = threadIdx.x; i < W; i += blockDim.x) { float v = x[i]; ss += v * v; }
    __shared__ float red[32];
#pragma unroll
    for (int o = 16; o; o >>= 1) ss += __shfl_down_sync(0xffffffffu, ss, o);
    if ((threadIdx.x & 31) == 0) red[threadIdx.x >> 5] = ss;
    __syncthreads();
    if (threadIdx.x < 32) {
        float v = (threadIdx.x < (blockDim.x >> 5)) ? red[threadIdx.x] : 0.f;
#pragma unroll
        for (int o = 16; o; o >>= 1) v += __shfl_down_sync(0xffffffffu, v, o);
        if (threadIdx.x == 0) red[0] = rsqrtf(v / (float)W + 1e-6f);
    }
    __syncthreads();
    float r = red[0];
    for (int i = threadIdx.x; i < W; i += blockDim.x)
        out[(size_t)row * W + i] = x[i] * r * w[i];
}

// ---------------- RoPE ----------------
__global__ void rope_k(float* __restrict__ x, int nheads, int d, int total_pairs)
{
    int idx = blockIdx.x * blockDim.x + threadIdx.x;
    if (idx >= total_pairs) return;
    int pairs_per_row = nheads * (d / 2);
    int row = idx / pairs_per_row;
    int p   = idx % pairs_per_row;
    int h = p / (d / 2);
    int i = p % (d / 2);
    int pos = row % SS;
    float inv = powf(10000.f, (-2.0f * (float)i) / (float)d);
    float ang = (float)pos * inv;
    float s, c;
    sincosf(ang, &s, &c);
    float* base = x + (size_t)row * nheads * d + h * d + 2 * i;
    float x1 = base[0], x2 = base[1];
    base[0] = x1 * c - x2 * s;
    base[1] = x1 * s + x2 * c;
}

// ============================================================
// attention operand packing
// ============================================================
// Q pack: [bh][s][ Qh(192) | Ql(192) | Qh(192) ], scale folded in
__global__ void pack_q(const float* __restrict__ qn, const float* __restrict__ qp,
                       __nv_bfloat16* __restrict__ out)
{
    long long idx = (long long)blockIdx.x * blockDim.x + threadIdx.x;
    if (idx >= (long long)BB*NH*SS*192) return;
    int d  = (int)(idx % 192);
    int s  = (int)((idx / 192) % SS);
    int bh = (int)(idx / (192LL*SS));
    int b = bh / NH, h = bh % NH;
    size_t m = (size_t)b * SS + s;
    const float scale = 1.0f / sqrtf(192.f);
    float v = ((d < 128) ? qn[m * (NH*DN) + h*DN + d]
                         : qp[m * (NH*DR) + h*DR + (d-128)]) * scale;
    __nv_bfloat16 hi = __float2bfloat16(v);
    __nv_bfloat16 lo = __float2bfloat16(v - __bfloat162float(hi));
    size_t base = ((size_t)bh * SS + s) * 576;
    out[base + d] = hi; out[base + 192 + d] = lo; out[base + 384 + d] = hi;
}

// K pack: [bh][s][ Kh | Kh | Kl ]
__global__ void pack_k(const float* __restrict__ kv, const float* __restrict__ kr,
                       __nv_bfloat16* __restrict__ out)
{
    long long idx = (long long)blockIdx.x * blockDim.x + threadIdx.x;
    if (idx >= (long long)BB*NH*SS*192) return;
    int d  = (int)(idx % 192);
    int s  = (int)((idx / 192) % SS);
    int bh = (int)(idx / (192LL*SS));
    int b = bh / NH, h = bh % NH;
    size_t m = (size_t)b * SS + s;
    float v = (d < 128) ? kv[m * (NH*256) + h*256 + d]
                        : kr[m * DR + (d-128)];
    __nv_bfloat16 hi = __float2bfloat16(v);
    __nv_bfloat16 lo = __float2bfloat16(v - __bfloat162float(hi));
    size_t base = ((size_t)bh * SS + s) * 576;
    out[base + d] = hi; out[base + 192 + d] = hi; out[base + 384 + d] = lo;
}

// V pack (transpose): vt[bh][d][tile*192 + [Vh 64 | Vh 64 | Vl 64]]
__global__ __launch_bounds__(256) void pack_v(const float* __restrict__ kv,
                                              __nv_bfloat16* __restrict__ vt)
{
    __shared__ float vs[64][129];
    const int t = blockIdx.x, h = blockIdx.y, b = blockIdx.z;
    const int bh = b*NH + h;
    const int tid = threadIdx.x;
    for (int i = tid; i < 64*128; i += 256) {
        int r = i >> 7, d = i & 127;
        size_t m = (size_t)b * SS + t*64 + r;
        vs[r][d] = kv[m * (NH*256) + h*256 + 128 + d];
    }
    __syncthreads();
    uint32_t* out32 = (uint32_t*)vt;
    for (int i = tid; i < 128*96; i += 256) {
        int d = i / 96, w = i % 96;
        int seg = w >> 5, kk = (w & 31) * 2;
        float v0 = vs[kk][d], v1 = vs[kk+1][d];
        __nv_bfloat16 h0 = __float2bfloat16(v0), h1 = __float2bfloat16(v1);
        __nv_bfloat16 p0, p1;
        if (seg < 2) { p0 = h0; p1 = h1; }
        else {
            p0 = __float2bfloat16(v0 - __bfloat162float(h0));
            p1 = __float2bfloat16(v1 - __bfloat162float(h1));
        }
        uint32_t packed = (uint32_t)(*(uint16_t*)&p0) | ((uint32_t)(*(uint16_t*)&p1) << 16);
        size_t off = ((size_t)bh * 128 + d) * (3*SS) + (size_t)t*192 + seg*64 + kk;
        out32[off >> 1] = packed;
    }
}

// ============================================================
// HMMA flash attention
// 64 queries per block, 8 warps (4m x 2n), bf16 split-3 S and PV.
// Writes output directly in split layout into g_ats.
// ============================================================
#define ATT_SMEM 108544
// smem map: [0,32768)   QK stages (stage s: Q s*16384, K s*16384+8192)
//           [32768,81920) V chunks c*16384
//           [81920,107520) P tile 64 rows x 400B
//           [107520,108032) redmax[2][64], [108032,108544) redsum[2][64]

__global__ __launch_bounds__(256, 2) void attn_mma(
    const __nv_bfloat16* __restrict__ Qsp, const __nv_bfloat16* __restrict__ Ksp,
    const __nv_bfloat16* __restrict__ Vt, __nv_bfloat16* __restrict__ ats)
{
    extern __shared__ __align__(16) char smem[];
    const uint32_t sb = smem_u32(smem);
    const int qt = blockIdx.x, h = blockIdx.y, b = blockIdx.z;
    const int bh = b*NH + h;
    const int q0 = qt * 64;
    const int tid = threadIdx.x, lane = tid & 31;
    const int wm = (tid >> 5) & 3, wn = tid >> 7;

    const __nv_bfloat16* Qg = Qsp + ((size_t)bh * SS + q0) * 576;
    const __nv_bfloat16* Kg = Ksp + (size_t)bh * SS * 576;
    const __nv_bfloat16* Vg = Vt  + (size_t)bh * 128 * (3*SS);

    float* redmax = (float*)(smem + 107520);
    float* redsum = (float*)(smem + 108032);

    float acc_o[8][4];
#pragma unroll
    for (int i = 0; i < 8; i++)
#pragma unroll
        for (int j = 0; j < 4; j++) acc_o[i][j] = 0.f;
    float m0 = -1e30f, m1 = -1e30f, l0 = 0.f, l1 = 0.f;

    const int a_row  = lane & 15;
    const int a_ch   = lane >> 4;
    const int b_nrow = (lane & 7) + ((lane & 16) ? 8 : 0);
    const int b_ch   = (lane >> 3) & 1;
    const int r0 = wm*16 + (lane >> 2);     // local row (second = +8)

    for (int t = 0; t <= qt; t++) {
        const int k0 = t * 64;
        // prefetch: S chunk 0, 1, then all V (3 groups of commits: S0, S1, V)
#pragma unroll
        for (int slot = 0; slot < 2; slot++) {
#pragma unroll
            for (int it = 0; it < 2; it++) {
                int i = tid + it*256; int r = i >> 3, ch = i & 7;
                CPA16(sb + slot*16384u + sw128(r, ch), Qg + (size_t)r*576 + slot*64 + ch*8);
                CPA16(sb + slot*16384u + 8192u + sw128(r, ch), Kg + (size_t)(k0 + r)*576 + slot*64 + ch*8);
            }
            CPCOMMIT();
        }
#pragma unroll
        for (int it = 0; it < 12; it++) {
            int i = tid + it*256;
            int c = i >> 10, j = i & 1023, d = j >> 3, ch = j & 7;
            CPA16(sb + 32768u + c*16384u + sw128(d, ch),
                  Vg + (size_t)d*(3*SS) + t*192 + c*64 + ch*8);
        }
        CPCOMMIT();

        float acc_s[4][4];
#pragma unroll
        for (int i = 0; i < 4; i++)
#pragma unroll
            for (int j = 0; j < 4; j++) acc_s[i][j] = 0.f;

        // ---- S = Q K^T over 9 chunks of 64 (2-stage) ----
        for (int c = 0; c < 9; c++) {
            if (c < 2) { CPWAIT(2); } else { CPWAIT(1); }
            __syncthreads();
            uint32_t qb = sb + (uint32_t)(c & 1) * 16384u;
            uint32_t kb = qb + 8192u;
#pragma unroll
            for (int ks = 0; ks < 4; ks++) {
                uint32_t a[4];
                ldsm4(a, qb + sw128(wm*16 + a_row, ks*2 + a_ch));
#pragma unroll
                for (int g = 0; g < 2; g++) {
                    uint32_t bb[4];
                    ldsm4(bb, kb + sw128(wn*32 + g*16 + b_nrow, ks*2 + b_ch));
                    mma16816(acc_s[g*2],   a, bb[0], bb[1]);
                    mma16816(acc_s[g*2+1], a, bb[2], bb[3]);
                }
            }
            __syncthreads();
            if (c + 2 < 9) {
#pragma unroll
                for (int it = 0; it < 2; it++) {
                    int i = tid + it*256; int r = i >> 3, ch = i & 7;
                    CPA16(sb + (uint32_t)(c & 1)*16384u + sw128(r, ch),
                          Qg + (size_t)r*576 + (c+2)*64 + ch*8);
                    CPA16(sb + (uint32_t)(c & 1)*16384u + 8192u + sw128(r, ch),
                          Kg + (size_t)(k0 + r)*576 + (c+2)*64 + ch*8);
                }
            }
            CPCOMMIT();
        }

        // ---- causal mask (diagonal tile only) ----
        if (t == qt) {
#pragma unroll
            for (int nt = 0; nt < 4; nt++) {
                int colb = wn*32 + nt*8 + (lane & 3)*2;
                if (colb     > r0)     acc_s[nt][0] = -1e30f;
                if (colb + 1 > r0)     acc_s[nt][1] = -1e30f;
                if (colb     > r0 + 8) acc_s[nt][2] = -1e30f;
                if (colb + 1 > r0 + 8) acc_s[nt][3] = -1e30f;
            }
        }

        // ---- online softmax ----
        float mx0 = -1e30f, mx1 = -1e30f;
#pragma unroll
        for (int nt = 0; nt < 4; nt++) {
            mx0 = fmaxf(mx0, fmaxf(acc_s[nt][0], acc_s[nt][1]));
            mx1 = fmaxf(mx1, fmaxf(acc_s[nt][2], acc_s[nt][3]));
        }
        mx0 = fmaxf(mx0, __shfl_xor_sync(0xffffffffu, mx0, 1));
        mx0 = fmaxf(mx0, __shfl_xor_sync(0xffffffffu, mx0, 2));
        mx1 = fmaxf(mx1, __shfl_xor_sync(0xffffffffu, mx1, 1));
        mx1 = fmaxf(mx1, __shfl_xor_sync(0xffffffffu, mx1, 2));
        if ((lane & 3) == 0) {
            redmax[wn*64 + r0]     = mx0;
            redmax[wn*64 + r0 + 8] = mx1;
        }
        __syncthreads();
        float tm0 = fmaxf(mx0, redmax[(wn^1)*64 + r0]);
        float tm1 = fmaxf(mx1, redmax[(wn^1)*64 + r0 + 8]);
        float nm0 = fmaxf(m0, tm0), nm1 = fmaxf(m1, tm1);
        float f0 = __expf(m0 - nm0), f1 = __expf(m1 - nm1);

        float s0 = 0.f, s1 = 0.f;
#pragma unroll
        for (int nt = 0; nt < 4; nt++) {
            acc_s[nt][0] = __expf(acc_s[nt][0] - nm0);
            acc_s[nt][1] = __expf(acc_s[nt][1] - nm0);
            acc_s[nt][2] = __expf(acc_s[nt][2] - nm1);
            acc_s[nt][3] = __expf(acc_s[nt][3] - nm1);
            s0 += acc_s[nt][0] + acc_s[nt][1];
            s1 += acc_s[nt][2] + acc_s[nt][3];
        }
        s0 += __shfl_xor_sync(0xffffffffu, s0, 1);
        s0 += __shfl_xor_sync(0xffffffffu, s0, 2);
        s1 += __shfl_xor_sync(0xffffffffu, s1, 1);
        s1 += __shfl_xor_sync(0xffffffffu, s1, 2);
        if ((lane & 3) == 0) {
            redsum[wn*64 + r0]     = s0;
            redsum[wn*64 + r0 + 8] = s1;
        }
        // write P (split) to smem: [Ph | Pl | Ph], 400B pitch
        {
            char* P = smem + 81920;
            int colb = wn*32 + (lane & 3)*2;
#pragma unroll
            for (int nt = 0; nt < 4; nt++) {
                int col = colb + nt*8;
#pragma unroll
                for (int half = 0; half < 2; half++) {
                    float pa = acc_s[nt][half*2], pb = acc_s[nt][half*2+1];
                    int row = r0 + half*8;
                    __nv_bfloat16 ha = __float2bfloat16(pa), hb = __float2bfloat16(pb);
                    __nv_bfloat16 la = __float2bfloat16(pa - __bfloat162float(ha));
                    __nv_bfloat16 lb = __float2bfloat16(pb - __bfloat162float(hb));
                    uint32_t hi = (uint32_t)(*(uint16_t*)&ha) | ((uint32_t)(*(uint16_t*)&hb) << 16);
                    uint32_t lo = (uint32_t)(*(uint16_t*)&la) | ((uint32_t)(*(uint16_t*)&lb) << 16);
                    uint32_t* base = (uint32_t*)(P + row*400 + col*2);
                    base[0]  = hi;            // Ph
                    base[32] = lo;            // Pl  (+128 B)
                    base[64] = hi;            // Ph  (+256 B)
                }
            }
        }
        __syncthreads();
        float ts0 = s0 + redsum[(wn^1)*64 + r0];
        float ts1 = s1 + redsum[(wn^1)*64 + r0 + 8];
        l0 = l0 * f0 + ts0;
        l1 = l1 * f1 + ts1;
        m0 = nm0; m1 = nm1;
#pragma unroll
        for (int nt = 0; nt < 8; nt++) {
            acc_o[nt][0] *= f0; acc_o[nt][1] *= f0;
            acc_o[nt][2] *= f1; acc_o[nt][3] *= f1;
        }

        // ---- PV over 3 chunks of 64 (V resident in smem) ----
#pragma unroll
        for (int c = 0; c < 3; c++) {
            uint32_t vb = sb + 32768u + (uint32_t)c * 16384u;
#pragma unroll
            for (int ks = 0; ks < 4; ks++) {
                uint32_t a[4];
                ldsm4(a, sb + 81920u + (uint32_t)((wm*16 + a_row)*400 + c*128 + ks*32 + a_ch*16));
#pragma unroll
                for (int g = 0; g < 4; g++) {
                    uint32_t bb[4];
                    ldsm4(bb, vb + sw128(wn*64 + g*16 + b_nrow, ks*2 + b_ch));
                    mma16816(acc_o[g*2],   a, bb[0], bb[1]);
                    mma16816(acc_o[g*2+1], a, bb[2], bb[3]);
                }
            }
        }
        __syncthreads();
    }

    // ---- epilogue: write split-bf16 output directly into ats ----
    float il0 = 1.f / l0, il1 = 1.f / l1;
    size_t mrow0 = (size_t)b * SS + q0 + r0;
#pragma unroll
    for (int nt = 0; nt < 8; nt++) {
        int col = h*128 + wn*64 + nt*8 + (lane & 3)*2;
#pragma unroll
        for (int half = 0; half < 2; half++) {
            float oa = acc_o[nt][half*2]   * (half ? il1 : il0);
            float ob = acc_o[nt][half*2+1] * (half ? il1 : il0);
            size_t row = mrow0 + half*8;
            __nv_bfloat16 ha = __float2bfloat16(oa), hb = __float2bfloat16(ob);
            __nv_bfloat16 la = __float2bfloat16(oa - __bfloat162float(ha));
            __nv_bfloat16 lb = __float2bfloat16(ob - __bfloat162float(hb));
            uint32_t hi = (uint32_t)(*(uint16_t*)&ha) | ((uint32_t)(*(uint16_t*)&hb) << 16);
            uint32_t lo = (uint32_t)(*(uint16_t*)&la) | ((uint32_t)(*(uint16_t*)&lb) << 16);
            uint32_t* o32 = (uint32_t*)(ats + row * 6144);
            o32[(col) >> 1]        = hi;
            o32[(2048 + col) >> 1] = lo;
            o32[(4096 + col) >> 1] = hi;
        }
    }
}

// ---------------- host orchestration ----------------
static void conv3(const float* in, __nv_bfloat16* out, int R, int Rpad, int C, int mode)
{
    long long tot = (long long)Rpad * C;
    int blocks = (int)((tot + 255) / 256);
    split3_k<<<blocks, 256>>>(in, out, R, Rpad, C, mode);
}

static void gemm3(const __nv_bfloat16* A, const __nv_bfloat16* B, float* C, int M, int N, int Kp)
{
    cudaFuncSetAttribute(gemm_tc, cudaFuncAttributeMaxDynamicSharedMemorySize, GEMM_SMEM);
    dim3 grid((N + 127) / 128, M / 128);
    gemm_tc<<<grid, 256, GEMM_SMEM>>>(A, B, C, M, N, Kp);
}

extern "C" void kernel_launch(void* const* d_in, const int* in_sizes, int n_in,
                              void* d_out, int out_size)
{
    const float* x        = (const float*)d_in[0];
    const float* wq_down  = (const float*)d_in[1];
    const float* q_norm_w = (const float*)d_in[2];
    const float* wq_up    = (const float*)d_in[3];
    const float* wq_rope  = (const float*)d_in[4];
    const float* wkv_down = (const float*)d_in[5];
    const float* kv_norm_w= (const float*)d_in[6];
    const float* wkv_up   = (const float*)d_in[7];
    const float* wk_rope  = (const float*)d_in[8];
    const float* wo       = (const float*)d_in[9];
    float* out = (float*)d_out;

    float *qc, *kvc, *qn, *qp, *kvu, *kr;
    cudaGetSymbolAddress((void**)&qc,  g_qc);
    cudaGetSymbolAddress((void**)&kvc, g_kvc);
    cudaGetSymbolAddress((void**)&qn,  g_qnope);
    cudaGetSymbolAddress((void**)&qp,  g_qpe);
    cudaGetSymbolAddress((void**)&kvu, g_kvup);
    cudaGetSymbolAddress((void**)&kr,  g_krope);

    __nv_bfloat16 *xs, *wqd, *wkvd, *wkr, *qcs, *wqu, *wqr, *kvcs, *wkvu, *ats, *wos;
    __nv_bfloat16 *qsp, *ksp, *vt;
    cudaGetSymbolAddress((void**)&xs,   g_xs);
    cudaGetSymbolAddress((void**)&wqd,  g_wqd);
    cudaGetSymbolAddress((void**)&wkvd, g_wkvd);
    cudaGetSymbolAddress((void**)&wkr,  g_wkr);
    cudaGetSymbolAddress((void**)&qcs,  g_qcs);
    cudaGetSymbolAddress((void**)&wqu,  g_wqu);
    cudaGetSymbolAddress((void**)&wqr,  g_wqr);
    cudaGetSymbolAddress((void**)&kvcs, g_kvcs);
    cudaGetSymbolAddress((void**)&wkvu, g_wkvu);
    cudaGetSymbolAddress((void**)&ats,  g_ats);
    cudaGetSymbolAddress((void**)&wos,  g_wos);
    cudaGetSymbolAddress((void**)&qsp,  g_qsp);
    cudaGetSymbolAddress((void**)&ksp,  g_ksp);
    cudaGetSymbolAddress((void**)&vt,   g_vt);

    // stage 1: down projections
    conv3(x,        xs,   MT,   MT,  DIMM, 0);
    conv3(wq_down,  wqd,  QR,   QR,  DIMM, 1);
    conv3(wkv_down, wkvd, KVR,  KVR, DIMM, 1);
    gemm3(xs, wqd,  qc,  MT, QR,  3*DIMM);
    conv3(wk_rope,  wkr,  DR,   128, DIMM, 1);
    gemm3(xs, wkvd, kvc, MT, KVR, 3*DIMM);
    gemm3(xs, wkr,  kr,  MT, DR,  3*DIMM);

    rmsnorm_k<<<MT, 256>>>(qc,  q_norm_w,  qc,  QR);
    rmsnorm_k<<<MT, 256>>>(kvc, kv_norm_w, kvc, KVR);

    // stage 2: up projections
    conv3(qc,      qcs,  MT,           MT,           QR,  0);
    conv3(wq_up,   wqu,  NH*DN,        NH*DN,        QR,  1);
    conv3(wq_rope, wqr,  NH*DR,        NH*DR,        QR,  1);
    conv3(kvc,     kvcs, MT,           MT,           KVR, 0);
    conv3(wkv_up,  wkvu, NH*(DN+DVV),  NH*(DN+DVV),  KVR, 1);

    gemm3(qcs,  wqu,  qn,  MT, NH*DN,       3*QR);
    gemm3(qcs,  wqr,  qp,  MT, NH*DR,       3*QR);
    gemm3(kvcs, wkvu, kvu, MT, NH*(DN+DVV), 3*KVR);

    // rope
    {
        int tot = MT * NH * (DR / 2);
        rope_k<<<(tot + 255) / 256, 256>>>(qp, NH, DR, tot);
    }
    {
        int tot = MT * 1 * (DR / 2);
        rope_k<<<(tot + 255) / 256, 256>>>(kr, 1, DR, tot);
    }

    // attention operand packing
    {
        long long tot = (long long)BB*NH*SS*192;
        int blocks = (int)((tot + 255) / 256);
        pack_q<<<blocks, 256>>>(qn, qp, qsp);
        pack_k<<<blocks, 256>>>(kvu, kr, ksp);
    }
    pack_v<<<dim3(SS/64, NH, BB), 256>>>(kvu, vt);

    // HMMA flash attention -> split output in ats
    cudaFuncSetAttribute(attn_mma, cudaFuncAttributeMaxDynamicSharedMemorySize, ATT_SMEM);
    attn_mma<<<dim3(SS/64, NH, BB), 256, ATT_SMEM>>>(qsp, ksp, vt, ats);

    // output projection
    conv3(wo, wos, DIMM, DIMM, NH*DVV, 1);
    gemm3(ats, wos, out, MT, DIMM, 3*(NH*DVV));
}

// round 6
// speedup vs baseline: 6.5320x; 1.1054x over previous
#include <cuda_runtime.h>
#include <cuda_bf16.h>
#include <math.h>
#include <stdint.h>

#define BB 2
#define SS 2048
#define DIMM 2048
#define NH 16
#define QR 1536
#define KVR 512
#define DN 128
#define DR 64
#define DVV 128
#define MT (BB*SS)   // 4096 token rows

#define NDOWN 2112   // qc(1536) | kvc(512) | kr(64)
#define NDOWNP 2176  // padded rows for B
#define NUP 3072     // qn(2048) | qp(1024)

// ---------------- fp32 scratch ----------------
__device__ float g_dall[MT*NDOWN];       // down-proj output (pitch 2112)
__device__ float g_qnp [MT*NUP];         // up-proj output   (pitch 3072)
__device__ float g_kvup[MT*NH*(DN+DVV)];

// ---------------- bf16 split scratch (K' = 3K) ----------------
__device__ __nv_bfloat16 g_xs   [MT    * 3*DIMM];
__device__ __nv_bfloat16 g_wdall[NDOWNP* 3*DIMM];
__device__ __nv_bfloat16 g_qcs  [MT    * 3*QR];
__device__ __nv_bfloat16 g_wuall[NUP   * 3*QR];
__device__ __nv_bfloat16 g_kvcs [MT    * 3*KVR];
__device__ __nv_bfloat16 g_wkvu [(NH*(DN+DVV)) * 3*KVR];
__device__ __nv_bfloat16 g_ats  [MT    * 3*(NH*DVV)];
__device__ __nv_bfloat16 g_wos  [DIMM  * 3*(NH*DVV)];

// ---------------- attention packed operands ----------------
__device__ __nv_bfloat16 g_qsp[BB*NH*SS*576];      // [bh][s][Qh|Ql|Qh]
__device__ __nv_bfloat16 g_ksp[BB*NH*SS*576];      // [bh][s][Kh|Kh|Kl]
__device__ __nv_bfloat16 g_vt [BB*NH*128*2*SS];    // [bh][d][tile*128 + [Vh|Vl]]

// ============================================================
// helpers
// ============================================================
__device__ __forceinline__ uint32_t smem_u32(const void* p){
    uint32_t a;
    asm("{ .reg .u64 t; cvta.to.shared.u64 t, %1; cvt.u32.u64 %0, t; }" : "=r"(a) : "l"(p));
    return a;
}
#define CPA16(dst, src) asm volatile("cp.async.cg.shared.global [%0], [%1], 16;" :: "r"(dst), "l"(src))
#define CPCOMMIT()      asm volatile("cp.async.commit_group;")
#define CPWAIT(n)       asm volatile("cp.async.wait_group %0;" :: "n"(n))

__device__ __forceinline__ void ldsm4(uint32_t* r, uint32_t addr){
    asm volatile("ldmatrix.sync.aligned.m8n8.x4.shared.b16 {%0,%1,%2,%3}, [%4];"
        : "=r"(r[0]), "=r"(r[1]), "=r"(r[2]), "=r"(r[3]) : "r"(addr));
}
__device__ __forceinline__ void mma16816(float* c, const uint32_t* a, uint32_t b0, uint32_t b1){
    asm volatile("mma.sync.aligned.m16n8k16.row.col.f32.bf16.bf16.f32 "
        "{%0,%1,%2,%3}, {%4,%5,%6,%7}, {%8,%9}, {%0,%1,%2,%3};"
        : "+f"(c[0]), "+f"(c[1]), "+f"(c[2]), "+f"(c[3])
        : "r"(a[0]), "r"(a[1]), "r"(a[2]), "r"(a[3]), "r"(b0), "r"(b1));
}
__device__ __forceinline__ uint32_t sw128(int row, int chunk){
    return (uint32_t)(row * 128 + ((chunk ^ (row & 7)) * 16));
}

// ============================================================
// split-3 conversion with input pitch
// mode 0 (A): [hi | lo | hi]    mode 1 (B): [hi | hi | lo]
// ============================================================
__global__ void split3_k(const float* __restrict__ in, __nv_bfloat16* __restrict__ out,
                         int R, int Rpad, int C, int inPitch, int mode)
{
    long long i = (long long)blockIdx.x * blockDim.x + threadIdx.x;
    long long tot = (long long)Rpad * C;
    if (i >= tot) return;
    int r = (int)(i / C), c = (int)(i % C);
    float x = (r < R) ? in[(size_t)r * inPitch + c] : 0.f;
    __nv_bfloat16 h = __float2bfloat16(x);
    __nv_bfloat16 l = __float2bfloat16(x - __bfloat162float(h));
    size_t base = (size_t)r * 3 * C;
    if (mode == 0) { out[base + c] = h; out[base + C + c] = l; out[base + 2*C + c] = h; }
    else           { out[base + c] = h; out[base + C + c] = h; out[base + 2*C + c] = l; }
}

// ============================================================
// dense mma.sync bf16 GEMM (round-4 core, redundant barrier removed)
// ============================================================
#define STAGES 3
#define STAGE_BYTES 32768
#define GEMM_SMEM (STAGES*STAGE_BYTES)

__global__ __launch_bounds__(256, 2) void gemm_tc(
    const __nv_bfloat16* __restrict__ A, const __nv_bfloat16* __restrict__ B,
    float* __restrict__ C, int M, int N, int Kp)
{
    extern __shared__ __align__(16) char smem[];
    const uint32_t sb = smem_u32(smem);
    const int m0 = blockIdx.y * 128, n0 = blockIdx.x * 128;
    const int tid = threadIdx.x, lane = tid & 31;
    const int wm = (tid >> 5) & 3;
    const int wn = tid >> 7;

    float acc[2][8][4];
#pragma unroll
    for (int i = 0; i < 2; i++)
#pragma unroll
        for (int j = 0; j < 8; j++)
#pragma unroll
            for (int q = 0; q < 4; q++) acc[i][j][q] = 0.f;

    const int KT = Kp >> 6;
    const __nv_bfloat16* Ag0 = A + (size_t)m0 * Kp;
    const __nv_bfloat16* Bg0 = B + (size_t)n0 * Kp;

    const int fr = tid >> 3;
    const int fc = tid & 7;

    auto fill = [&](int j){
        uint32_t base = sb + (uint32_t)(j % STAGES) * STAGE_BYTES;
        int k0 = j << 6;
#pragma unroll
        for (int i = 0; i < 4; i++) {
            int r = fr + i * 32;
            CPA16(base + sw128(r, fc), Ag0 + (size_t)r * Kp + k0 + fc*8);
        }
#pragma unroll
        for (int i = 0; i < 4; i++) {
            int r = fr + i * 32;
            CPA16(base + 16384u + sw128(r, fc), Bg0 + (size_t)r * Kp + k0 + fc*8);
        }
        CPCOMMIT();
    };

    fill(0);
    fill(1);

    const int a_row  = lane & 15;
    const int a_ch   = lane >> 4;
    const int b_nrow = (lane & 7) + ((lane & 16) ? 8 : 0);
    const int b_ch   = (lane >> 3) & 1;

    for (int kt = 0; kt < KT; kt++) {
        CPWAIT(1);
        __syncthreads();
        if (kt + 2 < KT) fill(kt + 2);
        else CPCOMMIT();

        uint32_t aT = sb + (uint32_t)(kt % STAGES) * STAGE_BYTES;
        uint32_t bT = aT + 16384u;
#pragma unroll
        for (int ks = 0; ks < 4; ks++) {
            uint32_t a[2][4];
#pragma unroll
            for (int i = 0; i < 2; i++)
                ldsm4(a[i], aT + sw128(wm*32 + i*16 + a_row, ks*2 + a_ch));
            uint32_t b[4][4];
#pragma unroll
            for (int g = 0; g < 4; g++)
                ldsm4(b[g], bT + sw128(wn*64 + g*16 + b_nrow, ks*2 + b_ch));
#pragma unroll
            for (int i = 0; i < 2; i++)
#pragma unroll
                for (int g = 0; g < 4; g++) {
                    mma16816(acc[i][2*g],   a[i], b[g][0], b[g][1]);
                    mma16816(acc[i][2*g+1], a[i], b[g][2], b[g][3]);
                }
        }
        // NOTE: no trailing __syncthreads — with 3 stages the top barrier of the
        // next iteration protects the refill slot (written slot was last read two
        // iterations ago).
    }

    const int rb = m0 + wm*32;
    const int cb = n0 + wn*64;
#pragma unroll
    for (int i = 0; i < 2; i++)
#pragma unroll
        for (int j = 0; j < 8; j++) {
            int c = cb + j*8 + (lane & 3)*2;
            if (c < N) {
                int r = rb + i*16 + (lane >> 2);
                *(float2*)&C[(size_t)r * N + c]     = make_float2(acc[i][j][0], acc[i][j][1]);
                *(float2*)&C[(size_t)(r+8) * N + c] = make_float2(acc[i][j][2], acc[i][j][3]);
            }
        }
}

// ---------------- RMSNorm (pitched, in place) ----------------
__global__ void rmsnorm_k(float* __restrict__ x, const float* __restrict__ w,
                          int W, int pitch)
{
    const int row = blockIdx.x;
    float* xr = x + (size_t)row * pitch;
    float ss = 0.f;
    for (int i = threadIdx.x; i < W; i += blockDim.x) { float v = xr[i]; ss += v * v; }
    __shared__ float red[32];
#pragma unroll
    for (int o = 16; o; o >>= 1) ss += __shfl_down_sync(0xffffffffu, ss, o);
    if ((threadIdx.x & 31) == 0) red[threadIdx.x >> 5] = ss;
    __syncthreads();
    if (threadIdx.x < 32) {
        float v = (threadIdx.x < (blockDim.x >> 5)) ? red[threadIdx.x] : 0.f;
#pragma unroll
        for (int o = 16; o; o >>= 1) v += __shfl_down_sync(0xffffffffu, v, o);
        if (threadIdx.x == 0) red[0] = rsqrtf(v / (float)W + 1e-6f);
    }
    __syncthreads();
    float r = red[0];
    for (int i = threadIdx.x; i < W; i += blockDim.x)
        xr[i] = xr[i] * r * w[i];
}

// ---------------- RoPE (pitched, col offset, in place) ----------------
__global__ void rope_k(float* __restrict__ x, int pitch, int colOff,
                       int nheads, int d, int total_pairs)
{
    int idx = blockIdx.x * blockDim.x + threadIdx.x;
    if (idx >= total_pairs) return;
    int pairs_per_row = nheads * (d / 2);
    int row = idx / pairs_per_row;
    int p   = idx % pairs_per_row;
    int h = p / (d / 2);
    int i = p % (d / 2);
    int pos = row % SS;
    float inv = powf(10000.f, (-2.0f * (float)i) / (float)d);
    float ang = (float)pos * inv;
    float s, c;
    sincosf(ang, &s, &c);
    float* base = x + (size_t)row * pitch + colOff + h * d + 2 * i;
    float x1 = base[0], x2 = base[1];
    base[0] = x1 * c - x2 * s;
    base[1] = x1 * s + x2 * c;
}

// ============================================================
// attention operand packing
// ============================================================
__global__ void pack_q(const float* __restrict__ qnp, __nv_bfloat16* __restrict__ out)
{
    long long idx = (long long)blockIdx.x * blockDim.x + threadIdx.x;
    if (idx >= (long long)BB*NH*SS*192) return;
    int d  = (int)(idx % 192);
    int s  = (int)((idx / 192) % SS);
    int bh = (int)(idx / (192LL*SS));
    int b = bh / NH, h = bh % NH;
    size_t m = (size_t)b * SS + s;
    const float scale = 1.0f / sqrtf(192.f);
    float v = ((d < 128) ? qnp[m * NUP + h*128 + d]
                         : qnp[m * NUP + 2048 + h*64 + (d-128)]) * scale;
    __nv_bfloat16 hi = __float2bfloat16(v);
    __nv_bfloat16 lo = __float2bfloat16(v - __bfloat162float(hi));
    size_t base = ((size_t)bh * SS + s) * 576;
    out[base + d] = hi; out[base + 192 + d] = lo; out[base + 384 + d] = hi;
}

__global__ void pack_k(const float* __restrict__ kv, const float* __restrict__ dall,
                       __nv_bfloat16* __restrict__ out)
{
    long long idx = (long long)blockIdx.x * blockDim.x + threadIdx.x;
    if (idx >= (long long)BB*NH*SS*192) return;
    int d  = (int)(idx % 192);
    int s  = (int)((idx / 192) % SS);
    int bh = (int)(idx / (192LL*SS));
    int b = bh / NH, h = bh % NH;
    size_t m = (size_t)b * SS + s;
    float v = (d < 128) ? kv[m * (NH*256) + h*256 + d]
                        : dall[m * NDOWN + 2048 + (d-128)];
    __nv_bfloat16 hi = __float2bfloat16(v);
    __nv_bfloat16 lo = __float2bfloat16(v - __bfloat162float(hi));
    size_t base = ((size_t)bh * SS + s) * 576;
    out[base + d] = hi; out[base + 192 + d] = hi; out[base + 384 + d] = lo;
}

// V pack (transpose): vt[bh][d][tile*128 + [Vh 64 | Vl 64]]
__global__ __launch_bounds__(256) void pack_v(const float* __restrict__ kv,
                                              __nv_bfloat16* __restrict__ vt)
{
    __shared__ float vs[64][129];
    const int t = blockIdx.x, h = blockIdx.y, b = blockIdx.z;
    const int bh = b*NH + h;
    const int tid = threadIdx.x;
    for (int i = tid; i < 64*128; i += 256) {
        int r = i >> 7, d = i & 127;
        size_t m = (size_t)b * SS + t*64 + r;
        vs[r][d] = kv[m * (NH*256) + h*256 + 128 + d];
    }
    __syncthreads();
    uint32_t* out32 = (uint32_t*)vt;
    for (int i = tid; i < 128*64; i += 256) {
        int d = i / 64, w = i % 64;
        int seg = w >> 5, kk = (w & 31) * 2;
        float v0 = vs[kk][d], v1 = vs[kk+1][d];
        __nv_bfloat16 h0 = __float2bfloat16(v0), h1 = __float2bfloat16(v1);
        __nv_bfloat16 p0, p1;
        if (seg == 0) { p0 = h0; p1 = h1; }
        else {
            p0 = __float2bfloat16(v0 - __bfloat162float(h0));
            p1 = __float2bfloat16(v1 - __bfloat162float(h1));
        }
        uint32_t packed = (uint32_t)(*(uint16_t*)&p0) | ((uint32_t)(*(uint16_t*)&p1) << 16);
        size_t off = ((size_t)bh * 128 + d) * (2*SS) + (size_t)t*128 + seg*64 + kk;
        out32[off >> 1] = packed;
    }
}

// ============================================================
// HMMA flash attention — 3-slot single-sync S pipeline, dedup P/V
// smem: [0,49152)  QK slots (Q s*16384, K s*16384+8192)
//       [49152,81920) V segs (Vh, Vl: 16KB each)
//       [81920,99328) P: 64 rows x 272B  [Ph(128B) | Pl(128B) | pad]
//       [99328,99840) redmax  [99840,100352) redsum
// ============================================================
#define VBASE 49152u
#define PBASE 81920u
#define ATT_SMEM 100352

__global__ __launch_bounds__(256, 2) void attn_mma(
    const __nv_bfloat16* __restrict__ Qsp, const __nv_bfloat16* __restrict__ Ksp,
    const __nv_bfloat16* __restrict__ Vt, __nv_bfloat16* __restrict__ ats)
{
    extern __shared__ __align__(16) char smem[];
    const uint32_t sb = smem_u32(smem);
    const int qt = blockIdx.x, h = blockIdx.y, b = blockIdx.z;
    const int bh = b*NH + h;
    const int q0 = qt * 64;
    const int tid = threadIdx.x, lane = tid & 31;
    const int wm = (tid >> 5) & 3, wn = tid >> 7;

    const __nv_bfloat16* Qg = Qsp + ((size_t)bh * SS + q0) * 576;
    const __nv_bfloat16* Kg = Ksp + (size_t)bh * SS * 576;
    const __nv_bfloat16* Vg = Vt  + (size_t)bh * 128 * (2*SS);

    float* redmax = (float*)(smem + 99328);
    float* redsum = (float*)(smem + 99840);

    float acc_o[8][4];
#pragma unroll
    for (int i = 0; i < 8; i++)
#pragma unroll
        for (int j = 0; j < 4; j++) acc_o[i][j] = 0.f;
    float m0 = -1e30f, m1 = -1e30f, l0 = 0.f, l1 = 0.f;

    const int a_row  = lane & 15;
    const int a_ch   = lane >> 4;
    const int b_nrow = (lane & 7) + ((lane & 16) ? 8 : 0);
    const int b_ch   = (lane >> 3) & 1;
    const int r0 = wm*16 + (lane >> 2);

    for (int t = 0; t <= qt; t++) {
        const int k0 = t * 64;
        // prologue: S chunks 0,1 (slots 0,1), then V (Vh+Vl, one group)
#pragma unroll
        for (int slot = 0; slot < 2; slot++) {
#pragma unroll
            for (int it = 0; it < 2; it++) {
                int i = tid + it*256; int r = i >> 3, ch = i & 7;
                CPA16(sb + slot*16384u + sw128(r, ch), Qg + (size_t)r*576 + slot*64 + ch*8);
                CPA16(sb + slot*16384u + 8192u + sw128(r, ch), Kg + (size_t)(k0 + r)*576 + slot*64 + ch*8);
            }
            CPCOMMIT();
        }
#pragma unroll
        for (int it = 0; it < 8; it++) {
            int i = tid + it*256;
            int c = i >> 10, j = i & 1023, d = j >> 3, ch = j & 7;
            CPA16(sb + VBASE + c*16384u + sw128(d, ch),
                  Vg + (size_t)d*(2*SS) + t*128 + c*64 + ch*8);
        }
        CPCOMMIT();

        float acc_s[4][4];
#pragma unroll
        for (int i = 0; i < 4; i++)
#pragma unroll
            for (int j = 0; j < 4; j++) acc_s[i][j] = 0.f;

        // ---- S = Q K^T, 9 chunks, 3 slots, ONE barrier per chunk ----
        for (int c = 0; c < 9; c++) {
            if (c < 2)       { CPWAIT(2); }
            else if (c == 8) { CPWAIT(0); }
            else             { CPWAIT(1); }
            __syncthreads();
            if (c + 2 < 9) {
                int slot = (c + 2) % 3;
#pragma unroll
                for (int it = 0; it < 2; it++) {
                    int i = tid + it*256; int r = i >> 3, ch = i & 7;
                    CPA16(sb + (uint32_t)slot*16384u + sw128(r, ch),
                          Qg + (size_t)r*576 + (c+2)*64 + ch*8);
                    CPA16(sb + (uint32_t)slot*16384u + 8192u + sw128(r, ch),
                          Kg + (size_t)(k0 + r)*576 + (c+2)*64 + ch*8);
                }
                CPCOMMIT();
            }
            uint32_t qb = sb + (uint32_t)(c % 3) * 16384u;
            uint32_t kb = qb + 8192u;
#pragma unroll
            for (int ks = 0; ks < 4; ks++) {
                uint32_t a[4];
                ldsm4(a, qb + sw128(wm*16 + a_row, ks*2 + a_ch));
#pragma unroll
                for (int g = 0; g < 2; g++) {
                    uint32_t bb[4];
                    ldsm4(bb, kb + sw128(wn*32 + g*16 + b_nrow, ks*2 + b_ch));
                    mma16816(acc_s[g*2],   a, bb[0], bb[1]);
                    mma16816(acc_s[g*2+1], a, bb[2], bb[3]);
                }
            }
        }

        // ---- causal mask (diagonal tile only) ----
        if (t == qt) {
#pragma unroll
            for (int nt = 0; nt < 4; nt++) {
                int colb = wn*32 + nt*8 + (lane & 3)*2;
                if (colb     > r0)     acc_s[nt][0] = -1e30f;
                if (colb + 1 > r0)     acc_s[nt][1] = -1e30f;
                if (colb     > r0 + 8) acc_s[nt][2] = -1e30f;
                if (colb + 1 > r0 + 8) acc_s[nt][3] = -1e30f;
            }
        }

        // ---- online softmax ----
        float mx0 = -1e30f, mx1 = -1e30f;
#pragma unroll
        for (int nt = 0; nt < 4; nt++) {
            mx0 = fmaxf(mx0, fmaxf(acc_s[nt][0], acc_s[nt][1]));
            mx1 = fmaxf(mx1, fmaxf(acc_s[nt][2], acc_s[nt][3]));
        }
        mx0 = fmaxf(mx0, __shfl_xor_sync(0xffffffffu, mx0, 1));
        mx0 = fmaxf(mx0, __shfl_xor_sync(0xffffffffu, mx0, 2));
        mx1 = fmaxf(mx1, __shfl_xor_sync(0xffffffffu, mx1, 1));
        mx1 = fmaxf(mx1, __shfl_xor_sync(0xffffffffu, mx1, 2));
        if ((lane & 3) == 0) {
            redmax[wn*64 + r0]     = mx0;
            redmax[wn*64 + r0 + 8] = mx1;
        }
        __syncthreads();
        float tm0 = fmaxf(mx0, redmax[(wn^1)*64 + r0]);
        float tm1 = fmaxf(mx1, redmax[(wn^1)*64 + r0 + 8]);
        float nm0 = fmaxf(m0, tm0), nm1 = fmaxf(m1, tm1);
        float f0 = __expf(m0 - nm0), f1 = __expf(m1 - nm1);

        float s0 = 0.f, s1 = 0.f;
#pragma unroll
        for (int nt = 0; nt < 4; nt++) {
            acc_s[nt][0] = __expf(acc_s[nt][0] - nm0);
            acc_s[nt][1] = __expf(acc_s[nt][1] - nm0);
            acc_s[nt][2] = __expf(acc_s[nt][2] - nm1);
            acc_s[nt][3] = __expf(acc_s[nt][3] - nm1);
            s0 += acc_s[nt][0] + acc_s[nt][1];
            s1 += acc_s[nt][2] + acc_s[nt][3];
        }
        s0 += __shfl_xor_sync(0xffffffffu, s0, 1);
        s0 += __shfl_xor_sync(0xffffffffu, s0, 2);
        s1 += __shfl_xor_sync(0xffffffffu, s1, 1);
        s1 += __shfl_xor_sync(0xffffffffu, s1, 2);
        if ((lane & 3) == 0) {
            redsum[wn*64 + r0]     = s0;
            redsum[wn*64 + r0 + 8] = s1;
        }
        // write P (split) to smem: [Ph | Pl], 272B pitch
        {
            char* P = smem + PBASE;
            int colb = wn*32 + (lane & 3)*2;
#pragma unroll
            for (int nt = 0; nt < 4; nt++) {
                int col = colb + nt*8;
#pragma unroll
                for (int half = 0; half < 2; half++) {
                    float pa = acc_s[nt][half*2], pb = acc_s[nt][half*2+1];
                    int row = r0 + half*8;
                    __nv_bfloat16 ha = __float2bfloat16(pa), hb = __float2bfloat16(pb);
                    __nv_bfloat16 la = __float2bfloat16(pa - __bfloat162float(ha));
                    __nv_bfloat16 lb = __float2bfloat16(pb - __bfloat162float(hb));
                    uint32_t hi = (uint32_t)(*(uint16_t*)&ha) | ((uint32_t)(*(uint16_t*)&hb) << 16);
                    uint32_t lo = (uint32_t)(*(uint16_t*)&la) | ((uint32_t)(*(uint16_t*)&lb) << 16);
                    uint32_t* base = (uint32_t*)(P + row*272 + col*2);
                    base[0]  = hi;            // Ph
                    base[32] = lo;            // Pl (+128 B)
                }
            }
        }
        __syncthreads();
        float ts0 = s0 + redsum[(wn^1)*64 + r0];
        float ts1 = s1 + redsum[(wn^1)*64 + r0 + 8];
        l0 = l0 * f0 + ts0;
        l1 = l1 * f1 + ts1;
        m0 = nm0; m1 = nm1;
#pragma unroll
        for (int nt = 0; nt < 8; nt++) {
            acc_o[nt][0] *= f0; acc_o[nt][1] *= f0;
            acc_o[nt][2] *= f1; acc_o[nt][3] *= f1;
        }

        // ---- PV: (Ph,Vh), (Pl,Vh), (Ph,Vl) ----
#pragma unroll
        for (int pc = 0; pc < 3; pc++) {
            uint32_t pseg = (pc == 1) ? 128u : 0u;
            uint32_t vb   = sb + VBASE + ((pc == 2) ? 16384u : 0u);
#pragma unroll
            for (int ks = 0; ks < 4; ks++) {
                uint32_t a[4];
                ldsm4(a, sb + PBASE + (uint32_t)((wm*16 + a_row)*272) + pseg
                         + (uint32_t)(ks*32 + a_ch*16));
#pragma unroll
                for (int g = 0; g < 4; g++) {
                    uint32_t bb[4];
                    ldsm4(bb, vb + sw128(wn*64 + g*16 + b_nrow, ks*2 + b_ch));
                    mma16816(acc_o[g*2],   a, bb[0], bb[1]);
                    mma16816(acc_o[g*2+1], a, bb[2], bb[3]);
                }
            }
        }
        __syncthreads();
    }

    // ---- epilogue: split-bf16 output into ats ----
    float il0 = 1.f / l0, il1 = 1.f / l1;
    size_t mrow0 = (size_t)b * SS + q0 + r0;
#pragma unroll
    for (int nt = 0; nt < 8; nt++) {
        int col = h*128 + wn*64 + nt*8 + (lane & 3)*2;
#pragma unroll
        for (int half = 0; half < 2; half++) {
            float oa = acc_o[nt][half*2]   * (half ? il1 : il0);
            float ob = acc_o[nt][half*2+1] * (half ? il1 : il0);
            size_t row = mrow0 + half*8;
            __nv_bfloat16 ha = __float2bfloat16(oa), hb = __float2bfloat16(ob);
            __nv_bfloat16 la = __float2bfloat16(oa - __bfloat162float(ha));
            __nv_bfloat16 lb = __float2bfloat16(ob - __bfloat162float(hb));
            uint32_t hi = (uint32_t)(*(uint16_t*)&ha) | ((uint32_t)(*(uint16_t*)&hb) << 16);
            uint32_t lo = (uint32_t)(*(uint16_t*)&la) | ((uint32_t)(*(uint16_t*)&lb) << 16);
            uint32_t* o32 = (uint32_t*)(ats + row * 6144);
            o32[(col) >> 1]        = hi;
            o32[(2048 + col) >> 1] = lo;
            o32[(4096 + col) >> 1] = hi;
        }
    }
}

// ---------------- host orchestration ----------------
static void conv3(const float* in, __nv_bfloat16* out, int R, int Rpad, int C,
                  int inPitch, int mode)
{
    long long tot = (long long)Rpad * C;
    int blocks = (int)((tot + 255) / 256);
    split3_k<<<blocks, 256>>>(in, out, R, Rpad, C, inPitch, mode);
}

static void gemm3(const __nv_bfloat16* A, const __nv_bfloat16* B, float* C, int M, int N, int Kp)
{
    cudaFuncSetAttribute(gemm_tc, cudaFuncAttributeMaxDynamicSharedMemorySize, GEMM_SMEM);
    dim3 grid((N + 127) / 128, M / 128);
    gemm_tc<<<grid, 256, GEMM_SMEM>>>(A, B, C, M, N, Kp);
}

extern "C" void kernel_launch(void* const* d_in, const int* in_sizes, int n_in,
                              void* d_out, int out_size)
{
    const float* x        = (const float*)d_in[0];
    const float* wq_down  = (const float*)d_in[1];
    const float* q_norm_w = (const float*)d_in[2];
    const float* wq_up    = (const float*)d_in[3];
    const float* wq_rope  = (const float*)d_in[4];
    const float* wkv_down = (const float*)d_in[5];
    const float* kv_norm_w= (const float*)d_in[6];
    const float* wkv_up   = (const float*)d_in[7];
    const float* wk_rope  = (const float*)d_in[8];
    const float* wo       = (const float*)d_in[9];
    float* out = (float*)d_out;

    float *dall, *qnp, *kvu;
    cudaGetSymbolAddress((void**)&dall, g_dall);
    cudaGetSymbolAddress((void**)&qnp,  g_qnp);
    cudaGetSymbolAddress((void**)&kvu,  g_kvup);

    __nv_bfloat16 *xs, *wdall, *qcs, *wuall, *kvcs, *wkvu, *ats, *wos, *qsp, *ksp, *vt;
    cudaGetSymbolAddress((void**)&xs,    g_xs);
    cudaGetSymbolAddress((void**)&wdall, g_wdall);
    cudaGetSymbolAddress((void**)&qcs,   g_qcs);
    cudaGetSymbolAddress((void**)&wuall, g_wuall);
    cudaGetSymbolAddress((void**)&kvcs,  g_kvcs);
    cudaGetSymbolAddress((void**)&wkvu,  g_wkvu);
    cudaGetSymbolAddress((void**)&ats,   g_ats);
    cudaGetSymbolAddress((void**)&wos,   g_wos);
    cudaGetSymbolAddress((void**)&qsp,   g_qsp);
    cudaGetSymbolAddress((void**)&ksp,   g_ksp);
    cudaGetSymbolAddress((void**)&vt,    g_vt);

    // ---- stage 1: merged down projection (N = 1536|512|64 -> 2112) ----
    conv3(x,        xs,                      MT,   MT,  DIMM, DIMM, 0);
    conv3(wq_down,  wdall,                   QR,   QR,  DIMM, DIMM, 1);
    conv3(wkv_down, wdall + (size_t)QR*3*DIMM,        KVR, KVR, DIMM, DIMM, 1);
    conv3(wk_rope,  wdall + (size_t)(QR+KVR)*3*DIMM,  DR,  128, DIMM, DIMM, 1);
    gemm3(xs, wdall, dall, MT, NDOWN, 3*DIMM);

    // ---- norms + k_rope rope (in place, pitched) ----
    rmsnorm_k<<<MT, 256>>>(dall,        q_norm_w,  QR,  NDOWN);
    rmsnorm_k<<<MT, 256>>>(dall + QR,   kv_norm_w, KVR, NDOWN);
    rope_k<<<(MT*32 + 255)/256, 256>>>(dall, NDOWN, QR+KVR, 1, DR, MT*32);

    // ---- stage 2: merged up projection (N = 2048|1024 -> 3072) ----
    conv3(dall,      qcs,  MT, MT, QR,  NDOWN, 0);
    conv3(dall + QR, kvcs, MT, MT, KVR, NDOWN, 0);
    conv3(wq_up,   wuall,                        NH*DN, NH*DN, QR, QR, 1);
    conv3(wq_rope, wuall + (size_t)(NH*DN)*3*QR, NH*DR, NH*DR, QR, QR, 1);
    gemm3(qcs,  wuall, qnp, MT, NUP, 3*QR);
    conv3(wkv_up, wkvu, NH*(DN+DVV), NH*(DN+DVV), KVR, KVR, 1);
    gemm3(kvcs, wkvu,  kvu, MT, NH*(DN+DVV), 3*KVR);

    // ---- q rope (in place, pitched) ----
    rope_k<<<(MT*NH*32 + 255)/256, 256>>>(qnp, NUP, 2048, NH, DR, MT*NH*32);

    // ---- attention operand packing ----
    {
        long long tot = (long long)BB*NH*SS*192;
        int blocks = (int)((tot + 255) / 256);
        pack_q<<<blocks, 256>>>(qnp, qsp);
        pack_k<<<blocks, 256>>>(kvu, dall, ksp);
    }
    pack_v<<<dim3(SS/64, NH, BB), 256>>>(kvu, vt);

    // ---- HMMA flash attention -> split output in ats ----
    cudaFuncSetAttribute(attn_mma, cudaFuncAttributeMaxDynamicSharedMemorySize, ATT_SMEM);
    attn_mma<<<dim3(SS/64, NH, BB), 256, ATT_SMEM>>>(qsp, ksp, vt, ats);

    // ---- output projection ----
    conv3(wo, wos, DIMM, DIMM, NH*DVV, NH*DVV, 1);
    gemm3(ats, wos, out, MT, DIMM, 3*(NH*DVV));
}

// round 7
// speedup vs baseline: 8.9611x; 1.3719x over previous
#include <cuda_runtime.h>
#include <cuda_fp16.h>
#include <math.h>
#include <stdint.h>

#define BB 2
#define SS 2048
#define DIMM 2048
#define NH 16
#define QR 1536
#define KVR 512
#define DN 128
#define DR 64
#define DVV 128
#define MT (BB*SS)   // 4096 token rows

#define NDOWN 2112   // qc(1536) | kvc(512) | kr(64)
#define NDOWNP 2176  // padded rows for down weights
#define NUP 3072     // qn(2048) | qp(1024)

// ---------------- fp32 scratch ----------------
__device__ float g_dall[MT*NDOWN];
__device__ float g_qnp [MT*NUP];
__device__ float g_kvup[MT*NH*(DN+DVV)];

// ---------------- fp16 split scratch (A: [hi|lo] pitch 2K, B: hi pitch K) ----
__device__ __half g_xs   [MT    * 2*DIMM];
__device__ __half g_wdall[NDOWNP* DIMM];
__device__ __half g_qcs  [MT    * 2*QR];
__device__ __half g_wuall[NUP   * QR];
__device__ __half g_kvcs [MT    * 2*KVR];
__device__ __half g_wkvu [(NH*(DN+DVV)) * KVR];
__device__ __half g_ats  [MT    * 2*(NH*DVV)];
__device__ __half g_wos  [DIMM  * (NH*DVV)];

// ---------------- attention packed operands ----------------
__device__ __half g_qsp[BB*NH*SS*384];     // [bh][s][Qh(192)|Ql(192)]
__device__ __half g_ksp[BB*NH*SS*192];     // [bh][s][Kh(192)]
__device__ __half g_vt [BB*NH*128*SS];     // [bh][d][s]  (Vh only, transposed)

// ============================================================
// helpers
// ============================================================
__device__ __forceinline__ uint32_t smem_u32(const void* p){
    uint32_t a;
    asm("{ .reg .u64 t; cvta.to.shared.u64 t, %1; cvt.u32.u64 %0, t; }" : "=r"(a) : "l"(p));
    return a;
}
#define CPA16(dst, src) asm volatile("cp.async.cg.shared.global [%0], [%1], 16;" :: "r"(dst), "l"(src))
#define CPCOMMIT()      asm volatile("cp.async.commit_group;")
#define CPWAIT(n)       asm volatile("cp.async.wait_group %0;" :: "n"(n))

__device__ __forceinline__ void ldsm4(uint32_t* r, uint32_t addr){
    asm volatile("ldmatrix.sync.aligned.m8n8.x4.shared.b16 {%0,%1,%2,%3}, [%4];"
        : "=r"(r[0]), "=r"(r[1]), "=r"(r[2]), "=r"(r[3]) : "r"(addr));
}
__device__ __forceinline__ void mma16816(float* c, const uint32_t* a, uint32_t b0, uint32_t b1){
    asm volatile("mma.sync.aligned.m16n8k16.row.col.f32.f16.f16.f32 "
        "{%0,%1,%2,%3}, {%4,%5,%6,%7}, {%8,%9}, {%0,%1,%2,%3};"
        : "+f"(c[0]), "+f"(c[1]), "+f"(c[2]), "+f"(c[3])
        : "r"(a[0]), "r"(a[1]), "r"(a[2]), "r"(a[3]), "r"(b0), "r"(b1));
}
__device__ __forceinline__ uint32_t sw128(int row, int chunk){
    return (uint32_t)(row * 128 + ((chunk ^ (row & 7)) * 16));
}

// ============================================================
// conversions
// ============================================================
__global__ void splitA_k(const float* __restrict__ in, __half* __restrict__ out,
                         int R, int Rpad, int C, int inPitch)
{
    long long i = (long long)blockIdx.x * blockDim.x + threadIdx.x;
    long long tot = (long long)Rpad * C;
    if (i >= tot) return;
    int r = (int)(i / C), c = (int)(i % C);
    float x = (r < R) ? in[(size_t)r * inPitch + c] : 0.f;
    __half h = __float2half(x);
    __half l = __float2half(x - __half2float(h));
    size_t base = (size_t)r * 2 * C;
    out[base + c] = h; out[base + C + c] = l;
}
__global__ void cvtB_k(const float* __restrict__ in, __half* __restrict__ out,
                       int R, int Rpad, int C, int inPitch)
{
    long long i = (long long)blockIdx.x * blockDim.x + threadIdx.x;
    long long tot = (long long)Rpad * C;
    if (i >= tot) return;
    int r = (int)(i / C), c = (int)(i % C);
    float x = (r < R) ? in[(size_t)r * inPitch + c] : 0.f;
    out[(size_t)r * C + c] = __float2half(x);
}

// ============================================================
// fp16 2-term GEMM: C = A([Ah|Al], pitch 2K) * B(hi, pitch K)^T
// ============================================================
#define STAGES 3
#define STAGE_BYTES 32768
#define GEMM_SMEM (STAGES*STAGE_BYTES)

__global__ __launch_bounds__(256, 2) void gemm_tc(
    const __half* __restrict__ A, const __half* __restrict__ B,
    float* __restrict__ C, int M, int N, int K)
{
    extern __shared__ __align__(16) char smem[];
    const uint32_t sb = smem_u32(smem);
    const int m0 = blockIdx.y * 128, n0 = blockIdx.x * 128;
    const int tid = threadIdx.x, lane = tid & 31;
    const int wm = (tid >> 5) & 3;
    const int wn = tid >> 7;

    float acc[2][8][4];
#pragma unroll
    for (int i = 0; i < 2; i++)
#pragma unroll
        for (int j = 0; j < 8; j++)
#pragma unroll
            for (int q = 0; q < 4; q++) acc[i][j][q] = 0.f;

    const int KA = 2 * K;
    const int KT  = KA >> 6;
    const int KTh = KT >> 1;
    const __half* Ag0 = A + (size_t)m0 * KA;
    const __half* Bg0 = B + (size_t)n0 * K;

    const int fr = tid >> 3;
    const int fc = tid & 7;

    auto fill = [&](int j){
        uint32_t base = sb + (uint32_t)(j % STAGES) * STAGE_BYTES;
        int ka = j << 6;
        int kb = (j >= KTh ? j - KTh : j) << 6;
#pragma unroll
        for (int i = 0; i < 4; i++) {
            int r = fr + i * 32;
            CPA16(base + sw128(r, fc), Ag0 + (size_t)r * KA + ka + fc*8);
        }
#pragma unroll
        for (int i = 0; i < 4; i++) {
            int r = fr + i * 32;
            CPA16(base + 16384u + sw128(r, fc), Bg0 + (size_t)r * K + kb + fc*8);
        }
        CPCOMMIT();
    };

    fill(0);
    fill(1);

    const int a_row  = lane & 15;
    const int a_ch   = lane >> 4;
    const int b_nrow = (lane & 7) + ((lane & 16) ? 8 : 0);
    const int b_ch   = (lane >> 3) & 1;

    for (int kt = 0; kt < KT; kt++) {
        CPWAIT(1);
        __syncthreads();
        if (kt + 2 < KT) fill(kt + 2);
        else CPCOMMIT();

        uint32_t aT = sb + (uint32_t)(kt % STAGES) * STAGE_BYTES;
        uint32_t bT = aT + 16384u;
#pragma unroll
        for (int ks = 0; ks < 4; ks++) {
            uint32_t a[2][4];
#pragma unroll
            for (int i = 0; i < 2; i++)
                ldsm4(a[i], aT + sw128(wm*32 + i*16 + a_row, ks*2 + a_ch));
            uint32_t b[4][4];
#pragma unroll
            for (int g = 0; g < 4; g++)
                ldsm4(b[g], bT + sw128(wn*64 + g*16 + b_nrow, ks*2 + b_ch));
#pragma unroll
            for (int i = 0; i < 2; i++)
#pragma unroll
                for (int g = 0; g < 4; g++) {
                    mma16816(acc[i][2*g],   a[i], b[g][0], b[g][1]);
                    mma16816(acc[i][2*g+1], a[i], b[g][2], b[g][3]);
                }
        }
    }

    const int rb = m0 + wm*32;
    const int cb = n0 + wn*64;
#pragma unroll
    for (int i = 0; i < 2; i++)
#pragma unroll
        for (int j = 0; j < 8; j++) {
            int c = cb + j*8 + (lane & 3)*2;
            if (c < N) {
                int r = rb + i*16 + (lane >> 2);
                *(float2*)&C[(size_t)r * N + c]     = make_float2(acc[i][j][0], acc[i][j][1]);
                *(float2*)&C[(size_t)(r+8) * N + c] = make_float2(acc[i][j][2], acc[i][j][3]);
            }
        }
}

// ---------------- RMSNorm (pitched, in place) ----------------
__global__ void rmsnorm_k(float* __restrict__ x, const float* __restrict__ w,
                          int W, int pitch)
{
    const int row = blockIdx.x;
    float* xr = x + (size_t)row * pitch;
    float ss = 0.f;
    for (int i = threadIdx.x; i < W; i += blockDim.x) { float v = xr[i]; ss += v * v; }
    __shared__ float red[32];
#pragma unroll
    for (int o = 16; o; o >>= 1) ss += __shfl_down_sync(0xffffffffu, ss, o);
    if ((threadIdx.x & 31) == 0) red[threadIdx.x >> 5] = ss;
    __syncthreads();
    if (threadIdx.x < 32) {
        float v = (threadIdx.x < (blockDim.x >> 5)) ? red[threadIdx.x] : 0.f;
#pragma unroll
        for (int o = 16; o; o >>= 1) v += __shfl_down_sync(0xffffffffu, v, o);
        if (threadIdx.x == 0) red[0] = rsqrtf(v / (float)W + 1e-6f);
    }
    __syncthreads();
    float r = red[0];
    for (int i = threadIdx.x; i < W; i += blockDim.x)
        xr[i] = xr[i] * r * w[i];
}

// ---------------- RoPE (pitched, col offset, in place) ----------------
__global__ void rope_k(float* __restrict__ x, int pitch, int colOff,
                       int nheads, int d, int total_pairs)
{
    int idx = blockIdx.x * blockDim.x + threadIdx.x;
    if (idx >= total_pairs) return;
    int pairs_per_row = nheads * (d / 2);
    int row = idx / pairs_per_row;
    int p   = idx % pairs_per_row;
    int h = p / (d / 2);
    int i = p % (d / 2);
    int pos = row % SS;
    float inv = powf(10000.f, (-2.0f * (float)i) / (float)d);
    float ang = (float)pos * inv;
    float s, c;
    sincosf(ang, &s, &c);
    float* base = x + (size_t)row * pitch + colOff + h * d + 2 * i;
    float x1 = base[0], x2 = base[1];
    base[0] = x1 * c - x2 * s;
    base[1] = x1 * s + x2 * c;
}

// ============================================================
// attention operand packing
// ============================================================
__global__ void pack_q(const float* __restrict__ qnp, __half* __restrict__ out)
{
    long long idx = (long long)blockIdx.x * blockDim.x + threadIdx.x;
    if (idx >= (long long)BB*NH*SS*192) return;
    int d  = (int)(idx % 192);
    int s  = (int)((idx / 192) % SS);
    int bh = (int)(idx / (192LL*SS));
    int b = bh / NH, h = bh % NH;
    size_t m = (size_t)b * SS + s;
    const float scale = 1.0f / sqrtf(192.f);
    float v = ((d < 128) ? qnp[m * NUP + h*128 + d]
                         : qnp[m * NUP + 2048 + h*64 + (d-128)]) * scale;
    __half hi = __float2half(v);
    __half lo = __float2half(v - __half2float(hi));
    size_t base = ((size_t)bh * SS + s) * 384;
    out[base + d] = hi; out[base + 192 + d] = lo;
}

__global__ void pack_k(const float* __restrict__ kv, const float* __restrict__ dall,
                       __half* __restrict__ out)
{
    long long idx = (long long)blockIdx.x * blockDim.x + threadIdx.x;
    if (idx >= (long long)BB*NH*SS*192) return;
    int d  = (int)(idx % 192);
    int s  = (int)((idx / 192) % SS);
    int bh = (int)(idx / (192LL*SS));
    int b = bh / NH, h = bh % NH;
    size_t m = (size_t)b * SS + s;
    float v = (d < 128) ? kv[m * (NH*256) + h*256 + d]
                        : dall[m * NDOWN + 2048 + (d-128)];
    out[((size_t)bh * SS + s) * 192 + d] = __float2half(v);
}

// V pack (transpose, hi only): vt[bh][d][s]
__global__ __launch_bounds__(256) void pack_v(const float* __restrict__ kv,
                                              __half* __restrict__ vt)
{
    __shared__ float vs[64][129];
    const int t = blockIdx.x, h = blockIdx.y, b = blockIdx.z;
    const int bh = b*NH + h;
    const int tid = threadIdx.x;
    for (int i = tid; i < 64*128; i += 256) {
        int r = i >> 7, d = i & 127;
        size_t m = (size_t)b * SS + t*64 + r;
        vs[r][d] = kv[m * (NH*256) + h*256 + 128 + d];
    }
    __syncthreads();
    uint32_t* out32 = (uint32_t*)vt;
    for (int i = tid; i < 128*32; i += 256) {
        int d = i >> 5, w = i & 31;
        int kk = w * 2;
        __half p0 = __float2half(vs[kk][d]);
        __half p1 = __float2half(vs[kk+1][d]);
        uint32_t packed = (uint32_t)(*(uint16_t*)&p0) | ((uint32_t)(*(uint16_t*)&p1) << 16);
        out32[((size_t)bh * 128 + d) * (SS/2) + t*32 + w] = packed;
    }
}

// ============================================================
// HMMA flash attention — fp16 2-term, 6 S-chunks, 2 PV-chunks
// smem: [0,49152)  QK slots (Q s*16384, K s*16384+8192)
//       [49152,65536) V (16KB)
//       [65536,82944) P: 64 rows x 272B [Ph|Pl]
//       [82944,83456) redmax  [83456,83968) redsum
// ============================================================
#define VBASE 49152u
#define PBASE 65536u
#define ATT_SMEM 83968

__global__ __launch_bounds__(256, 2) void attn_mma(
    const __half* __restrict__ Qsp, const __half* __restrict__ Ksp,
    const __half* __restrict__ Vt, __half* __restrict__ ats)
{
    extern __shared__ __align__(16) char smem[];
    const uint32_t sb = smem_u32(smem);
    const int qt = blockIdx.x, h = blockIdx.y, b = blockIdx.z;
    const int bh = b*NH + h;
    const int q0 = qt * 64;
    const int tid = threadIdx.x, lane = tid & 31;
    const int wm = (tid >> 5) & 3, wn = tid >> 7;

    const __half* Qg = Qsp + ((size_t)bh * SS + q0) * 384;
    const __half* Kg = Ksp + (size_t)bh * SS * 192;
    const __half* Vg = Vt  + (size_t)bh * 128 * SS;

    float* redmax = (float*)(smem + 82944);
    float* redsum = (float*)(smem + 83456);

    float acc_o[8][4];
#pragma unroll
    for (int i = 0; i < 8; i++)
#pragma unroll
        for (int j = 0; j < 4; j++) acc_o[i][j] = 0.f;
    float m0 = -1e30f, m1 = -1e30f, l0 = 0.f, l1 = 0.f;

    const int a_row  = lane & 15;
    const int a_ch   = lane >> 4;
    const int b_nrow = (lane & 7) + ((lane & 16) ? 8 : 0);
    const int b_ch   = (lane >> 3) & 1;
    const int r0 = wm*16 + (lane >> 2);

    for (int t = 0; t <= qt; t++) {
        const int k0 = t * 64;
#pragma unroll
        for (int slot = 0; slot < 2; slot++) {
#pragma unroll
            for (int it = 0; it < 2; it++) {
                int i = tid + it*256; int r = i >> 3, ch = i & 7;
                CPA16(sb + slot*16384u + sw128(r, ch), Qg + (size_t)r*384 + slot*64 + ch*8);
                CPA16(sb + slot*16384u + 8192u + sw128(r, ch), Kg + (size_t)(k0 + r)*192 + slot*64 + ch*8);
            }
            CPCOMMIT();
        }
#pragma unroll
        for (int it = 0; it < 4; it++) {
            int i = tid + it*256;
            int d = i >> 3, ch = i & 7;
            CPA16(sb + VBASE + sw128(d, ch), Vg + (size_t)d*SS + t*64 + ch*8);
        }
        CPCOMMIT();

        float acc_s[4][4];
#pragma unroll
        for (int i = 0; i < 4; i++)
#pragma unroll
            for (int j = 0; j < 4; j++) acc_s[i][j] = 0.f;

        for (int c = 0; c < 6; c++) {
            if (c < 2)       { CPWAIT(2); }
            else if (c == 5) { CPWAIT(0); }
            else             { CPWAIT(1); }
            __syncthreads();
            if (c + 2 < 6) {
                int slot = (c + 2) % 3;
                int kc = (c + 2 >= 3) ? (c - 1) : (c + 2);
#pragma unroll
                for (int it = 0; it < 2; it++) {
                    int i = tid + it*256; int r = i >> 3, ch = i & 7;
                    CPA16(sb + (uint32_t)slot*16384u + sw128(r, ch),
                          Qg + (size_t)r*384 + (c+2)*64 + ch*8);
                    CPA16(sb + (uint32_t)slot*16384u + 8192u + sw128(r, ch),
                          Kg + (size_t)(k0 + r)*192 + kc*64 + ch*8);
                }
                CPCOMMIT();
            }
            uint32_t qb = sb + (uint32_t)(c % 3) * 16384u;
            uint32_t kb = qb + 8192u;
#pragma unroll
            for (int ks = 0; ks < 4; ks++) {
                uint32_t a[4];
                ldsm4(a, qb + sw128(wm*16 + a_row, ks*2 + a_ch));
#pragma unroll
                for (int g = 0; g < 2; g++) {
                    uint32_t bb[4];
                    ldsm4(bb, kb + sw128(wn*32 + g*16 + b_nrow, ks*2 + b_ch));
                    mma16816(acc_s[g*2],   a, bb[0], bb[1]);
                    mma16816(acc_s[g*2+1], a, bb[2], bb[3]);
                }
            }
        }

        if (t == qt) {
#pragma unroll
            for (int nt = 0; nt < 4; nt++) {
                int colb = wn*32 + nt*8 + (lane & 3)*2;
                if (colb     > r0)     acc_s[nt][0] = -1e30f;
                if (colb + 1 > r0)     acc_s[nt][1] = -1e30f;
                if (colb     > r0 + 8) acc_s[nt][2] = -1e30f;
                if (colb + 1 > r0 + 8) acc_s[nt][3] = -1e30f;
            }
        }

        float mx0 = -1e30f, mx1 = -1e30f;
#pragma unroll
        for (int nt = 0; nt < 4; nt++) {
            mx0 = fmaxf(mx0, fmaxf(acc_s[nt][0], acc_s[nt][1]));
            mx1 = fmaxf(mx1, fmaxf(acc_s[nt][2], acc_s[nt][3]));
        }
        mx0 = fmaxf(mx0, __shfl_xor_sync(0xffffffffu, mx0, 1));
        mx0 = fmaxf(mx0, __shfl_xor_sync(0xffffffffu, mx0, 2));
        mx1 = fmaxf(mx1, __shfl_xor_sync(0xffffffffu, mx1, 1));
        mx1 = fmaxf(mx1, __shfl_xor_sync(0xffffffffu, mx1, 2));
        if ((lane & 3) == 0) {
            redmax[wn*64 + r0]     = mx0;
            redmax[wn*64 + r0 + 8] = mx1;
        }
        __syncthreads();
        float tm0 = fmaxf(mx0, redmax[(wn^1)*64 + r0]);
        float tm1 = fmaxf(mx1, redmax[(wn^1)*64 + r0 + 8]);
        float nm0 = fmaxf(m0, tm0), nm1 = fmaxf(m1, tm1);
        float f0 = __expf(m0 - nm0), f1 = __expf(m1 - nm1);

        float s0 = 0.f, s1 = 0.f;
#pragma unroll
        for (int nt = 0; nt < 4; nt++) {
            acc_s[nt][0] = __expf(acc_s[nt][0] - nm0);
            acc_s[nt][1] = __expf(acc_s[nt][1] - nm0);
            acc_s[nt][2] = __expf(acc_s[nt][2] - nm1);
            acc_s[nt][3] = __expf(acc_s[nt][3] - nm1);
            s0 += acc_s[nt][0] + acc_s[nt][1];
            s1 += acc_s[nt][2] + acc_s[nt][3];
        }
        s0 += __shfl_xor_sync(0xffffffffu, s0, 1);
        s0 += __shfl_xor_sync(0xffffffffu, s0, 2);
        s1 += __shfl_xor_sync(0xffffffffu, s1, 1);
        s1 += __shfl_xor_sync(0xffffffffu, s1, 2);
        if ((lane & 3) == 0) {
            redsum[wn*64 + r0]     = s0;
            redsum[wn*64 + r0 + 8] = s1;
        }
        {
            char* P = smem + PBASE;
            int colb = wn*32 + (lane & 3)*2;
#pragma unroll
            for (int nt = 0; nt < 4; nt++) {
                int col = colb + nt*8;
#pragma unroll
                for (int half = 0; half < 2; half++) {
                    float pa = acc_s[nt][half*2], pb = acc_s[nt][half*2+1];
                    int row = r0 + half*8;
                    __half ha = __float2half(pa), hb = __float2half(pb);
                    __half la = __float2half(pa - __half2float(ha));
                    __half lb = __float2half(pb - __half2float(hb));
                    uint32_t hi = (uint32_t)(*(uint16_t*)&ha) | ((uint32_t)(*(uint16_t*)&hb) << 16);
                    uint32_t lo = (uint32_t)(*(uint16_t*)&la) | ((uint32_t)(*(uint16_t*)&lb) << 16);
                    uint32_t* base = (uint32_t*)(P + row*272 + col*2);
                    base[0]  = hi;
                    base[32] = lo;
                }
            }
        }
        __syncthreads();
        float ts0 = s0 + redsum[(wn^1)*64 + r0];
        float ts1 = s1 + redsum[(wn^1)*64 + r0 + 8];
        l0 = l0 * f0 + ts0;
        l1 = l1 * f1 + ts1;
        m0 = nm0; m1 = nm1;
#pragma unroll
        for (int nt = 0; nt < 8; nt++) {
            acc_o[nt][0] *= f0; acc_o[nt][1] *= f0;
            acc_o[nt][2] *= f1; acc_o[nt][3] *= f1;
        }

#pragma unroll
        for (int pc = 0; pc < 2; pc++) {
            uint32_t pseg = (uint32_t)pc * 128u;
#pragma unroll
            for (int ks = 0; ks < 4; ks++) {
                uint32_t a[4];
                ldsm4(a, sb + PBASE + (uint32_t)((wm*16 + a_row)*272) + pseg
                         + (uint32_t)(ks*32 + a_ch*16));
#pragma unroll
                for (int g = 0; g < 4; g++) {
                    uint32_t bb[4];
                    ldsm4(bb, sb + VBASE + sw128(wn*64 + g*16 + b_nrow, ks*2 + b_ch));
                    mma16816(acc_o[g*2],   a, bb[0], bb[1]);
                    mma16816(acc_o[g*2+1], a, bb[2], bb[3]);
                }
            }
        }
        __syncthreads();
    }

    float il0 = 1.f / l0, il1 = 1.f / l1;
    size_t mrow0 = (size_t)b * SS + q0 + r0;
#pragma unroll
    for (int nt = 0; nt < 8; nt++) {
        int col = h*128 + wn*64 + nt*8 + (lane & 3)*2;
#pragma unroll
        for (int half = 0; half < 2; half++) {
            float oa = acc_o[nt][half*2]   * (half ? il1 : il0);
            float ob = acc_o[nt][half*2+1] * (half ? il1 : il0);
            size_t row = mrow0 + half*8;
            __half ha = __float2half(oa), hb = __float2half(ob);
            __half la = __float2half(oa - __half2float(ha));
            __half lb = __float2half(ob - __half2float(hb));
            uint32_t hi = (uint32_t)(*(uint16_t*)&ha) | ((uint32_t)(*(uint16_t*)&hb) << 16);
            uint32_t lo = (uint32_t)(*(uint16_t*)&la) | ((uint32_t)(*(uint16_t*)&lb) << 16);
            uint32_t* o32 = (uint32_t*)(ats + row * 4096);
            o32[col >> 1]          = hi;
            o32[1024 + (col >> 1)] = lo;
        }
    }
}

// ---------------- host orchestration ----------------
static void convA(const float* in, __half* out, int R, int Rpad, int C, int inPitch)
{
    long long tot = (long long)Rpad * C;
    splitA_k<<<(int)((tot + 255) / 256), 256>>>(in, out, R, Rpad, C, inPitch);
}
static void convB(const float* in, __half* out, int R, int Rpad, int C, int inPitch)
{
    long long tot = (long long)Rpad * C;
    cvtB_k<<<(int)((tot + 255) / 256), 256>>>(in, out, R, Rpad, C, inPitch);
}
static void gemm2(const __half* A, const __half* B, float* C, int M, int N, int K)
{
    cudaFuncSetAttribute(gemm_tc, cudaFuncAttributeMaxDynamicSharedMemorySize, GEMM_SMEM);
    dim3 grid((N + 127) / 128, M / 128);
    gemm_tc<<<grid, 256, GEMM_SMEM>>>(A, B, C, M, N, K);
}

extern "C" void kernel_launch(void* const* d_in, const int* in_sizes, int n_in,
                              void* d_out, int out_size)
{
    const float* x        = (const float*)d_in[0];
    const float* wq_down  = (const float*)d_in[1];
    const float* q_norm_w = (const float*)d_in[2];
    const float* wq_up    = (const float*)d_in[3];
    const float* wq_rope  = (const float*)d_in[4];
    const float* wkv_down = (const float*)d_in[5];
    const float* kv_norm_w= (const float*)d_in[6];
    const float* wkv_up   = (const float*)d_in[7];
    const float* wk_rope  = (const float*)d_in[8];
    const float* wo       = (const float*)d_in[9];
    float* out = (float*)d_out;

    float *dall, *qnp, *kvu;
    cudaGetSymbolAddress((void**)&dall, g_dall);
    cudaGetSymbolAddress((void**)&qnp,  g_qnp);
    cudaGetSymbolAddress((void**)&kvu,  g_kvup);

    __half *xs, *wdall, *qcs, *wuall, *kvcs, *wkvu, *ats, *wos, *qsp, *ksp, *vt;
    cudaGetSymbolAddress((void**)&xs,    g_xs);
    cudaGetSymbolAddress((void**)&wdall, g_wdall);
    cudaGetSymbolAddress((void**)&qcs,   g_qcs);
    cudaGetSymbolAddress((void**)&wuall, g_wuall);
    cudaGetSymbolAddress((void**)&kvcs,  g_kvcs);
    cudaGetSymbolAddress((void**)&wkvu,  g_wkvu);
    cudaGetSymbolAddress((void**)&ats,   g_ats);
    cudaGetSymbolAddress((void**)&wos,   g_wos);
    cudaGetSymbolAddress((void**)&qsp,   g_qsp);
    cudaGetSymbolAddress((void**)&ksp,   g_ksp);
    cudaGetSymbolAddress((void**)&vt,    g_vt);

    // ---- stage 1: merged down projection (all convs BEFORE the gemm) ----
    convA(x,        xs,    MT,  MT,  DIMM, DIMM);
    convB(wq_down,  wdall,                         QR,  QR,  DIMM, DIMM);
    convB(wkv_down, wdall + (size_t)QR*DIMM,       KVR, KVR, DIMM, DIMM);
    convB(wk_rope,  wdall + (size_t)(QR+KVR)*DIMM, DR,  128, DIMM, DIMM);
    gemm2(xs, wdall, dall, MT, NDOWN, DIMM);

    // ---- norms + k_rope rope ----
    rmsnorm_k<<<MT, 256>>>(dall,      q_norm_w,  QR,  NDOWN);
    rmsnorm_k<<<MT, 256>>>(dall + QR, kv_norm_w, KVR, NDOWN);
    rope_k<<<(MT*32 + 255)/256, 256>>>(dall, NDOWN, QR+KVR, 1, DR, MT*32);

    // ---- stage 2: merged up projection ----
    convA(dall,      qcs,  MT, MT, QR,  NDOWN);
    convA(dall + QR, kvcs, MT, MT, KVR, NDOWN);
    convB(wq_up,   wuall,                      NH*DN, NH*DN, QR, QR);
    convB(wq_rope, wuall + (size_t)(NH*DN)*QR, NH*DR, NH*DR, QR, QR);
    gemm2(qcs,  wuall, qnp, MT, NUP, QR);
    convB(wkv_up, wkvu, NH*(DN+DVV), NH*(DN+DVV), KVR, KVR);
    gemm2(kvcs, wkvu,  kvu, MT, NH*(DN+DVV), KVR);

    // ---- q rope ----
    rope_k<<<(MT*NH*32 + 255)/256, 256>>>(qnp, NUP, 2048, NH, DR, MT*NH*32);

    // ---- attention operand packing ----
    {
        long long tot = (long long)BB*NH*SS*192;
        int blocks = (int)((tot + 255) / 256);
        pack_q<<<blocks, 256>>>(qnp, qsp);
        pack_k<<<blocks, 256>>>(kvu, dall, ksp);
    }
    pack_v<<<dim3(SS/64, NH, BB), 256>>>(kvu, vt);

    // ---- HMMA flash attention -> split output in ats ----
    cudaFuncSetAttribute(attn_mma, cudaFuncAttributeMaxDynamicSharedMemorySize, ATT_SMEM);
    attn_mma<<<dim3(SS/64, NH, BB), 256, ATT_SMEM>>>(qsp, ksp, vt, ats);

    // ---- output projection ----
    convB(wo, wos, DIMM, DIMM, NH*DVV, NH*DVV);
    gemm2(ats, wos, out, MT, DIMM, NH*DVV);
}

// round 8
// speedup vs baseline: 10.1225x; 1.1296x over previous
#include <cuda_runtime.h>
#include <cuda_fp16.h>
#include <math.h>
#include <stdint.h>

#define BB 2
#define SS 2048
#define DIMM 2048
#define NH 16
#define QR 1536
#define KVR 512
#define DN 128
#define DR 64
#define DVV 128
#define MT (BB*SS)   // 4096 token rows

#define NDOWN 2112   // qc(1536) | kvc(512) | kr(64)
#define NDOWNP 2176
#define NUP 3072     // qn(2048) | qp(1024)

// ---------------- fp32 scratch ----------------
__device__ float g_dall[MT*NDOWN];
__device__ float g_qnp [MT*NUP];
__device__ float g_kvup[MT*NH*(DN+DVV)];

// ---------------- fp16 scratch ----------------
__device__ __half g_xs   [MT    * 2*DIMM];     // [Xh|Xl]
__device__ __half g_wdall[NDOWNP* DIMM];
__device__ __half g_qcs  [MT    * 2*QR];       // [Qch|Qcl] (written by rmsnorm_split)
__device__ __half g_wuall[NUP   * QR];
__device__ __half g_kvcs [MT    * 2*KVR];
__device__ __half g_wkvu [(NH*(DN+DVV)) * KVR];
__device__ __half g_ats  [MT    * (NH*DVV)];   // attention out, hi only
__device__ __half g_wos  [DIMM  * (NH*DVV)];

// ---------------- attention packed operands ----------------
__device__ __half g_qsp[BB*NH*SS*384];     // [bh][s][Qh(192)|Ql(192)] (rope applied)
__device__ __half g_ksp[BB*NH*SS*192];     // [bh][s][Kh(192)]
__device__ __half g_vt [BB*NH*128*SS];     // [bh][d][s] (Vh, transposed)

// ============================================================
// helpers
// ============================================================
__device__ __forceinline__ uint32_t smem_u32(const void* p){
    uint32_t a;
    asm("{ .reg .u64 t; cvta.to.shared.u64 t, %1; cvt.u32.u64 %0, t; }" : "=r"(a) : "l"(p));
    return a;
}
#define CPA16(dst, src) asm volatile("cp.async.cg.shared.global [%0], [%1], 16;" :: "r"(dst), "l"(src))
#define CPCOMMIT()      asm volatile("cp.async.commit_group;")
#define CPWAIT(n)       asm volatile("cp.async.wait_group %0;" :: "n"(n))

__device__ __forceinline__ void ldsm4(uint32_t* r, uint32_t addr){
    asm volatile("ldmatrix.sync.aligned.m8n8.x4.shared.b16 {%0,%1,%2,%3}, [%4];"
        : "=r"(r[0]), "=r"(r[1]), "=r"(r[2]), "=r"(r[3]) : "r"(addr));
}
__device__ __forceinline__ void mma16816(float* c, const uint32_t* a, uint32_t b0, uint32_t b1){
    asm volatile("mma.sync.aligned.m16n8k16.row.col.f32.f16.f16.f32 "
        "{%0,%1,%2,%3}, {%4,%5,%6,%7}, {%8,%9}, {%0,%1,%2,%3};"
        : "+f"(c[0]), "+f"(c[1]), "+f"(c[2]), "+f"(c[3])
        : "r"(a[0]), "r"(a[1]), "r"(a[2]), "r"(a[3]), "r"(b0), "r"(b1));
}
__device__ __forceinline__ uint32_t sw128(int row, int chunk){
    return (uint32_t)(row * 128 + ((chunk ^ (row & 7)) * 16));
}

// ============================================================
// conversions
// ============================================================
__global__ void splitA_k(const float* __restrict__ in, __half* __restrict__ out,
                         int R, int Rpad, int C, int inPitch)
{
    long long i = (long long)blockIdx.x * blockDim.x + threadIdx.x;
    long long tot = (long long)Rpad * C;
    if (i >= tot) return;
    int r = (int)(i / C), c = (int)(i % C);
    float x = (r < R) ? in[(size_t)r * inPitch + c] : 0.f;
    __half h = __float2half(x);
    __half l = __float2half(x - __half2float(h));
    size_t base = (size_t)r * 2 * C;
    out[base + c] = h; out[base + C + c] = l;
}
__global__ void cvtB_k(const float* __restrict__ in, __half* __restrict__ out,
                       int R, int Rpad, int C, int inPitch)
{
    long long i = (long long)blockIdx.x * blockDim.x + threadIdx.x;
    long long tot = (long long)Rpad * C;
    if (i >= tot) return;
    int r = (int)(i / C), c = (int)(i % C);
    float x = (r < R) ? in[(size_t)r * inPitch + c] : 0.f;
    out[(size_t)r * C + c] = __float2half(x);
}

// ============================================================
// fp16 GEMM: C = A(pitch KA) * B(hi, pitch K)^T
// KA = 2K: 2-term split A [Ah|Al] vs Bh.  KA = K: plain fp16.
// ============================================================
#define STAGES 3
#define STAGE_BYTES 32768
#define GEMM_SMEM (STAGES*STAGE_BYTES)

__global__ __launch_bounds__(256, 2) void gemm_tc(
    const __half* __restrict__ A, const __half* __restrict__ B,
    float* __restrict__ C, int M, int N, int K, int KA)
{
    extern __shared__ __align__(16) char smem[];
    const uint32_t sb = smem_u32(smem);
    const int m0 = blockIdx.y * 128, n0 = blockIdx.x * 128;
    const int tid = threadIdx.x, lane = tid & 31;
    const int wm = (tid >> 5) & 3;
    const int wn = tid >> 7;

    float acc[2][8][4];
#pragma unroll
    for (int i = 0; i < 2; i++)
#pragma unroll
        for (int j = 0; j < 8; j++)
#pragma unroll
            for (int q = 0; q < 4; q++) acc[i][j][q] = 0.f;

    const int KT  = KA >> 6;
    const int KTh = K >> 6;
    const __half* Ag0 = A + (size_t)m0 * KA;
    const __half* Bg0 = B + (size_t)n0 * K;

    const int fr = tid >> 3;
    const int fc = tid & 7;

    auto fill = [&](int j){
        uint32_t base = sb + (uint32_t)(j % STAGES) * STAGE_BYTES;
        int ka = j << 6;
        int kb = (j >= KTh ? j - KTh : j) << 6;
#pragma unroll
        for (int i = 0; i < 4; i++) {
            int r = fr + i * 32;
            CPA16(base + sw128(r, fc), Ag0 + (size_t)r * KA + ka + fc*8);
        }
#pragma unroll
        for (int i = 0; i < 4; i++) {
            int r = fr + i * 32;
            CPA16(base + 16384u + sw128(r, fc), Bg0 + (size_t)r * K + kb + fc*8);
        }
        CPCOMMIT();
    };

    fill(0);
    fill(1);

    const int a_row  = lane & 15;
    const int a_ch   = lane >> 4;
    const int b_nrow = (lane & 7) + ((lane & 16) ? 8 : 0);
    const int b_ch   = (lane >> 3) & 1;

    for (int kt = 0; kt < KT; kt++) {
        CPWAIT(1);
        __syncthreads();
        if (kt + 2 < KT) fill(kt + 2);
        else CPCOMMIT();

        uint32_t aT = sb + (uint32_t)(kt % STAGES) * STAGE_BYTES;
        uint32_t bT = aT + 16384u;
#pragma unroll
        for (int ks = 0; ks < 4; ks++) {
            uint32_t a[2][4];
#pragma unroll
            for (int i = 0; i < 2; i++)
                ldsm4(a[i], aT + sw128(wm*32 + i*16 + a_row, ks*2 + a_ch));
            uint32_t b[4][4];
#pragma unroll
            for (int g = 0; g < 4; g++)
                ldsm4(b[g], bT + sw128(wn*64 + g*16 + b_nrow, ks*2 + b_ch));
#pragma unroll
            for (int i = 0; i < 2; i++)
#pragma unroll
                for (int g = 0; g < 4; g++) {
                    mma16816(acc[i][2*g],   a[i], b[g][0], b[g][1]);
                    mma16816(acc[i][2*g+1], a[i], b[g][2], b[g][3]);
                }
        }
    }

    const int rb = m0 + wm*32;
    const int cb = n0 + wn*64;
#pragma unroll
    for (int i = 0; i < 2; i++)
#pragma unroll
        for (int j = 0; j < 8; j++) {
            int c = cb + j*8 + (lane & 3)*2;
            if (c < N) {
                int r = rb + i*16 + (lane >> 2);
                *(float2*)&C[(size_t)r * N + c]     = make_float2(acc[i][j][0], acc[i][j][1]);
                *(float2*)&C[(size_t)(r+8) * N + c] = make_float2(acc[i][j][2], acc[i][j][3]);
            }
        }
}

// ---------------- RMSNorm -> split fp16 [hi|lo] (fused) ----------------
__global__ void rmsnorm_split_k(const float* __restrict__ x, const float* __restrict__ w,
                                __half* __restrict__ out, int W, int pitch)
{
    const int row = blockIdx.x;
    const float* xr = x + (size_t)row * pitch;
    float ss = 0.f;
    for (int i = threadIdx.x; i < W; i += blockDim.x) { float v = xr[i]; ss += v * v; }
    __shared__ float red[32];
#pragma unroll
    for (int o = 16; o; o >>= 1) ss += __shfl_down_sync(0xffffffffu, ss, o);
    if ((threadIdx.x & 31) == 0) red[threadIdx.x >> 5] = ss;
    __syncthreads();
    if (threadIdx.x < 32) {
        float v = (threadIdx.x < (blockDim.x >> 5)) ? red[threadIdx.x] : 0.f;
#pragma unroll
        for (int o = 16; o; o >>= 1) v += __shfl_down_sync(0xffffffffu, v, o);
        if (threadIdx.x == 0) red[0] = rsqrtf(v / (float)W + 1e-6f);
    }
    __syncthreads();
    float r = red[0];
    __half* orow = out + (size_t)row * 2 * W;
    for (int i = threadIdx.x; i < W; i += blockDim.x) {
        float v = xr[i] * r * w[i];
        __half h = __float2half(v);
        __half l = __float2half(v - __half2float(h));
        orow[i] = h; orow[W + i] = l;
    }
}

// ---------------- RoPE on k_rope slice of dall (in place) ----------------
__global__ void rope_k(float* __restrict__ x, int pitch, int colOff,
                       int nheads, int d, int total_pairs)
{
    int idx = blockIdx.x * blockDim.x + threadIdx.x;
    if (idx >= total_pairs) return;
    int pairs_per_row = nheads * (d / 2);
    int row = idx / pairs_per_row;
    int p   = idx % pairs_per_row;
    int h = p / (d / 2);
    int i = p % (d / 2);
    int pos = row % SS;
    float inv = powf(10000.f, (-2.0f * (float)i) / (float)d);
    float ang = (float)pos * inv;
    float s, c;
    sincosf(ang, &s, &c);
    float* base = x + (size_t)row * pitch + colOff + h * d + 2 * i;
    float x1 = base[0], x2 = base[1];
    base[0] = x1 * c - x2 * s;
    base[1] = x1 * s + x2 * c;
}

// ---------------- fused Q rope + split pack ----------------
// j < 128: nope elem.  j >= 128: rope pair p = j-128 covers dims 128+2p, 129+2p.
__global__ void rope_pack_q(const float* __restrict__ qnp, __half* __restrict__ out)
{
    long long idx = (long long)blockIdx.x * blockDim.x + threadIdx.x;
    if (idx >= (long long)BB*NH*SS*160) return;
    int j  = (int)(idx % 160);
    int s  = (int)((idx / 160) % SS);
    int bh = (int)(idx / (160LL*SS));
    int b = bh / NH, h = bh % NH;
    size_t m = (size_t)b * SS + s;
    const float scale = 1.0f / sqrtf(192.f);
    size_t base = ((size_t)bh * SS + s) * 384;
    if (j < 128) {
        float v = qnp[m * NUP + h*128 + j] * scale;
        __half hi = __float2half(v);
        __half lo = __float2half(v - __half2float(hi));
        out[base + j] = hi; out[base + 192 + j] = lo;
    } else {
        int p = j - 128;                      // 0..31
        const float* src = qnp + m * NUP + 2048 + h*64 + 2*p;
        float x1 = src[0], x2 = src[1];
        float inv = powf(10000.f, (-2.0f * (float)p) / 64.f);
        float sn, cs;
        sincosf((float)s * inv, &sn, &cs);
        float o1 = (x1 * cs - x2 * sn) * scale;
        float o2 = (x1 * sn + x2 * cs) * scale;
        int d = 128 + 2*p;
        __half h1 = __float2half(o1), h2 = __float2half(o2);
        __half l1 = __float2half(o1 - __half2float(h1));
        __half l2 = __float2half(o2 - __half2float(h2));
        out[base + d] = h1;       out[base + d + 1] = h2;
        out[base + 192 + d] = l1; out[base + 192 + d + 1] = l2;
    }
}

__global__ void pack_k(const float* __restrict__ kv, const float* __restrict__ dall,
                       __half* __restrict__ out)
{
    long long idx = (long long)blockIdx.x * blockDim.x + threadIdx.x;
    if (idx >= (long long)BB*NH*SS*192) return;
    int d  = (int)(idx % 192);
    int s  = (int)((idx / 192) % SS);
    int bh = (int)(idx / (192LL*SS));
    int b = bh / NH, h = bh % NH;
    size_t m = (size_t)b * SS + s;
    float v = (d < 128) ? kv[m * (NH*256) + h*256 + d]
                        : dall[m * NDOWN + 2048 + (d-128)];
    out[((size_t)bh * SS + s) * 192 + d] = __float2half(v);
}

__global__ __launch_bounds__(256) void pack_v(const float* __restrict__ kv,
                                              __half* __restrict__ vt)
{
    __shared__ float vs[64][129];
    const int t = blockIdx.x, h = blockIdx.y, b = blockIdx.z;
    const int bh = b*NH + h;
    const int tid = threadIdx.x;
    for (int i = tid; i < 64*128; i += 256) {
        int r = i >> 7, d = i & 127;
        size_t m = (size_t)b * SS + t*64 + r;
        vs[r][d] = kv[m * (NH*256) + h*256 + 128 + d];
    }
    __syncthreads();
    uint32_t* out32 = (uint32_t*)vt;
    for (int i = tid; i < 128*32; i += 256) {
        int d = i >> 5, w = i & 31;
        int kk = w * 2;
        __half p0 = __float2half(vs[kk][d]);
        __half p1 = __float2half(vs[kk+1][d]);
        uint32_t packed = (uint32_t)(*(uint16_t*)&p0) | ((uint32_t)(*(uint16_t*)&p1) << 16);
        out32[((size_t)bh * 128 + d) * (SS/2) + t*32 + w] = packed;
    }
}

// ============================================================
// HMMA flash attention — fp16 2-term, largest-first scheduling
// ============================================================
#define VBASE 49152u
#define PBASE 65536u
#define ATT_SMEM 83968

__global__ __launch_bounds__(256, 2) void attn_mma(
    const __half* __restrict__ Qsp, const __half* __restrict__ Ksp,
    const __half* __restrict__ Vt, __half* __restrict__ ats)
{
    extern __shared__ __align__(16) char smem[];
    const uint32_t sb = smem_u32(smem);
    const int qt = (int)gridDim.x - 1 - (int)blockIdx.x;   // heavy CTAs first
    const int h = blockIdx.y, b = blockIdx.z;
    const int bh = b*NH + h;
    const int q0 = qt * 64;
    const int tid = threadIdx.x, lane = tid & 31;
    const int wm = (tid >> 5) & 3, wn = tid >> 7;

    const __half* Qg = Qsp + ((size_t)bh * SS + q0) * 384;
    const __half* Kg = Ksp + (size_t)bh * SS * 192;
    const __half* Vg = Vt  + (size_t)bh * 128 * SS;

    float* redmax = (float*)(smem + 82944);
    float* redsum = (float*)(smem + 83456);

    float acc_o[8][4];
#pragma unroll
    for (int i = 0; i < 8; i++)
#pragma unroll
        for (int j = 0; j < 4; j++) acc_o[i][j] = 0.f;
    float m0 = -1e30f, m1 = -1e30f, l0 = 0.f, l1 = 0.f;

    const int a_row  = lane & 15;
    const int a_ch   = lane >> 4;
    const int b_nrow = (lane & 7) + ((lane & 16) ? 8 : 0);
    const int b_ch   = (lane >> 3) & 1;
    const int r0 = wm*16 + (lane >> 2);

    for (int t = 0; t <= qt; t++) {
        const int k0 = t * 64;
#pragma unroll
        for (int slot = 0; slot < 2; slot++) {
#pragma unroll
            for (int it = 0; it < 2; it++) {
                int i = tid + it*256; int r = i >> 3, ch = i & 7;
                CPA16(sb + slot*16384u + sw128(r, ch), Qg + (size_t)r*384 + slot*64 + ch*8);
                CPA16(sb + slot*16384u + 8192u + sw128(r, ch), Kg + (size_t)(k0 + r)*192 + slot*64 + ch*8);
            }
            CPCOMMIT();
        }
#pragma unroll
        for (int it = 0; it < 4; it++) {
            int i = tid + it*256;
            int d = i >> 3, ch = i & 7;
            CPA16(sb + VBASE + sw128(d, ch), Vg + (size_t)d*SS + t*64 + ch*8);
        }
        CPCOMMIT();

        float acc_s[4][4];
#pragma unroll
        for (int i = 0; i < 4; i++)
#pragma unroll
            for (int j = 0; j < 4; j++) acc_s[i][j] = 0.f;

        for (int c = 0; c < 6; c++) {
            if (c < 2)       { CPWAIT(2); }
            else if (c == 5) { CPWAIT(0); }
            else             { CPWAIT(1); }
            __syncthreads();
            if (c + 2 < 6) {
                int slot = (c + 2) % 3;
                int kc = (c + 2 >= 3) ? (c - 1) : (c + 2);
#pragma unroll
                for (int it = 0; it < 2; it++) {
                    int i = tid + it*256; int r = i >> 3, ch = i & 7;
                    CPA16(sb + (uint32_t)slot*16384u + sw128(r, ch),
                          Qg + (size_t)r*384 + (c+2)*64 + ch*8);
                    CPA16(sb + (uint32_t)slot*16384u + 8192u + sw128(r, ch),
                          Kg + (size_t)(k0 + r)*192 + kc*64 + ch*8);
                }
                CPCOMMIT();
            }
            uint32_t qb = sb + (uint32_t)(c % 3) * 16384u;
            uint32_t kb = qb + 8192u;
#pragma unroll
            for (int ks = 0; ks < 4; ks++) {
                uint32_t a[4];
                ldsm4(a, qb + sw128(wm*16 + a_row, ks*2 + a_ch));
#pragma unroll
                for (int g = 0; g < 2; g++) {
                    uint32_t bb[4];
                    ldsm4(bb, kb + sw128(wn*32 + g*16 + b_nrow, ks*2 + b_ch));
                    mma16816(acc_s[g*2],   a, bb[0], bb[1]);
                    mma16816(acc_s[g*2+1], a, bb[2], bb[3]);
                }
            }
        }

        if (t == qt) {
#pragma unroll
            for (int nt = 0; nt < 4; nt++) {
                int colb = wn*32 + nt*8 + (lane & 3)*2;
                if (colb     > r0)     acc_s[nt][0] = -1e30f;
                if (colb + 1 > r0)     acc_s[nt][1] = -1e30f;
                if (colb     > r0 + 8) acc_s[nt][2] = -1e30f;
                if (colb + 1 > r0 + 8) acc_s[nt][3] = -1e30f;
            }
        }

        float mx0 = -1e30f, mx1 = -1e30f;
#pragma unroll
        for (int nt = 0; nt < 4; nt++) {
            mx0 = fmaxf(mx0, fmaxf(acc_s[nt][0], acc_s[nt][1]));
            mx1 = fmaxf(mx1, fmaxf(acc_s[nt][2], acc_s[nt][3]));
        }
        mx0 = fmaxf(mx0, __shfl_xor_sync(0xffffffffu, mx0, 1));
        mx0 = fmaxf(mx0, __shfl_xor_sync(0xffffffffu, mx0, 2));
        mx1 = fmaxf(mx1, __shfl_xor_sync(0xffffffffu, mx1, 1));
        mx1 = fmaxf(mx1, __shfl_xor_sync(0xffffffffu, mx1, 2));
        if ((lane & 3) == 0) {
            redmax[wn*64 + r0]     = mx0;
            redmax[wn*64 + r0 + 8] = mx1;
        }
        __syncthreads();
        float tm0 = fmaxf(mx0, redmax[(wn^1)*64 + r0]);
        float tm1 = fmaxf(mx1, redmax[(wn^1)*64 + r0 + 8]);
        float nm0 = fmaxf(m0, tm0), nm1 = fmaxf(m1, tm1);
        float f0 = __expf(m0 - nm0), f1 = __expf(m1 - nm1);

        float s0 = 0.f, s1 = 0.f;
#pragma unroll
        for (int nt = 0; nt < 4; nt++) {
            acc_s[nt][0] = __expf(acc_s[nt][0] - nm0);
            acc_s[nt][1] = __expf(acc_s[nt][1] - nm0);
            acc_s[nt][2] = __expf(acc_s[nt][2] - nm1);
            acc_s[nt][3] = __expf(acc_s[nt][3] - nm1);
            s0 += acc_s[nt][0] + acc_s[nt][1];
            s1 += acc_s[nt][2] + acc_s[nt][3];
        }
        s0 += __shfl_xor_sync(0xffffffffu, s0, 1);
        s0 += __shfl_xor_sync(0xffffffffu, s0, 2);
        s1 += __shfl_xor_sync(0xffffffffu, s1, 1);
        s1 += __shfl_xor_sync(0xffffffffu, s1, 2);
        if ((lane & 3) == 0) {
            redsum[wn*64 + r0]     = s0;
            redsum[wn*64 + r0 + 8] = s1;
        }
        {
            char* P = smem + PBASE;
            int colb = wn*32 + (lane & 3)*2;
#pragma unroll
            for (int nt = 0; nt < 4; nt++) {
                int col = colb + nt*8;
#pragma unroll
                for (int half = 0; half < 2; half++) {
                    float pa = acc_s[nt][half*2], pb = acc_s[nt][half*2+1];
                    int row = r0 + half*8;
                    __half ha = __float2half(pa), hb = __float2half(pb);
                    __half la = __float2half(pa - __half2float(ha));
                    __half lb = __float2half(pb - __half2float(hb));
                    uint32_t hi = (uint32_t)(*(uint16_t*)&ha) | ((uint32_t)(*(uint16_t*)&hb) << 16);
                    uint32_t lo = (uint32_t)(*(uint16_t*)&la) | ((uint32_t)(*(uint16_t*)&lb) << 16);
                    uint32_t* base = (uint32_t*)(P + row*272 + col*2);
                    base[0]  = hi;
                    base[32] = lo;
                }
            }
        }
        __syncthreads();
        float ts0 = s0 + redsum[(wn^1)*64 + r0];
        float ts1 = s1 + redsum[(wn^1)*64 + r0 + 8];
        l0 = l0 * f0 + ts0;
        l1 = l1 * f1 + ts1;
        m0 = nm0; m1 = nm1;
#pragma unroll
        for (int nt = 0; nt < 8; nt++) {
            acc_o[nt][0] *= f0; acc_o[nt][1] *= f0;
            acc_o[nt][2] *= f1; acc_o[nt][3] *= f1;
        }

#pragma unroll
        for (int pc = 0; pc < 2; pc++) {
            uint32_t pseg = (uint32_t)pc * 128u;
#pragma unroll
            for (int ks = 0; ks < 4; ks++) {
                uint32_t a[4];
                ldsm4(a, sb + PBASE + (uint32_t)((wm*16 + a_row)*272) + pseg
                         + (uint32_t)(ks*32 + a_ch*16));
#pragma unroll
                for (int g = 0; g < 4; g++) {
                    uint32_t bb[4];
                    ldsm4(bb, sb + VBASE + sw128(wn*64 + g*16 + b_nrow, ks*2 + b_ch));
                    mma16816(acc_o[g*2],   a, bb[0], bb[1]);
                    mma16816(acc_o[g*2+1], a, bb[2], bb[3]);
                }
            }
        }
        __syncthreads();
    }

    // epilogue: hi-only fp16 output, pitch 2048
    float il0 = 1.f / l0, il1 = 1.f / l1;
    size_t mrow0 = (size_t)b * SS + q0 + r0;
#pragma unroll
    for (int nt = 0; nt < 8; nt++) {
        int col = h*128 + wn*64 + nt*8 + (lane & 3)*2;
#pragma unroll
        for (int half = 0; half < 2; half++) {
            float oa = acc_o[nt][half*2]   * (half ? il1 : il0);
            float ob = acc_o[nt][half*2+1] * (half ? il1 : il0);
            size_t row = mrow0 + half*8;
            __half ha = __float2half(oa), hb = __float2half(ob);
            uint32_t hi = (uint32_t)(*(uint16_t*)&ha) | ((uint32_t)(*(uint16_t*)&hb) << 16);
            ((uint32_t*)(ats + row * 2048))[col >> 1] = hi;
        }
    }
}

// ---------------- host orchestration ----------------
static void convA(const float* in, __half* out, int R, int Rpad, int C, int inPitch)
{
    long long tot = (long long)Rpad * C;
    splitA_k<<<(int)((tot + 255) / 256), 256>>>(in, out, R, Rpad, C, inPitch);
}
static void convB(const float* in, __half* out, int R, int Rpad, int C, int inPitch)
{
    long long tot = (long long)Rpad * C;
    cvtB_k<<<(int)((tot + 255) / 256), 256>>>(in, out, R, Rpad, C, inPitch);
}
static void gemmx(const __half* A, const __half* B, float* C, int M, int N, int K, int KA)
{
    cudaFuncSetAttribute(gemm_tc, cudaFuncAttributeMaxDynamicSharedMemorySize, GEMM_SMEM);
    dim3 grid((N + 127) / 128, M / 128);
    gemm_tc<<<grid, 256, GEMM_SMEM>>>(A, B, C, M, N, K, KA);
}

extern "C" void kernel_launch(void* const* d_in, const int* in_sizes, int n_in,
                              void* d_out, int out_size)
{
    const float* x        = (const float*)d_in[0];
    const float* wq_down  = (const float*)d_in[1];
    const float* q_norm_w = (const float*)d_in[2];
    const float* wq_up    = (const float*)d_in[3];
    const float* wq_rope  = (const float*)d_in[4];
    const float* wkv_down = (const float*)d_in[5];
    const float* kv_norm_w= (const float*)d_in[6];
    const float* wkv_up   = (const float*)d_in[7];
    const float* wk_rope  = (const float*)d_in[8];
    const float* wo       = (const float*)d_in[9];
    float* out = (float*)d_out;

    float *dall, *qnp, *kvu;
    cudaGetSymbolAddress((void**)&dall, g_dall);
    cudaGetSymbolAddress((void**)&qnp,  g_qnp);
    cudaGetSymbolAddress((void**)&kvu,  g_kvup);

    __half *xs, *wdall, *qcs, *wuall, *kvcs, *wkvu, *ats, *wos, *qsp, *ksp, *vt;
    cudaGetSymbolAddress((void**)&xs,    g_xs);
    cudaGetSymbolAddress((void**)&wdall, g_wdall);
    cudaGetSymbolAddress((void**)&qcs,   g_qcs);
    cudaGetSymbolAddress((void**)&wuall, g_wuall);
    cudaGetSymbolAddress((void**)&kvcs,  g_kvcs);
    cudaGetSymbolAddress((void**)&wkvu,  g_wkvu);
    cudaGetSymbolAddress((void**)&ats,   g_ats);
    cudaGetSymbolAddress((void**)&wos,   g_wos);
    cudaGetSymbolAddress((void**)&qsp,   g_qsp);
    cudaGetSymbolAddress((void**)&ksp,   g_ksp);
    cudaGetSymbolAddress((void**)&vt,    g_vt);

    // ---- stage 1: merged down projection ----
    convA(x,        xs,    MT,  MT,  DIMM, DIMM);
    convB(wq_down,  wdall,                         QR,  QR,  DIMM, DIMM);
    convB(wkv_down, wdall + (size_t)QR*DIMM,       KVR, KVR, DIMM, DIMM);
    convB(wk_rope,  wdall + (size_t)(QR+KVR)*DIMM, DR,  128, DIMM, DIMM);
    gemmx(xs, wdall, dall, MT, NDOWN, DIMM, 2*DIMM);

    // ---- fused rmsnorm -> split fp16 activations; kr rope in dall ----
    rmsnorm_split_k<<<MT, 256>>>(dall,      q_norm_w,  qcs,  QR,  NDOWN);
    rmsnorm_split_k<<<MT, 256>>>(dall + QR, kv_norm_w, kvcs, KVR, NDOWN);
    rope_k<<<(MT*32 + 255)/256, 256>>>(dall, NDOWN, QR+KVR, 1, DR, MT*32);

    // ---- stage 2: merged up projections ----
    convB(wq_up,   wuall,                      NH*DN, NH*DN, QR, QR);
    convB(wq_rope, wuall + (size_t)(NH*DN)*QR, NH*DR, NH*DR, QR, QR);
    gemmx(qcs,  wuall, qnp, MT, NUP, QR, 2*QR);
    convB(wkv_up, wkvu, NH*(DN+DVV), NH*(DN+DVV), KVR, KVR);
    gemmx(kvcs, wkvu,  kvu, MT, NH*(DN+DVV), KVR, 2*KVR);

    // ---- fused q rope + split pack ----
    {
        long long tot = (long long)BB*NH*SS*160;
        rope_pack_q<<<(int)((tot + 255) / 256), 256>>>(qnp, qsp);
    }
    {
        long long tot = (long long)BB*NH*SS*192;
        pack_k<<<(int)((tot + 255) / 256), 256>>>(kvu, dall, ksp);
    }
    pack_v<<<dim3(SS/64, NH, BB), 256>>>(kvu, vt);

    // ---- HMMA flash attention -> hi-only fp16 output ----
    cudaFuncSetAttribute(attn_mma, cudaFuncAttributeMaxDynamicSharedMemorySize, ATT_SMEM);
    attn_mma<<<dim3(SS/64, NH, BB), 256, ATT_SMEM>>>(qsp, ksp, vt, ats);

    // ---- output projection (1-term fp16) ----
    convB(wo, wos, DIMM, DIMM, NH*DVV, NH*DVV);
    gemmx(ats, wos, out, MT, DIMM, NH*DVV, NH*DVV);
}

// round 9
// speedup vs baseline: 10.8096x; 1.0679x over previous
#include <cuda_runtime.h>
#include <cuda_fp16.h>
#include <math.h>
#include <stdint.h>

#define BB 2
#define SS 2048
#define DIMM 2048
#define NH 16
#define QR 1536
#define KVR 512
#define DN 128
#define DR 64
#define DVV 128
#define MT (BB*SS)   // 4096 token rows

#define NDOWN 2112   // qc(1536) | kvc(512) | kr(64)
#define NDOWNP 2176
#define NUP 3072     // qn(2048) | qp(1024)

// ---------------- fp32 scratch ----------------
__device__ float g_dall[MT*NDOWN];
__device__ float g_qnp [MT*NUP];
__device__ float g_kvup[MT*NH*(DN+DVV)];

// ---------------- fp16 scratch ----------------
__device__ __half g_xs   [MT    * 2*DIMM];
__device__ __half g_wdall[NDOWNP* DIMM];
__device__ __half g_qcs  [MT    * 2*QR];
__device__ __half g_wuall[NUP   * QR];
__device__ __half g_kvcs [MT    * 2*KVR];
__device__ __half g_wkvu [(NH*(DN+DVV)) * KVR];
__device__ __half g_ats  [MT    * (NH*DVV)];
__device__ __half g_wos  [DIMM  * (NH*DVV)];

// ---------------- attention packed operands ----------------
__device__ __half g_qsp[BB*NH*SS*384];     // [bh][s][Qh(192)|Ql(192)] (rope applied)
__device__ __half g_ksp[BB*NH*SS*192];     // [bh][s][Kh(192)]
__device__ __half g_vt [BB*NH*128*SS];     // [bh][d][s]

// ============================================================
// helpers
// ============================================================
__device__ __forceinline__ uint32_t smem_u32(const void* p){
    uint32_t a;
    asm("{ .reg .u64 t; cvta.to.shared.u64 t, %1; cvt.u32.u64 %0, t; }" : "=r"(a) : "l"(p));
    return a;
}
#define CPA16(dst, src) asm volatile("cp.async.cg.shared.global [%0], [%1], 16;" :: "r"(dst), "l"(src))
#define CPCOMMIT()      asm volatile("cp.async.commit_group;")
#define CPWAIT(n)       asm volatile("cp.async.wait_group %0;" :: "n"(n))

__device__ __forceinline__ void ldsm4(uint32_t* r, uint32_t addr){
    asm volatile("ldmatrix.sync.aligned.m8n8.x4.shared.b16 {%0,%1,%2,%3}, [%4];"
        : "=r"(r[0]), "=r"(r[1]), "=r"(r[2]), "=r"(r[3]) : "r"(addr));
}
__device__ __forceinline__ void mma16816(float* c, const uint32_t* a, uint32_t b0, uint32_t b1){
    asm volatile("mma.sync.aligned.m16n8k16.row.col.f32.f16.f16.f32 "
        "{%0,%1,%2,%3}, {%4,%5,%6,%7}, {%8,%9}, {%0,%1,%2,%3};"
        : "+f"(c[0]), "+f"(c[1]), "+f"(c[2]), "+f"(c[3])
        : "r"(a[0]), "r"(a[1]), "r"(a[2]), "r"(a[3]), "r"(b0), "r"(b1));
}
__device__ __forceinline__ uint32_t sw128(int row, int chunk){
    return (uint32_t)(row * 128 + ((chunk ^ (row & 7)) * 16));
}

// ============================================================
// conversions
// ============================================================
__global__ void splitA_k(const float* __restrict__ in, __half* __restrict__ out,
                         int R, int Rpad, int C, int inPitch)
{
    long long i = (long long)blockIdx.x * blockDim.x + threadIdx.x;
    long long tot = (long long)Rpad * C;
    if (i >= tot) return;
    int r = (int)(i / C), c = (int)(i % C);
    float x = (r < R) ? in[(size_t)r * inPitch + c] : 0.f;
    __half h = __float2half(x);
    __half l = __float2half(x - __half2float(h));
    size_t base = (size_t)r * 2 * C;
    out[base + c] = h; out[base + C + c] = l;
}
__global__ void cvtB_k(const float* __restrict__ in, __half* __restrict__ out,
                       int R, int Rpad, int C, int inPitch)
{
    long long i = (long long)blockIdx.x * blockDim.x + threadIdx.x;
    long long tot = (long long)Rpad * C;
    if (i >= tot) return;
    int r = (int)(i / C), c = (int)(i % C);
    float x = (r < R) ? in[(size_t)r * inPitch + c] : 0.f;
    out[(size_t)r * C + c] = __float2half(x);
}

// ============================================================
// fp16 GEMM (verified round-7/8 core)
// ============================================================
#define STAGES 3
#define STAGE_BYTES 32768
#define GEMM_SMEM (STAGES*STAGE_BYTES)

__global__ __launch_bounds__(256, 2) void gemm_tc(
    const __half* __restrict__ A, const __half* __restrict__ B,
    float* __restrict__ C, int M, int N, int K, int KA)
{
    extern __shared__ __align__(16) char smem[];
    const uint32_t sb = smem_u32(smem);
    const int m0 = blockIdx.y * 128, n0 = blockIdx.x * 128;
    const int tid = threadIdx.x, lane = tid & 31;
    const int wm = (tid >> 5) & 3;
    const int wn = tid >> 7;

    float acc[2][8][4];
#pragma unroll
    for (int i = 0; i < 2; i++)
#pragma unroll
        for (int j = 0; j < 8; j++)
#pragma unroll
            for (int q = 0; q < 4; q++) acc[i][j][q] = 0.f;

    const int KT  = KA >> 6;
    const int KTh = K >> 6;
    const __half* Ag0 = A + (size_t)m0 * KA;
    const __half* Bg0 = B + (size_t)n0 * K;

    const int fr = tid >> 3;
    const int fc = tid & 7;

    auto fill = [&](int j){
        uint32_t base = sb + (uint32_t)(j % STAGES) * STAGE_BYTES;
        int ka = j << 6;
        int kb = (j >= KTh ? j - KTh : j) << 6;
#pragma unroll
        for (int i = 0; i < 4; i++) {
            int r = fr + i * 32;
            CPA16(base + sw128(r, fc), Ag0 + (size_t)r * KA + ka + fc*8);
        }
#pragma unroll
        for (int i = 0; i < 4; i++) {
            int r = fr + i * 32;
            CPA16(base + 16384u + sw128(r, fc), Bg0 + (size_t)r * K + kb + fc*8);
        }
        CPCOMMIT();
    };

    fill(0);
    fill(1);

    const int a_row  = lane & 15;
    const int a_ch   = lane >> 4;
    const int b_nrow = (lane & 7) + ((lane & 16) ? 8 : 0);
    const int b_ch   = (lane >> 3) & 1;

    for (int kt = 0; kt < KT; kt++) {
        CPWAIT(1);
        __syncthreads();
        if (kt + 2 < KT) fill(kt + 2);
        else CPCOMMIT();

        uint32_t aT = sb + (uint32_t)(kt % STAGES) * STAGE_BYTES;
        uint32_t bT = aT + 16384u;
#pragma unroll
        for (int ks = 0; ks < 4; ks++) {
            uint32_t a[2][4];
#pragma unroll
            for (int i = 0; i < 2; i++)
                ldsm4(a[i], aT + sw128(wm*32 + i*16 + a_row, ks*2 + a_ch));
            uint32_t b[4][4];
#pragma unroll
            for (int g = 0; g < 4; g++)
                ldsm4(b[g], bT + sw128(wn*64 + g*16 + b_nrow, ks*2 + b_ch));
#pragma unroll
            for (int i = 0; i < 2; i++)
#pragma unroll
                for (int g = 0; g < 4; g++) {
                    mma16816(acc[i][2*g],   a[i], b[g][0], b[g][1]);
                    mma16816(acc[i][2*g+1], a[i], b[g][2], b[g][3]);
                }
        }
    }

    const int rb = m0 + wm*32;
    const int cb = n0 + wn*64;
#pragma unroll
    for (int i = 0; i < 2; i++)
#pragma unroll
        for (int j = 0; j < 8; j++) {
            int c = cb + j*8 + (lane & 3)*2;
            if (c < N) {
                int r = rb + i*16 + (lane >> 2);
                *(float2*)&C[(size_t)r * N + c]     = make_float2(acc[i][j][0], acc[i][j][1]);
                *(float2*)&C[(size_t)(r+8) * N + c] = make_float2(acc[i][j][2], acc[i][j][3]);
            }
        }
}

// ---------------- RMSNorm -> split fp16 [hi|lo] ----------------
__global__ void rmsnorm_split_k(const float* __restrict__ x, const float* __restrict__ w,
                                __half* __restrict__ out, int W, int pitch)
{
    const int row = blockIdx.x;
    const float* xr = x + (size_t)row * pitch;
    float ss = 0.f;
    for (int i = threadIdx.x; i < W; i += blockDim.x) { float v = xr[i]; ss += v * v; }
    __shared__ float red[32];
#pragma unroll
    for (int o = 16; o; o >>= 1) ss += __shfl_down_sync(0xffffffffu, ss, o);
    if ((threadIdx.x & 31) == 0) red[threadIdx.x >> 5] = ss;
    __syncthreads();
    if (threadIdx.x < 32) {
        float v = (threadIdx.x < (blockDim.x >> 5)) ? red[threadIdx.x] : 0.f;
#pragma unroll
        for (int o = 16; o; o >>= 1) v += __shfl_down_sync(0xffffffffu, v, o);
        if (threadIdx.x == 0) red[0] = rsqrtf(v / (float)W + 1e-6f);
    }
    __syncthreads();
    float r = red[0];
    __half* orow = out + (size_t)row * 2 * W;
    for (int i = threadIdx.x; i < W; i += blockDim.x) {
        float v = xr[i] * r * w[i];
        __half h = __float2half(v);
        __half l = __float2half(v - __half2float(h));
        orow[i] = h; orow[W + i] = l;
    }
}

// ---------------- RoPE on k_rope slice of dall ----------------
__global__ void rope_k(float* __restrict__ x, int pitch, int colOff,
                       int nheads, int d, int total_pairs)
{
    int idx = blockIdx.x * blockDim.x + threadIdx.x;
    if (idx >= total_pairs) return;
    int pairs_per_row = nheads * (d / 2);
    int row = idx / pairs_per_row;
    int p   = idx % pairs_per_row;
    int h = p / (d / 2);
    int i = p % (d / 2);
    int pos = row % SS;
    float inv = powf(10000.f, (-2.0f * (float)i) / (float)d);
    float ang = (float)pos * inv;
    float s, c;
    sincosf(ang, &s, &c);
    float* base = x + (size_t)row * pitch + colOff + h * d + 2 * i;
    float x1 = base[0], x2 = base[1];
    base[0] = x1 * c - x2 * s;
    base[1] = x1 * s + x2 * c;
}

// ---------------- fused Q rope + split pack ----------------
__global__ void rope_pack_q(const float* __restrict__ qnp, __half* __restrict__ out)
{
    long long idx = (long long)blockIdx.x * blockDim.x + threadIdx.x;
    if (idx >= (long long)BB*NH*SS*160) return;
    int j  = (int)(idx % 160);
    int s  = (int)((idx / 160) % SS);
    int bh = (int)(idx / (160LL*SS));
    int b = bh / NH, h = bh % NH;
    size_t m = (size_t)b * SS + s;
    const float scale = 1.0f / sqrtf(192.f);
    size_t base = ((size_t)bh * SS + s) * 384;
    if (j < 128) {
        float v = qnp[m * NUP + h*128 + j] * scale;
        __half hi = __float2half(v);
        __half lo = __float2half(v - __half2float(hi));
        out[base + j] = hi; out[base + 192 + j] = lo;
    } else {
        int p = j - 128;
        const float* src = qnp + m * NUP + 2048 + h*64 + 2*p;
        float x1 = src[0], x2 = src[1];
        float inv = powf(10000.f, (-2.0f * (float)p) / 64.f);
        float sn, cs;
        sincosf((float)s * inv, &sn, &cs);
        float o1 = (x1 * cs - x2 * sn) * scale;
        float o2 = (x1 * sn + x2 * cs) * scale;
        int d = 128 + 2*p;
        __half h1 = __float2half(o1), h2 = __float2half(o2);
        __half l1 = __float2half(o1 - __half2float(h1));
        __half l2 = __float2half(o2 - __half2float(h2));
        out[base + d] = h1;       out[base + d + 1] = h2;
        out[base + 192 + d] = l1; out[base + 192 + d + 1] = l2;
    }
}

__global__ void pack_k(const float* __restrict__ kv, const float* __restrict__ dall,
                       __half* __restrict__ out)
{
    long long idx = (long long)blockIdx.x * blockDim.x + threadIdx.x;
    if (idx >= (long long)BB*NH*SS*192) return;
    int d  = (int)(idx % 192);
    int s  = (int)((idx / 192) % SS);
    int bh = (int)(idx / (192LL*SS));
    int b = bh / NH, h = bh % NH;
    size_t m = (size_t)b * SS + s;
    float v = (d < 128) ? kv[m * (NH*256) + h*256 + d]
                        : dall[m * NDOWN + 2048 + (d-128)];
    out[((size_t)bh * SS + s) * 192 + d] = __float2half(v);
}

__global__ __launch_bounds__(256) void pack_v(const float* __restrict__ kv,
                                              __half* __restrict__ vt)
{
    __shared__ float vs[64][129];
    const int t = blockIdx.x, h = blockIdx.y, b = blockIdx.z;
    const int bh = b*NH + h;
    const int tid = threadIdx.x;
    for (int i = tid; i < 64*128; i += 256) {
        int r = i >> 7, d = i & 127;
        size_t m = (size_t)b * SS + t*64 + r;
        vs[r][d] = kv[m * (NH*256) + h*256 + 128 + d];
    }
    __syncthreads();
    uint32_t* out32 = (uint32_t*)vt;
    for (int i = tid; i < 128*32; i += 256) {
        int d = i >> 5, w = i & 31;
        int kk = w * 2;
        __half p0 = __float2half(vs[kk][d]);
        __half p1 = __float2half(vs[kk+1][d]);
        uint32_t packed = (uint32_t)(*(uint16_t*)&p0) | ((uint32_t)(*(uint16_t*)&p1) << 16);
        out32[((size_t)bh * 128 + d) * (SS/2) + t*32 + w] = packed;
    }
}

// ============================================================
// HMMA flash attention — Q resident in smem, 3 K-chunks/tile
// smem: [0,49152)        Q resident (6 chunks x 8KB: Qh c0..2, Ql c3..5)
//       [49152,73728)    K ring (3 slots x 8KB)
//       [73728,90112)    V (16KB)
//       [90112,107520)   P: 64 x 272B [Ph|Pl]
//       [107520,108032)  redmax   [108032,108544) redsum
// ============================================================
#define KBASE 49152u
#define VBASE 73728u
#define PBASE 90112u
#define ATT_SMEM 108544

__global__ __launch_bounds__(256, 2) void attn_mma(
    const __half* __restrict__ Qsp, const __half* __restrict__ Ksp,
    const __half* __restrict__ Vt, __half* __restrict__ ats)
{
    extern __shared__ __align__(16) char smem[];
    const uint32_t sb = smem_u32(smem);
    const int qt = (int)gridDim.x - 1 - (int)blockIdx.x;   // heavy CTAs first
    const int h = blockIdx.y, b = blockIdx.z;
    const int bh = b*NH + h;
    const int q0 = qt * 64;
    const int tid = threadIdx.x, lane = tid & 31;
    const int wm = (tid >> 5) & 3, wn = tid >> 7;

    const __half* Qg = Qsp + ((size_t)bh * SS + q0) * 384;
    const __half* Kg = Ksp + (size_t)bh * SS * 192;
    const __half* Vg = Vt  + (size_t)bh * 128 * SS;

    float* redmax = (float*)(smem + 107520);
    float* redsum = (float*)(smem + 108032);

    // ---- Q resident load (once): 6 chunks, one commit group ----
    {
        int r = tid >> 3, ch = tid & 7;
#pragma unroll
        for (int cq = 0; cq < 6; cq++) {
#pragma unroll
            for (int it = 0; it < 2; it++) {
                int rr = r + it*32;
                CPA16(sb + (uint32_t)cq*8192u + sw128(rr, ch),
                      Qg + (size_t)rr*384 + cq*64 + ch*8);
            }
        }
        CPCOMMIT();
    }

    float acc_o[8][4];
#pragma unroll
    for (int i = 0; i < 8; i++)
#pragma unroll
        for (int j = 0; j < 4; j++) acc_o[i][j] = 0.f;
    float m0 = -1e30f, m1 = -1e30f, l0 = 0.f, l1 = 0.f;

    const int a_row  = lane & 15;
    const int a_ch   = lane >> 4;
    const int b_nrow = (lane & 7) + ((lane & 16) ? 8 : 0);
    const int b_ch   = (lane >> 3) & 1;
    const int r0 = wm*16 + (lane >> 2);

    for (int t = 0; t <= qt; t++) {
        const int k0 = t * 64;
        // prologue: K chunks 0,1 (slots 0,1) then V; 3 commit groups
        {
            int r = tid >> 3, ch = tid & 7;
#pragma unroll
            for (int slot = 0; slot < 2; slot++) {
#pragma unroll
                for (int it = 0; it < 2; it++) {
                    int rr = r + it*32;
                    CPA16(sb + KBASE + (uint32_t)slot*8192u + sw128(rr, ch),
                          Kg + (size_t)(k0 + rr)*192 + slot*64 + ch*8);
                }
                CPCOMMIT();
            }
#pragma unroll
            for (int it = 0; it < 4; it++) {
                int i = tid + it*256;
                int d = i >> 3, vch = i & 7;
                CPA16(sb + VBASE + sw128(d, vch), Vg + (size_t)d*SS + t*64 + vch*8);
            }
            CPCOMMIT();
        }

        float acc_s[4][4];
#pragma unroll
        for (int i = 0; i < 4; i++)
#pragma unroll
            for (int j = 0; j < 4; j++) acc_s[i][j] = 0.f;

        // ---- S = (Qh+Ql) K^T over 3 K-chunks ----
#pragma unroll
        for (int c = 0; c < 3; c++) {
            if (c < 2) { CPWAIT(2); } else { CPWAIT(0); }
            __syncthreads();
            if (c == 0) {   // prefetch K chunk 2 -> slot 2
                int r = tid >> 3, ch = tid & 7;
#pragma unroll
                for (int it = 0; it < 2; it++) {
                    int rr = r + it*32;
                    CPA16(sb + KBASE + 2u*8192u + sw128(rr, ch),
                          Kg + (size_t)(k0 + rr)*192 + 2*64 + ch*8);
                }
                CPCOMMIT();
            }
            uint32_t kb = sb + KBASE + (uint32_t)c*8192u;
            uint32_t qh = sb + (uint32_t)c*8192u;
            uint32_t ql = sb + (uint32_t)(c+3)*8192u;
#pragma unroll
            for (int ks = 0; ks < 4; ks++) {
                uint32_t a0[4], a1[4];
                ldsm4(a0, qh + sw128(wm*16 + a_row, ks*2 + a_ch));
                ldsm4(a1, ql + sw128(wm*16 + a_row, ks*2 + a_ch));
#pragma unroll
                for (int g = 0; g < 2; g++) {
                    uint32_t bb[4];
                    ldsm4(bb, kb + sw128(wn*32 + g*16 + b_nrow, ks*2 + b_ch));
                    mma16816(acc_s[g*2],   a0, bb[0], bb[1]);
                    mma16816(acc_s[g*2+1], a0, bb[2], bb[3]);
                    mma16816(acc_s[g*2],   a1, bb[0], bb[1]);
                    mma16816(acc_s[g*2+1], a1, bb[2], bb[3]);
                }
            }
        }

        // ---- causal mask (diagonal tile only) ----
        if (t == qt) {
#pragma unroll
            for (int nt = 0; nt < 4; nt++) {
                int colb = wn*32 + nt*8 + (lane & 3)*2;
                if (colb     > r0)     acc_s[nt][0] = -1e30f;
                if (colb + 1 > r0)     acc_s[nt][1] = -1e30f;
                if (colb     > r0 + 8) acc_s[nt][2] = -1e30f;
                if (colb + 1 > r0 + 8) acc_s[nt][3] = -1e30f;
            }
        }

        // ---- online softmax ----
        float mx0 = -1e30f, mx1 = -1e30f;
#pragma unroll
        for (int nt = 0; nt < 4; nt++) {
            mx0 = fmaxf(mx0, fmaxf(acc_s[nt][0], acc_s[nt][1]));
            mx1 = fmaxf(mx1, fmaxf(acc_s[nt][2], acc_s[nt][3]));
        }
        mx0 = fmaxf(mx0, __shfl_xor_sync(0xffffffffu, mx0, 1));
        mx0 = fmaxf(mx0, __shfl_xor_sync(0xffffffffu, mx0, 2));
        mx1 = fmaxf(mx1, __shfl_xor_sync(0xffffffffu, mx1, 1));
        mx1 = fmaxf(mx1, __shfl_xor_sync(0xffffffffu, mx1, 2));
        if ((lane & 3) == 0) {
            redmax[wn*64 + r0]     = mx0;
            redmax[wn*64 + r0 + 8] = mx1;
        }
        __syncthreads();
        float tm0 = fmaxf(mx0, redmax[(wn^1)*64 + r0]);
        float tm1 = fmaxf(mx1, redmax[(wn^1)*64 + r0 + 8]);
        float nm0 = fmaxf(m0, tm0), nm1 = fmaxf(m1, tm1);
        float f0 = __expf(m0 - nm0), f1 = __expf(m1 - nm1);

        float s0 = 0.f, s1 = 0.f;
#pragma unroll
        for (int nt = 0; nt < 4; nt++) {
            acc_s[nt][0] = __expf(acc_s[nt][0] - nm0);
            acc_s[nt][1] = __expf(acc_s[nt][1] - nm0);
            acc_s[nt][2] = __expf(acc_s[nt][2] - nm1);
            acc_s[nt][3] = __expf(acc_s[nt][3] - nm1);
            s0 += acc_s[nt][0] + acc_s[nt][1];
            s1 += acc_s[nt][2] + acc_s[nt][3];
        }
        s0 += __shfl_xor_sync(0xffffffffu, s0, 1);
        s0 += __shfl_xor_sync(0xffffffffu, s0, 2);
        s1 += __shfl_xor_sync(0xffffffffu, s1, 1);
        s1 += __shfl_xor_sync(0xffffffffu, s1, 2);
        if ((lane & 3) == 0) {
            redsum[wn*64 + r0]     = s0;
            redsum[wn*64 + r0 + 8] = s1;
        }
        {
            char* P = smem + PBASE;
            int colb = wn*32 + (lane & 3)*2;
#pragma unroll
            for (int nt = 0; nt < 4; nt++) {
                int col = colb + nt*8;
#pragma unroll
                for (int half = 0; half < 2; half++) {
                    float pa = acc_s[nt][half*2], pb = acc_s[nt][half*2+1];
                    int row = r0 + half*8;
                    __half ha = __float2half(pa), hb = __float2half(pb);
                    __half la = __float2half(pa - __half2float(ha));
                    __half lb = __float2half(pb - __half2float(hb));
                    uint32_t hi = (uint32_t)(*(uint16_t*)&ha) | ((uint32_t)(*(uint16_t*)&hb) << 16);
                    uint32_t lo = (uint32_t)(*(uint16_t*)&la) | ((uint32_t)(*(uint16_t*)&lb) << 16);
                    uint32_t* base = (uint32_t*)(P + row*272 + col*2);
                    base[0]  = hi;
                    base[32] = lo;
                }
            }
        }
        __syncthreads();
        float ts0 = s0 + redsum[(wn^1)*64 + r0];
        float ts1 = s1 + redsum[(wn^1)*64 + r0 + 8];
        l0 = l0 * f0 + ts0;
        l1 = l1 * f1 + ts1;
        m0 = nm0; m1 = nm1;
#pragma unroll
        for (int nt = 0; nt < 8; nt++) {
            acc_o[nt][0] *= f0; acc_o[nt][1] *= f0;
            acc_o[nt][2] *= f1; acc_o[nt][3] *= f1;
        }

        // ---- PV: (Ph,Vh), (Pl,Vh) ----
#pragma unroll
        for (int pc = 0; pc < 2; pc++) {
            uint32_t pseg = (uint32_t)pc * 128u;
#pragma unroll
            for (int ks = 0; ks < 4; ks++) {
                uint32_t a[4];
                ldsm4(a, sb + PBASE + (uint32_t)((wm*16 + a_row)*272) + pseg
                         + (uint32_t)(ks*32 + a_ch*16));
#pragma unroll
                for (int g = 0; g < 4; g++) {
                    uint32_t bb[4];
                    ldsm4(bb, sb + VBASE + sw128(wn*64 + g*16 + b_nrow, ks*2 + b_ch));
                    mma16816(acc_o[g*2],   a, bb[0], bb[1]);
                    mma16816(acc_o[g*2+1], a, bb[2], bb[3]);
                }
            }
        }
        __syncthreads();
    }

    // epilogue: hi-only fp16 output
    float il0 = 1.f / l0, il1 = 1.f / l1;
    size_t mrow0 = (size_t)b * SS + q0 + r0;
#pragma unroll
    for (int nt = 0; nt < 8; nt++) {
        int col = h*128 + wn*64 + nt*8 + (lane & 3)*2;
#pragma unroll
        for (int half = 0; half < 2; half++) {
            float oa = acc_o[nt][half*2]   * (half ? il1 : il0);
            float ob = acc_o[nt][half*2+1] * (half ? il1 : il0);
            size_t row = mrow0 + half*8;
            __half ha = __float2half(oa), hb = __float2half(ob);
            uint32_t hi = (uint32_t)(*(uint16_t*)&ha) | ((uint32_t)(*(uint16_t*)&hb) << 16);
            ((uint32_t*)(ats + row * 2048))[col >> 1] = hi;
        }
    }
}

// ---------------- host orchestration ----------------
static void convA(const float* in, __half* out, int R, int Rpad, int C, int inPitch)
{
    long long tot = (long long)Rpad * C;
    splitA_k<<<(int)((tot + 255) / 256), 256>>>(in, out, R, Rpad, C, inPitch);
}
static void convB(const float* in, __half* out, int R, int Rpad, int C, int inPitch)
{
    long long tot = (long long)Rpad * C;
    cvtB_k<<<(int)((tot + 255) / 256), 256>>>(in, out, R, Rpad, C, inPitch);
}
static void gemmx(const __half* A, const __half* B, float* C, int M, int N, int K, int KA)
{
    cudaFuncSetAttribute(gemm_tc, cudaFuncAttributeMaxDynamicSharedMemorySize, GEMM_SMEM);
    dim3 grid((N + 127) / 128, M / 128);
    gemm_tc<<<grid, 256, GEMM_SMEM>>>(A, B, C, M, N, K, KA);
}

extern "C" void kernel_launch(void* const* d_in, const int* in_sizes, int n_in,
                              void* d_out, int out_size)
{
    const float* x        = (const float*)d_in[0];
    const float* wq_down  = (const float*)d_in[1];
    const float* q_norm_w = (const float*)d_in[2];
    const float* wq_up    = (const float*)d_in[3];
    const float* wq_rope  = (const float*)d_in[4];
    const float* wkv_down = (const float*)d_in[5];
    const float* kv_norm_w= (const float*)d_in[6];
    const float* wkv_up   = (const float*)d_in[7];
    const float* wk_rope  = (const float*)d_in[8];
    const float* wo       = (const float*)d_in[9];
    float* out = (float*)d_out;

    float *dall, *qnp, *kvu;
    cudaGetSymbolAddress((void**)&dall, g_dall);
    cudaGetSymbolAddress((void**)&qnp,  g_qnp);
    cudaGetSymbolAddress((void**)&kvu,  g_kvup);

    __half *xs, *wdall, *qcs, *wuall, *kvcs, *wkvu, *ats, *wos, *qsp, *ksp, *vt;
    cudaGetSymbolAddress((void**)&xs,    g_xs);
    cudaGetSymbolAddress((void**)&wdall, g_wdall);
    cudaGetSymbolAddress((void**)&qcs,   g_qcs);
    cudaGetSymbolAddress((void**)&wuall, g_wuall);
    cudaGetSymbolAddress((void**)&kvcs,  g_kvcs);
    cudaGetSymbolAddress((void**)&wkvu,  g_wkvu);
    cudaGetSymbolAddress((void**)&ats,   g_ats);
    cudaGetSymbolAddress((void**)&wos,   g_wos);
    cudaGetSymbolAddress((void**)&qsp,   g_qsp);
    cudaGetSymbolAddress((void**)&ksp,   g_ksp);
    cudaGetSymbolAddress((void**)&vt,    g_vt);

    // ---- stage 1: merged down projection ----
    convA(x,        xs,    MT,  MT,  DIMM, DIMM);
    convB(wq_down,  wdall,                         QR,  QR,  DIMM, DIMM);
    convB(wkv_down, wdall + (size_t)QR*DIMM,       KVR, KVR, DIMM, DIMM);
    convB(wk_rope,  wdall + (size_t)(QR+KVR)*DIMM, DR,  128, DIMM, DIMM);
    gemmx(xs, wdall, dall, MT, NDOWN, DIMM, 2*DIMM);

    // ---- fused rmsnorm -> split fp16; kr rope ----
    rmsnorm_split_k<<<MT, 256>>>(dall,      q_norm_w,  qcs,  QR,  NDOWN);
    rmsnorm_split_k<<<MT, 256>>>(dall + QR, kv_norm_w, kvcs, KVR, NDOWN);
    rope_k<<<(MT*32 + 255)/256, 256>>>(dall, NDOWN, QR+KVR, 1, DR, MT*32);

    // ---- stage 2: merged up projections ----
    convB(wq_up,   wuall,                      NH*DN, NH*DN, QR, QR);
    convB(wq_rope, wuall + (size_t)(NH*DN)*QR, NH*DR, NH*DR, QR, QR);
    gemmx(qcs,  wuall, qnp, MT, NUP, QR, 2*QR);
    convB(wkv_up, wkvu, NH*(DN+DVV), NH*(DN+DVV), KVR, KVR);
    gemmx(kvcs, wkvu,  kvu, MT, NH*(DN+DVV), KVR, 2*KVR);

    // ---- fused q rope + split pack ----
    {
        long long tot = (long long)BB*NH*SS*160;
        rope_pack_q<<<(int)((tot + 255) / 256), 256>>>(qnp, qsp);
    }
    {
        long long tot = (long long)BB*NH*SS*192;
        pack_k<<<(int)((tot + 255) / 256), 256>>>(kvu, dall, ksp);
    }
    pack_v<<<dim3(SS/64, NH, BB), 256>>>(kvu, vt);

    // ---- HMMA flash attention (Q resident) ----
    cudaFuncSetAttribute(attn_mma, cudaFuncAttributeMaxDynamicSharedMemorySize, ATT_SMEM);
    attn_mma<<<dim3(SS/64, NH, BB), 256, ATT_SMEM>>>(qsp, ksp, vt, ats);

    // ---- output projection (1-term fp16) ----
    convB(wo, wos, DIMM, DIMM, NH*DVV, NH*DVV);
    gemmx(ats, wos, out, MT, DIMM, NH*DVV, NH*DVV);
}

// round 10
// speedup vs baseline: 11.9360x; 1.1042x over previous
#include <cuda_runtime.h>
#include <cuda_fp16.h>
#include <math.h>
#include <stdint.h>

#define BB 2
#define SS 2048
#define DIMM 2048
#define NH 16
#define QR 1536
#define KVR 512
#define DN 128
#define DR 64
#define DVV 128
#define MT (BB*SS)   // 4096 token rows

#define NDOWN 2112   // qc(1536) | kvc(512) | kr(64)
#define NDOWNP 2176
#define NUP 3072     // qn(2048) | qp(1024)

// ---------------- fp32 scratch ----------------
__device__ float g_dall[MT*NDOWN];
__device__ float g_qnp [MT*NUP];
__device__ float g_kvup[MT*NH*(DN+DVV)];

// ---------------- fp16 scratch ----------------
__device__ __half g_xs   [MT    * 2*DIMM];
__device__ __half g_wdall[NDOWNP* DIMM];
__device__ __half g_qcs  [MT    * 2*QR];
__device__ __half g_wuall[NUP   * QR];
__device__ __half g_kvcs [MT    * 2*KVR];
__device__ __half g_wkvu [(NH*(DN+DVV)) * KVR];
__device__ __half g_ats  [MT    * (NH*DVV)];
__device__ __half g_wos  [DIMM  * (NH*DVV)];

// ---------------- attention packed operands ----------------
__device__ __half g_qsp[BB*NH*SS*384];     // [bh][s][Qh(192)|Ql(192)]
__device__ __half g_ksp[BB*NH*SS*192];     // [bh][s][Kh(192)]
__device__ __half g_vt [BB*NH*128*SS];     // [bh][d][s]

// ============================================================
// helpers
// ============================================================
__device__ __forceinline__ uint32_t smem_u32(const void* p){
    uint32_t a;
    asm("{ .reg .u64 t; cvta.to.shared.u64 t, %1; cvt.u32.u64 %0, t; }" : "=r"(a) : "l"(p));
    return a;
}
#define CPA16(dst, src) asm volatile("cp.async.cg.shared.global [%0], [%1], 16;" :: "r"(dst), "l"(src))
#define CPCOMMIT()      asm volatile("cp.async.commit_group;")
#define CPWAIT(n)       asm volatile("cp.async.wait_group %0;" :: "n"(n))

__device__ __forceinline__ void ldsm4(uint32_t* r, uint32_t addr){
    asm volatile("ldmatrix.sync.aligned.m8n8.x4.shared.b16 {%0,%1,%2,%3}, [%4];"
        : "=r"(r[0]), "=r"(r[1]), "=r"(r[2]), "=r"(r[3]) : "r"(addr));
}
__device__ __forceinline__ void mma16816(float* c, const uint32_t* a, uint32_t b0, uint32_t b1){
    asm volatile("mma.sync.aligned.m16n8k16.row.col.f32.f16.f16.f32 "
        "{%0,%1,%2,%3}, {%4,%5,%6,%7}, {%8,%9}, {%0,%1,%2,%3};"
        : "+f"(c[0]), "+f"(c[1]), "+f"(c[2]), "+f"(c[3])
        : "r"(a[0]), "r"(a[1]), "r"(a[2]), "r"(a[3]), "r"(b0), "r"(b1));
}
__device__ __forceinline__ uint32_t sw128(int row, int chunk){
    return (uint32_t)(row * 128 + ((chunk ^ (row & 7)) * 16));
}

// split 8 fp32 -> hi/lo halves
__device__ __forceinline__ void split8(const float* v, __half* hi, __half* lo){
#pragma unroll
    for (int k = 0; k < 8; k++) {
        __half h = __float2half(v[k]);
        hi[k] = h;
        lo[k] = __float2half(v[k] - __half2float(h));
    }
}

// ============================================================
// vectorized conversions (8 elems/thread)
// ============================================================
__global__ void splitA_k(const float* __restrict__ in, __half* __restrict__ out,
                         int R, int Rpad, int C, int inPitch)
{
    long long i = (long long)blockIdx.x * blockDim.x + threadIdx.x;
    int C8 = C >> 3;
    long long tot = (long long)Rpad * C8;
    if (i >= tot) return;
    int r = (int)(i / C8), c = ((int)(i % C8)) << 3;
    float v[8];
    if (r < R) {
        float4 a = *(const float4*)&in[(size_t)r * inPitch + c];
        float4 b = *(const float4*)&in[(size_t)r * inPitch + c + 4];
        v[0]=a.x; v[1]=a.y; v[2]=a.z; v[3]=a.w; v[4]=b.x; v[5]=b.y; v[6]=b.z; v[7]=b.w;
    } else {
#pragma unroll
        for (int k = 0; k < 8; k++) v[k] = 0.f;
    }
    __align__(16) __half hi[8], lo[8];
    split8(v, hi, lo);
    size_t base = (size_t)r * 2 * C;
    *(uint4*)&out[base + c]     = *(uint4*)hi;
    *(uint4*)&out[base + C + c] = *(uint4*)lo;
}

__global__ void cvtB_k(const float* __restrict__ in, __half* __restrict__ out,
                       int R, int Rpad, int C, int inPitch)
{
    long long i = (long long)blockIdx.x * blockDim.x + threadIdx.x;
    int C8 = C >> 3;
    long long tot = (long long)Rpad * C8;
    if (i >= tot) return;
    int r = (int)(i / C8), c = ((int)(i % C8)) << 3;
    __align__(16) __half h[8];
    if (r < R) {
        float4 a = *(const float4*)&in[(size_t)r * inPitch + c];
        float4 b = *(const float4*)&in[(size_t)r * inPitch + c + 4];
        h[0]=__float2half(a.x); h[1]=__float2half(a.y); h[2]=__float2half(a.z); h[3]=__float2half(a.w);
        h[4]=__float2half(b.x); h[5]=__float2half(b.y); h[6]=__float2half(b.z); h[7]=__float2half(b.w);
    } else {
#pragma unroll
        for (int k = 0; k < 8; k++) h[k] = __float2half(0.f);
    }
    *(uint4*)&out[(size_t)r * C + c] = *(uint4*)h;
}

// ============================================================
// fp16 GEMM (verified core, unchanged)
// ============================================================
#define STAGES 3
#define STAGE_BYTES 32768
#define GEMM_SMEM (STAGES*STAGE_BYTES)

__global__ __launch_bounds__(256, 2) void gemm_tc(
    const __half* __restrict__ A, const __half* __restrict__ B,
    float* __restrict__ C, int M, int N, int K, int KA)
{
    extern __shared__ __align__(16) char smem[];
    const uint32_t sb = smem_u32(smem);
    const int m0 = blockIdx.y * 128, n0 = blockIdx.x * 128;
    const int tid = threadIdx.x, lane = tid & 31;
    const int wm = (tid >> 5) & 3;
    const int wn = tid >> 7;

    float acc[2][8][4];
#pragma unroll
    for (int i = 0; i < 2; i++)
#pragma unroll
        for (int j = 0; j < 8; j++)
#pragma unroll
            for (int q = 0; q < 4; q++) acc[i][j][q] = 0.f;

    const int KT  = KA >> 6;
    const int KTh = K >> 6;
    const __half* Ag0 = A + (size_t)m0 * KA;
    const __half* Bg0 = B + (size_t)n0 * K;

    const int fr = tid >> 3;
    const int fc = tid & 7;

    auto fill = [&](int j){
        uint32_t base = sb + (uint32_t)(j % STAGES) * STAGE_BYTES;
        int ka = j << 6;
        int kb = (j >= KTh ? j - KTh : j) << 6;
#pragma unroll
        for (int i = 0; i < 4; i++) {
            int r = fr + i * 32;
            CPA16(base + sw128(r, fc), Ag0 + (size_t)r * KA + ka + fc*8);
        }
#pragma unroll
        for (int i = 0; i < 4; i++) {
            int r = fr + i * 32;
            CPA16(base + 16384u + sw128(r, fc), Bg0 + (size_t)r * K + kb + fc*8);
        }
        CPCOMMIT();
    };

    fill(0);
    fill(1);

    const int a_row  = lane & 15;
    const int a_ch   = lane >> 4;
    const int b_nrow = (lane & 7) + ((lane & 16) ? 8 : 0);
    const int b_ch   = (lane >> 3) & 1;

    for (int kt = 0; kt < KT; kt++) {
        CPWAIT(1);
        __syncthreads();
        if (kt + 2 < KT) fill(kt + 2);
        else CPCOMMIT();

        uint32_t aT = sb + (uint32_t)(kt % STAGES) * STAGE_BYTES;
        uint32_t bT = aT + 16384u;
#pragma unroll
        for (int ks = 0; ks < 4; ks++) {
            uint32_t a[2][4];
#pragma unroll
            for (int i = 0; i < 2; i++)
                ldsm4(a[i], aT + sw128(wm*32 + i*16 + a_row, ks*2 + a_ch));
            uint32_t b[4][4];
#pragma unroll
            for (int g = 0; g < 4; g++)
                ldsm4(b[g], bT + sw128(wn*64 + g*16 + b_nrow, ks*2 + b_ch));
#pragma unroll
            for (int i = 0; i < 2; i++)
#pragma unroll
                for (int g = 0; g < 4; g++) {
                    mma16816(acc[i][2*g],   a[i], b[g][0], b[g][1]);
                    mma16816(acc[i][2*g+1], a[i], b[g][2], b[g][3]);
                }
        }
    }

    const int rb = m0 + wm*32;
    const int cb = n0 + wn*64;
#pragma unroll
    for (int i = 0; i < 2; i++)
#pragma unroll
        for (int j = 0; j < 8; j++) {
            int c = cb + j*8 + (lane & 3)*2;
            if (c < N) {
                int r = rb + i*16 + (lane >> 2);
                *(float2*)&C[(size_t)r * N + c]     = make_float2(acc[i][j][0], acc[i][j][1]);
                *(float2*)&C[(size_t)(r+8) * N + c] = make_float2(acc[i][j][2], acc[i][j][3]);
            }
        }
}

// ---------------- RMSNorm -> split fp16 [hi|lo] (vectorized) ----------------
__global__ void rmsnorm_split_k(const float* __restrict__ x, const float* __restrict__ w,
                                __half* __restrict__ out, int W, int pitch)
{
    const int row = blockIdx.x;
    const float* xr = x + (size_t)row * pitch;
    const float4* x4 = (const float4*)xr;
    float ss = 0.f;
    int W4 = W >> 2;
    for (int i = threadIdx.x; i < W4; i += blockDim.x) {
        float4 v = x4[i];
        ss += v.x*v.x + v.y*v.y + v.z*v.z + v.w*v.w;
    }
    __shared__ float red[32];
#pragma unroll
    for (int o = 16; o; o >>= 1) ss += __shfl_down_sync(0xffffffffu, ss, o);
    if ((threadIdx.x & 31) == 0) red[threadIdx.x >> 5] = ss;
    __syncthreads();
    if (threadIdx.x < 32) {
        float v = (threadIdx.x < (blockDim.x >> 5)) ? red[threadIdx.x] : 0.f;
#pragma unroll
        for (int o = 16; o; o >>= 1) v += __shfl_down_sync(0xffffffffu, v, o);
        if (threadIdx.x == 0) red[0] = rsqrtf(v / (float)W + 1e-6f);
    }
    __syncthreads();
    float r = red[0];
    __half* orow = out + (size_t)row * 2 * W;
    const float4* w4 = (const float4*)w;
    int W8 = W >> 3;
    for (int i8 = threadIdx.x; i8 < W8; i8 += blockDim.x) {
        float4 a = x4[i8*2], b = x4[i8*2+1];
        float4 wa = w4[i8*2], wb = w4[i8*2+1];
        float v[8] = { a.x*r*wa.x, a.y*r*wa.y, a.z*r*wa.z, a.w*r*wa.w,
                       b.x*r*wb.x, b.y*r*wb.y, b.z*r*wb.z, b.w*r*wb.w };
        __align__(16) __half hi[8], lo[8];
        split8(v, hi, lo);
        *(uint4*)&orow[i8*8]     = *(uint4*)hi;
        *(uint4*)&orow[W + i8*8] = *(uint4*)lo;
    }
}

// ---------------- RoPE on k_rope slice of dall ----------------
__global__ void rope_k(float* __restrict__ x, int pitch, int colOff,
                       int nheads, int d, int total_pairs)
{
    int idx = blockIdx.x * blockDim.x + threadIdx.x;
    if (idx >= total_pairs) return;
    int pairs_per_row = nheads * (d / 2);
    int row = idx / pairs_per_row;
    int p   = idx % pairs_per_row;
    int h = p / (d / 2);
    int i = p % (d / 2);
    int pos = row % SS;
    float inv = powf(10000.f, (-2.0f * (float)i) / (float)d);
    float ang = (float)pos * inv;
    float s, c;
    sincosf(ang, &s, &c);
    float* base = x + (size_t)row * pitch + colOff + h * d + 2 * i;
    float x1 = base[0], x2 = base[1];
    base[0] = x1 * c - x2 * s;
    base[1] = x1 * s + x2 * c;
}

// ---------------- fused Q rope + split pack (vectorized: 8 dims/thread) ----
__global__ void rope_pack_q(const float* __restrict__ qnp, __half* __restrict__ out)
{
    long long idx = (long long)blockIdx.x * blockDim.x + threadIdx.x;
    if (idx >= (long long)BB*NH*SS*24) return;
    int c8 = (int)(idx % 24);
    int s  = (int)((idx / 24) % SS);
    int bh = (int)(idx / (24LL*SS));
    int b = bh / NH, h = bh % NH;
    size_t m = (size_t)b * SS + s;
    const float scale = 0.072168783648703220563f;   // 1/sqrt(192)
    size_t base = ((size_t)bh * SS + s) * 384;
    int d = c8 * 8;
    float v[8];
    if (c8 < 16) {
        const float4* src = (const float4*)&qnp[m * NUP + h*128 + d];
        float4 a = src[0], bb = src[1];
        v[0]=a.x; v[1]=a.y; v[2]=a.z; v[3]=a.w; v[4]=bb.x; v[5]=bb.y; v[6]=bb.z; v[7]=bb.w;
#pragma unroll
        for (int k = 0; k < 8; k++) v[k] *= scale;
    } else {
        int r8 = c8 - 16;                            // 0..7, pairs r8*4 .. r8*4+3
        const float4* src = (const float4*)&qnp[m * NUP + 2048 + h*64 + r8*8];
        float4 a = src[0], bb = src[1];
        float t[8] = {a.x, a.y, a.z, a.w, bb.x, bb.y, bb.z, bb.w};
#pragma unroll
        for (int pi = 0; pi < 4; pi++) {
            int p = r8*4 + pi;
            float inv = powf(10000.f, (-2.0f * (float)p) / 64.f);
            float sn, cs;
            sincosf((float)s * inv, &sn, &cs);
            float x1 = t[2*pi], x2 = t[2*pi+1];
            v[2*pi]   = (x1 * cs - x2 * sn) * scale;
            v[2*pi+1] = (x1 * sn + x2 * cs) * scale;
        }
    }
    __align__(16) __half hi[8], lo[8];
    split8(v, hi, lo);
    *(uint4*)&out[base + d]       = *(uint4*)hi;
    *(uint4*)&out[base + 192 + d] = *(uint4*)lo;
}

// ---------------- pack K (vectorized: 8 dims/thread) ----------------
__global__ void pack_k(const float* __restrict__ kv, const float* __restrict__ dall,
                       __half* __restrict__ out)
{
    long long idx = (long long)blockIdx.x * blockDim.x + threadIdx.x;
    if (idx >= (long long)BB*NH*SS*24) return;
    int c8 = (int)(idx % 24);
    int s  = (int)((idx / 24) % SS);
    int bh = (int)(idx / (24LL*SS));
    int b = bh / NH, h = bh % NH;
    size_t m = (size_t)b * SS + s;
    int d = c8 * 8;
    const float* src = (d < 128) ? &kv[m * (NH*256) + h*256 + d]
                                 : &dall[m * NDOWN + 2048 + (d - 128)];
    float4 a = ((const float4*)src)[0], bb = ((const float4*)src)[1];
    __align__(16) __half hh[8];
    hh[0]=__float2half(a.x);  hh[1]=__float2half(a.y);  hh[2]=__float2half(a.z);  hh[3]=__float2half(a.w);
    hh[4]=__float2half(bb.x); hh[5]=__float2half(bb.y); hh[6]=__float2half(bb.z); hh[7]=__float2half(bb.w);
    *(uint4*)&out[((size_t)bh * SS + s) * 192 + d] = *(uint4*)hh;
}

// ---------------- pack V transpose (vectorized writes) ----------------
__global__ __launch_bounds__(256) void pack_v(const float* __restrict__ kv,
                                              __half* __restrict__ vt)
{
    __shared__ float vs[64][129];
    const int t = blockIdx.x, h = blockIdx.y, b = blockIdx.z;
    const int bh = b*NH + h;
    const int tid = threadIdx.x;
    for (int i = tid; i < 64*32; i += 256) {
        int r = i >> 5, d4 = (i & 31) * 4;
        size_t m = (size_t)b * SS + t*64 + r;
        float4 v = *(const float4*)&kv[m * (NH*256) + h*256 + 128 + d4];
        vs[r][d4] = v.x; vs[r][d4+1] = v.y; vs[r][d4+2] = v.z; vs[r][d4+3] = v.w;
    }
    __syncthreads();
    for (int i = tid; i < 128*8; i += 256) {
        int d = i >> 3, w8 = i & 7;
        int kk0 = w8 * 8;
        __align__(16) __half p[8];
#pragma unroll
        for (int k = 0; k < 8; k++) p[k] = __float2half(vs[kk0 + k][d]);
        *(uint4*)&vt[((size_t)bh * 128 + d) * SS + t*64 + kk0] = *(uint4*)p;
    }
}

// ============================================================
// HMMA flash attention — Q resident (verified round-9 core)
// ============================================================
#define KBASE 49152u
#define VBASE 73728u
#define PBASE 90112u
#define ATT_SMEM 108544

__global__ __launch_bounds__(256, 2) void attn_mma(
    const __half* __restrict__ Qsp, const __half* __restrict__ Ksp,
    const __half* __restrict__ Vt, __half* __restrict__ ats)
{
    extern __shared__ __align__(16) char smem[];
    const uint32_t sb = smem_u32(smem);
    const int qt = (int)gridDim.x - 1 - (int)blockIdx.x;
    const int h = blockIdx.y, b = blockIdx.z;
    const int bh = b*NH + h;
    const int q0 = qt * 64;
    const int tid = threadIdx.x, lane = tid & 31;
    const int wm = (tid >> 5) & 3, wn = tid >> 7;

    const __half* Qg = Qsp + ((size_t)bh * SS + q0) * 384;
    const __half* Kg = Ksp + (size_t)bh * SS * 192;
    const __half* Vg = Vt  + (size_t)bh * 128 * SS;

    float* redmax = (float*)(smem + 107520);
    float* redsum = (float*)(smem + 108032);

    {
        int r = tid >> 3, ch = tid & 7;
#pragma unroll
        for (int cq = 0; cq < 6; cq++) {
#pragma unroll
            for (int it = 0; it < 2; it++) {
                int rr = r + it*32;
                CPA16(sb + (uint32_t)cq*8192u + sw128(rr, ch),
                      Qg + (size_t)rr*384 + cq*64 + ch*8);
            }
        }
        CPCOMMIT();
    }

    float acc_o[8][4];
#pragma unroll
    for (int i = 0; i < 8; i++)
#pragma unroll
        for (int j = 0; j < 4; j++) acc_o[i][j] = 0.f;
    float m0 = -1e30f, m1 = -1e30f, l0 = 0.f, l1 = 0.f;

    const int a_row  = lane & 15;
    const int a_ch   = lane >> 4;
    const int b_nrow = (lane & 7) + ((lane & 16) ? 8 : 0);
    const int b_ch   = (lane >> 3) & 1;
    const int r0 = wm*16 + (lane >> 2);

    for (int t = 0; t <= qt; t++) {
        const int k0 = t * 64;
        {
            int r = tid >> 3, ch = tid & 7;
#pragma unroll
            for (int slot = 0; slot < 2; slot++) {
#pragma unroll
                for (int it = 0; it < 2; it++) {
                    int rr = r + it*32;
                    CPA16(sb + KBASE + (uint32_t)slot*8192u + sw128(rr, ch),
                          Kg + (size_t)(k0 + rr)*192 + slot*64 + ch*8);
                }
                CPCOMMIT();
            }
#pragma unroll
            for (int it = 0; it < 4; it++) {
                int i = tid + it*256;
                int d = i >> 3, vch = i & 7;
                CPA16(sb + VBASE + sw128(d, vch), Vg + (size_t)d*SS + t*64 + vch*8);
            }
            CPCOMMIT();
        }

        float acc_s[4][4];
#pragma unroll
        for (int i = 0; i < 4; i++)
#pragma unroll
            for (int j = 0; j < 4; j++) acc_s[i][j] = 0.f;

#pragma unroll
        for (int c = 0; c < 3; c++) {
            if (c < 2) { CPWAIT(2); } else { CPWAIT(0); }
            __syncthreads();
            if (c == 0) {
                int r = tid >> 3, ch = tid & 7;
#pragma unroll
                for (int it = 0; it < 2; it++) {
                    int rr = r + it*32;
                    CPA16(sb + KBASE + 2u*8192u + sw128(rr, ch),
                          Kg + (size_t)(k0 + rr)*192 + 2*64 + ch*8);
                }
                CPCOMMIT();
            }
            uint32_t kb = sb + KBASE + (uint32_t)c*8192u;
            uint32_t qh = sb + (uint32_t)c*8192u;
            uint32_t ql = sb + (uint32_t)(c+3)*8192u;
#pragma unroll
            for (int ks = 0; ks < 4; ks++) {
                uint32_t a0[4], a1[4];
                ldsm4(a0, qh + sw128(wm*16 + a_row, ks*2 + a_ch));
                ldsm4(a1, ql + sw128(wm*16 + a_row, ks*2 + a_ch));
#pragma unroll
                for (int g = 0; g < 2; g++) {
                    uint32_t bb[4];
                    ldsm4(bb, kb + sw128(wn*32 + g*16 + b_nrow, ks*2 + b_ch));
                    mma16816(acc_s[g*2],   a0, bb[0], bb[1]);
                    mma16816(acc_s[g*2+1], a0, bb[2], bb[3]);
                    mma16816(acc_s[g*2],   a1, bb[0], bb[1]);
                    mma16816(acc_s[g*2+1], a1, bb[2], bb[3]);
                }
            }
        }

        if (t == qt) {
#pragma unroll
            for (int nt = 0; nt < 4; nt++) {
                int colb = wn*32 + nt*8 + (lane & 3)*2;
                if (colb     > r0)     acc_s[nt][0] = -1e30f;
                if (colb + 1 > r0)     acc_s[nt][1] = -1e30f;
                if (colb     > r0 + 8) acc_s[nt][2] = -1e30f;
                if (colb + 1 > r0 + 8) acc_s[nt][3] = -1e30f;
            }
        }

        float mx0 = -1e30f, mx1 = -1e30f;
#pragma unroll
        for (int nt = 0; nt < 4; nt++) {
            mx0 = fmaxf(mx0, fmaxf(acc_s[nt][0], acc_s[nt][1]));
            mx1 = fmaxf(mx1, fmaxf(acc_s[nt][2], acc_s[nt][3]));
        }
        mx0 = fmaxf(mx0, __shfl_xor_sync(0xffffffffu, mx0, 1));
        mx0 = fmaxf(mx0, __shfl_xor_sync(0xffffffffu, mx0, 2));
        mx1 = fmaxf(mx1, __shfl_xor_sync(0xffffffffu, mx1, 1));
        mx1 = fmaxf(mx1, __shfl_xor_sync(0xffffffffu, mx1, 2));
        if ((lane & 3) == 0) {
            redmax[wn*64 + r0]     = mx0;
            redmax[wn*64 + r0 + 8] = mx1;
        }
        __syncthreads();
        float tm0 = fmaxf(mx0, redmax[(wn^1)*64 + r0]);
        float tm1 = fmaxf(mx1, redmax[(wn^1)*64 + r0 + 8]);
        float nm0 = fmaxf(m0, tm0), nm1 = fmaxf(m1, tm1);
        float f0 = __expf(m0 - nm0), f1 = __expf(m1 - nm1);

        float s0 = 0.f, s1 = 0.f;
#pragma unroll
        for (int nt = 0; nt < 4; nt++) {
            acc_s[nt][0] = __expf(acc_s[nt][0] - nm0);
            acc_s[nt][1] = __expf(acc_s[nt][1] - nm0);
            acc_s[nt][2] = __expf(acc_s[nt][2] - nm1);
            acc_s[nt][3] = __expf(acc_s[nt][3] - nm1);
            s0 += acc_s[nt][0] + acc_s[nt][1];
            s1 += acc_s[nt][2] + acc_s[nt][3];
        }
        s0 += __shfl_xor_sync(0xffffffffu, s0, 1);
        s0 += __shfl_xor_sync(0xffffffffu, s0, 2);
        s1 += __shfl_xor_sync(0xffffffffu, s1, 1);
        s1 += __shfl_xor_sync(0xffffffffu, s1, 2);
        if ((lane & 3) == 0) {
            redsum[wn*64 + r0]     = s0;
            redsum[wn*64 + r0 + 8] = s1;
        }
        {
            char* P = smem + PBASE;
            int colb = wn*32 + (lane & 3)*2;
#pragma unroll
            for (int nt = 0; nt < 4; nt++) {
                int col = colb + nt*8;
#pragma unroll
                for (int half = 0; half < 2; half++) {
                    float pa = acc_s[nt][half*2], pb = acc_s[nt][half*2+1];
                    int row = r0 + half*8;
                    __half ha = __float2half(pa), hb = __float2half(pb);
                    __half la = __float2half(pa - __half2float(ha));
                    __half lb = __float2half(pb - __half2float(hb));
                    uint32_t hi = (uint32_t)(*(uint16_t*)&ha) | ((uint32_t)(*(uint16_t*)&hb) << 16);
                    uint32_t lo = (uint32_t)(*(uint16_t*)&la) | ((uint32_t)(*(uint16_t*)&lb) << 16);
                    uint32_t* base = (uint32_t*)(P + row*272 + col*2);
                    base[0]  = hi;
                    base[32] = lo;
                }
            }
        }
        __syncthreads();
        float ts0 = s0 + redsum[(wn^1)*64 + r0];
        float ts1 = s1 + redsum[(wn^1)*64 + r0 + 8];
        l0 = l0 * f0 + ts0;
        l1 = l1 * f1 + ts1;
        m0 = nm0; m1 = nm1;
#pragma unroll
        for (int nt = 0; nt < 8; nt++) {
            acc_o[nt][0] *= f0; acc_o[nt][1] *= f0;
            acc_o[nt][2] *= f1; acc_o[nt][3] *= f1;
        }

#pragma unroll
        for (int pc = 0; pc < 2; pc++) {
            uint32_t pseg = (uint32_t)pc * 128u;
#pragma unroll
            for (int ks = 0; ks < 4; ks++) {
                uint32_t a[4];
                ldsm4(a, sb + PBASE + (uint32_t)((wm*16 + a_row)*272) + pseg
                         + (uint32_t)(ks*32 + a_ch*16));
#pragma unroll
                for (int g = 0; g < 4; g++) {
                    uint32_t bb[4];
                    ldsm4(bb, sb + VBASE + sw128(wn*64 + g*16 + b_nrow, ks*2 + b_ch));
                    mma16816(acc_o[g*2],   a, bb[0], bb[1]);
                    mma16816(acc_o[g*2+1], a, bb[2], bb[3]);
                }
            }
        }
        __syncthreads();
    }

    float il0 = 1.f / l0, il1 = 1.f / l1;
    size_t mrow0 = (size_t)b * SS + q0 + r0;
#pragma unroll
    for (int nt = 0; nt < 8; nt++) {
        int col = h*128 + wn*64 + nt*8 + (lane & 3)*2;
#pragma unroll
        for (int half = 0; half < 2; half++) {
            float oa = acc_o[nt][half*2]   * (half ? il1 : il0);
            float ob = acc_o[nt][half*2+1] * (half ? il1 : il0);
            size_t row = mrow0 + half*8;
            __half ha = __float2half(oa), hb = __float2half(ob);
            uint32_t hi = (uint32_t)(*(uint16_t*)&ha) | ((uint32_t)(*(uint16_t*)&hb) << 16);
            ((uint32_t*)(ats + row * 2048))[col >> 1] = hi;
        }
    }
}

// ---------------- host orchestration ----------------
static void convA(const float* in, __half* out, int R, int Rpad, int C, int inPitch)
{
    long long tot = (long long)Rpad * (C >> 3);
    splitA_k<<<(int)((tot + 255) / 256), 256>>>(in, out, R, Rpad, C, inPitch);
}
static void convB(const float* in, __half* out, int R, int Rpad, int C, int inPitch)
{
    long long tot = (long long)Rpad * (C >> 3);
    cvtB_k<<<(int)((tot + 255) / 256), 256>>>(in, out, R, Rpad, C, inPitch);
}
static void gemmx(const __half* A, const __half* B, float* C, int M, int N, int K, int KA)
{
    cudaFuncSetAttribute(gemm_tc, cudaFuncAttributeMaxDynamicSharedMemorySize, GEMM_SMEM);
    dim3 grid((N + 127) / 128, M / 128);
    gemm_tc<<<grid, 256, GEMM_SMEM>>>(A, B, C, M, N, K, KA);
}

extern "C" void kernel_launch(void* const* d_in, const int* in_sizes, int n_in,
                              void* d_out, int out_size)
{
    const float* x        = (const float*)d_in[0];
    const float* wq_down  = (const float*)d_in[1];
    const float* q_norm_w = (const float*)d_in[2];
    const float* wq_up    = (const float*)d_in[3];
    const float* wq_rope  = (const float*)d_in[4];
    const float* wkv_down = (const float*)d_in[5];
    const float* kv_norm_w= (const float*)d_in[6];
    const float* wkv_up   = (const float*)d_in[7];
    const float* wk_rope  = (const float*)d_in[8];
    const float* wo       = (const float*)d_in[9];
    float* out = (float*)d_out;

    float *dall, *qnp, *kvu;
    cudaGetSymbolAddress((void**)&dall, g_dall);
    cudaGetSymbolAddress((void**)&qnp,  g_qnp);
    cudaGetSymbolAddress((void**)&kvu,  g_kvup);

    __half *xs, *wdall, *qcs, *wuall, *kvcs, *wkvu, *ats, *wos, *qsp, *ksp, *vt;
    cudaGetSymbolAddress((void**)&xs,    g_xs);
    cudaGetSymbolAddress((void**)&wdall, g_wdall);
    cudaGetSymbolAddress((void**)&qcs,   g_qcs);
    cudaGetSymbolAddress((void**)&wuall, g_wuall);
    cudaGetSymbolAddress((void**)&kvcs,  g_kvcs);
    cudaGetSymbolAddress((void**)&wkvu,  g_wkvu);
    cudaGetSymbolAddress((void**)&ats,   g_ats);
    cudaGetSymbolAddress((void**)&wos,   g_wos);
    cudaGetSymbolAddress((void**)&qsp,   g_qsp);
    cudaGetSymbolAddress((void**)&ksp,   g_ksp);
    cudaGetSymbolAddress((void**)&vt,    g_vt);

    // ---- stage 1: merged down projection ----
    convA(x,        xs,    MT,  MT,  DIMM, DIMM);
    convB(wq_down,  wdall,                         QR,  QR,  DIMM, DIMM);
    convB(wkv_down, wdall + (size_t)QR*DIMM,       KVR, KVR, DIMM, DIMM);
    convB(wk_rope,  wdall + (size_t)(QR+KVR)*DIMM, DR,  128, DIMM, DIMM);
    gemmx(xs, wdall, dall, MT, NDOWN, DIMM, 2*DIMM);

    // ---- fused rmsnorm -> split fp16; kr rope ----
    rmsnorm_split_k<<<MT, 256>>>(dall,      q_norm_w,  qcs,  QR,  NDOWN);
    rmsnorm_split_k<<<MT, 256>>>(dall + QR, kv_norm_w, kvcs, KVR, NDOWN);
    rope_k<<<(MT*32 + 255)/256, 256>>>(dall, NDOWN, QR+KVR, 1, DR, MT*32);

    // ---- stage 2: merged up projections ----
    convB(wq_up,   wuall,                      NH*DN, NH*DN, QR, QR);
    convB(wq_rope, wuall + (size_t)(NH*DN)*QR, NH*DR, NH*DR, QR, QR);
    gemmx(qcs,  wuall, qnp, MT, NUP, QR, 2*QR);
    convB(wkv_up, wkvu, NH*(DN+DVV), NH*(DN+DVV), KVR, KVR);
    gemmx(kvcs, wkvu,  kvu, MT, NH*(DN+DVV), KVR, 2*KVR);

    // ---- fused q rope + split pack (vectorized) ----
    {
        long long tot = (long long)BB*NH*SS*24;
        rope_pack_q<<<(int)((tot + 255) / 256), 256>>>(qnp, qsp);
        pack_k<<<(int)((tot + 255) / 256), 256>>>(kvu, dall, ksp);
    }
    pack_v<<<dim3(SS/64, NH, BB), 256>>>(kvu, vt);

    // ---- HMMA flash attention (Q resident) ----
    cudaFuncSetAttribute(attn_mma, cudaFuncAttributeMaxDynamicSharedMemorySize, ATT_SMEM);
    attn_mma<<<dim3(SS/64, NH, BB), 256, ATT_SMEM>>>(qsp, ksp, vt, ats);

    // ---- output projection (1-term fp16) ----
    convB(wo, wos, DIMM, DIMM, NH*DVV, NH*DVV);
    gemmx(ats, wos, out, MT, DIMM, NH*DVV, NH*DVV);
}